// round 12
// baseline (speedup 1.0000x reference)
#include <cuda_runtime.h>
#include <cuda_bf16.h>
#include <math.h>
#include <stdint.h>

// Problem constants
#define BB 16
#define TT 1024
#define CC 256
#define HH 4
#define KK 31
#define PADK 15
#define BT (BB * TT)          // 16384 tokens
#define C2 (2 * CC)           // 512
#define NSMALL (KK + HH * KK) // 155
#define NSP 160               // padded row stride for raw
#define NWW (HH * KK)         // 124
#define NSMPAD 256            // padded N rows for small weight

// -------------------- device scratch ---------------------------------------
__device__ float g_x[(size_t)BT * CC];
__device__ __nv_bfloat16 g_xhi[(size_t)BT * CC];
__device__ __nv_bfloat16 g_xlo[(size_t)BT * CC];
__device__ __nv_bfloat16 g_zhi[(size_t)BT * C2];
__device__ __nv_bfloat16 g_zlo[(size_t)BT * C2];
__device__ float g_raw[(size_t)BT * NSP];
__device__ __nv_bfloat16 g_w1t_hi[(size_t)C2 * CC];
__device__ __nv_bfloat16 g_w1t_lo[(size_t)C2 * CC];
__device__ __nv_bfloat16 g_w2t_hi[(size_t)CC * C2];
__device__ __nv_bfloat16 g_w2t_lo[(size_t)CC * C2];
__device__ __nv_bfloat16 g_wst_hi[(size_t)NSMPAD * CC];
__device__ __nv_bfloat16 g_wst_lo[(size_t)NSMPAD * CC];
__device__ float g_bsmall[NSP];

static __device__ __forceinline__ void split2(float v, __nv_bfloat16& h, __nv_bfloat16& l) {
    h = __float2bfloat16(v);
    l = __float2bfloat16(v - __bfloat162float(h));
}

__device__ __forceinline__ void mma16816(float* c, uint32_t a0, uint32_t a1,
                                         uint32_t a2, uint32_t a3,
                                         uint32_t b0, uint32_t b1) {
    asm volatile(
        "mma.sync.aligned.m16n8k16.row.col.f32.bf16.bf16.f32 "
        "{%0,%1,%2,%3}, {%4,%5,%6,%7}, {%8,%9}, {%0,%1,%2,%3};"
        : "+f"(c[0]), "+f"(c[1]), "+f"(c[2]), "+f"(c[3])
        : "r"(a0), "r"(a1), "r"(a2), "r"(a3), "r"(b0), "r"(b1));
}

__device__ __forceinline__ uint32_t smem_u32(const void* p) {
    uint32_t a;
    asm("{ .reg .u64 t; cvta.to.shared.u64 t, %1; cvt.u32.u64 %0, t; }"
        : "=r"(a) : "l"(p));
    return a;
}
__device__ __forceinline__ void cpa16(uint32_t saddr, const void* g) {
    asm volatile("cp.async.cg.shared.global [%0], [%1], 16;" :: "r"(saddr), "l"(g));
}
#define CP_COMMIT() asm volatile("cp.async.commit_group;" ::: "memory")
#define CP_WAIT0()  asm volatile("cp.async.wait_group 0;" ::: "memory")

#define BMT 128
#define BNT 128
#define APAD 40   // bf16 elems per smem row
#define TILE_ELEMS (128 * APAD)

// ============ fused GEMM1 + GLU + split (unchanged R11) =====================
#define G1_STAGE (6 * TILE_ELEMS)
#define G1_SMEM_BYTES (2 * G1_STAGE * 2)   // 122880

__global__ __launch_bounds__(256) void gemm1_glu(
    const float* __restrict__ Q,
    const __nv_bfloat16* __restrict__ Wh, const __nv_bfloat16* __restrict__ Wl,
    const float* __restrict__ b1,
    float* __restrict__ X, __nv_bfloat16* __restrict__ Xhi,
    __nv_bfloat16* __restrict__ Xlo)
{
    extern __shared__ __align__(16) __nv_bfloat16 sm[];
    const int tid = threadIdx.x;
    const int wid = tid >> 5;
    const int lane = tid & 31;
    const int m0 = blockIdx.y * BMT;
    const int n0 = blockIdx.x * BNT;
    const int wm = (wid & 1) * 64;
    const int wn = (wid >> 1) * 32;
    const int r8 = lane >> 2;
    const int cp = (lane & 3) * 2;
    const uint32_t smbase = smem_u32(sm);

    const __nv_bfloat16* bsrc[4] = { Wh, Wl, Wh, Wl };
    const int brow[4] = { n0, n0, n0 + 256, n0 + 256 };

    const int c0 = tid, c1 = tid + 256;
    const int r0c = c0 >> 2, q0c = (c0 & 3) * 8;
    const int r1c = c1 >> 2, q1c = (c1 & 3) * 8;

    float acc_a[4][4][4], acc_g[4][4][4];
#pragma unroll
    for (int i = 0; i < 4; i++)
#pragma unroll
        for (int j = 0; j < 4; j++)
#pragma unroll
            for (int q = 0; q < 4; q++) { acc_a[i][j][q] = 0.f; acc_g[i][j][q] = 0.f; }

    const int NK = CC / 32;  // 8
    float apre[2][8];

#pragma unroll
    for (int t = 0; t < 4; t++) {
        cpa16(smbase + (uint32_t)(((t + 2) * 128 + r0c) * APAD + q0c) * 2,
              bsrc[t] + (size_t)(brow[t] + r0c) * CC + q0c);
        cpa16(smbase + (uint32_t)(((t + 2) * 128 + r1c) * APAD + q1c) * 2,
              bsrc[t] + (size_t)(brow[t] + r1c) * CC + q1c);
    }
    CP_COMMIT();
    {
        *reinterpret_cast<float4*>(&apre[0][0]) = *reinterpret_cast<const float4*>(&Q[(size_t)(m0 + r0c) * CC + q0c]);
        *reinterpret_cast<float4*>(&apre[0][4]) = *reinterpret_cast<const float4*>(&Q[(size_t)(m0 + r0c) * CC + q0c + 4]);
        *reinterpret_cast<float4*>(&apre[1][0]) = *reinterpret_cast<const float4*>(&Q[(size_t)(m0 + r1c) * CC + q1c]);
        *reinterpret_cast<float4*>(&apre[1][4]) = *reinterpret_cast<const float4*>(&Q[(size_t)(m0 + r1c) * CC + q1c + 4]);
        __nv_bfloat16 h8[8], l8[8];
#pragma unroll
        for (int e = 0; e < 8; e++) split2(apre[0][e], h8[e], l8[e]);
        *reinterpret_cast<uint4*>(&sm[(0 * 128 + r0c) * APAD + q0c]) = *reinterpret_cast<uint4*>(h8);
        *reinterpret_cast<uint4*>(&sm[(1 * 128 + r0c) * APAD + q0c]) = *reinterpret_cast<uint4*>(l8);
#pragma unroll
        for (int e = 0; e < 8; e++) split2(apre[1][e], h8[e], l8[e]);
        *reinterpret_cast<uint4*>(&sm[(0 * 128 + r1c) * APAD + q1c]) = *reinterpret_cast<uint4*>(h8);
        *reinterpret_cast<uint4*>(&sm[(1 * 128 + r1c) * APAD + q1c]) = *reinterpret_cast<uint4*>(l8);
    }
    CP_WAIT0();
    __syncthreads();

    for (int kc = 0; kc < NK; kc++) {
        const int nxt = kc + 1;
        if (nxt < NK) {
            const int sb = (nxt & 1) * G1_STAGE;
            const int k0 = nxt << 5;
#pragma unroll
            for (int t = 0; t < 4; t++) {
                cpa16(smbase + (uint32_t)(sb + ((t + 2) * 128 + r0c) * APAD + q0c) * 2,
                      bsrc[t] + (size_t)(brow[t] + r0c) * CC + k0 + q0c);
                cpa16(smbase + (uint32_t)(sb + ((t + 2) * 128 + r1c) * APAD + q1c) * 2,
                      bsrc[t] + (size_t)(brow[t] + r1c) * CC + k0 + q1c);
            }
            CP_COMMIT();
            *reinterpret_cast<float4*>(&apre[0][0]) = *reinterpret_cast<const float4*>(&Q[(size_t)(m0 + r0c) * CC + k0 + q0c]);
            *reinterpret_cast<float4*>(&apre[0][4]) = *reinterpret_cast<const float4*>(&Q[(size_t)(m0 + r0c) * CC + k0 + q0c + 4]);
            *reinterpret_cast<float4*>(&apre[1][0]) = *reinterpret_cast<const float4*>(&Q[(size_t)(m0 + r1c) * CC + k0 + q1c]);
            *reinterpret_cast<float4*>(&apre[1][4]) = *reinterpret_cast<const float4*>(&Q[(size_t)(m0 + r1c) * CC + k0 + q1c + 4]);
        }

        const __nv_bfloat16* Ah_ = sm + (kc & 1) * G1_STAGE;
        const __nv_bfloat16* Al_ = Ah_ + TILE_ELEMS;
        const __nv_bfloat16* Bah = Ah_ + 2 * TILE_ELEMS;
        const __nv_bfloat16* Bal = Ah_ + 3 * TILE_ELEMS;
        const __nv_bfloat16* Bgh = Ah_ + 4 * TILE_ELEMS;
        const __nv_bfloat16* Bgl = Ah_ + 5 * TILE_ELEMS;
#pragma unroll
        for (int ks = 0; ks < 2; ks++) {
            const int kb = ks * 16;
            uint32_t afh[4][4], afl[4][4];
#pragma unroll
            for (int im = 0; im < 4; im++) {
                const int rb = wm + im * 16;
                afh[im][0] = *reinterpret_cast<const uint32_t*>(&Ah_[(rb + r8) * APAD + kb + cp]);
                afh[im][1] = *reinterpret_cast<const uint32_t*>(&Ah_[(rb + r8 + 8) * APAD + kb + cp]);
                afh[im][2] = *reinterpret_cast<const uint32_t*>(&Ah_[(rb + r8) * APAD + kb + cp + 8]);
                afh[im][3] = *reinterpret_cast<const uint32_t*>(&Ah_[(rb + r8 + 8) * APAD + kb + cp + 8]);
                afl[im][0] = *reinterpret_cast<const uint32_t*>(&Al_[(rb + r8) * APAD + kb + cp]);
                afl[im][1] = *reinterpret_cast<const uint32_t*>(&Al_[(rb + r8 + 8) * APAD + kb + cp]);
                afl[im][2] = *reinterpret_cast<const uint32_t*>(&Al_[(rb + r8) * APAD + kb + cp + 8]);
                afl[im][3] = *reinterpret_cast<const uint32_t*>(&Al_[(rb + r8 + 8) * APAD + kb + cp + 8]);
            }
            {
                uint32_t bh[4][2], bl[4][2];
#pragma unroll
                for (int jn = 0; jn < 4; jn++) {
                    const int nb = wn + jn * 8;
                    bh[jn][0] = *reinterpret_cast<const uint32_t*>(&Bah[(nb + r8) * APAD + kb + cp]);
                    bh[jn][1] = *reinterpret_cast<const uint32_t*>(&Bah[(nb + r8) * APAD + kb + cp + 8]);
                    bl[jn][0] = *reinterpret_cast<const uint32_t*>(&Bal[(nb + r8) * APAD + kb + cp]);
                    bl[jn][1] = *reinterpret_cast<const uint32_t*>(&Bal[(nb + r8) * APAD + kb + cp + 8]);
                }
#pragma unroll
                for (int im = 0; im < 4; im++)
#pragma unroll
                    for (int jn = 0; jn < 4; jn++) {
                        mma16816(acc_a[im][jn], afh[im][0], afh[im][1], afh[im][2], afh[im][3], bh[jn][0], bh[jn][1]);
                        mma16816(acc_a[im][jn], afh[im][0], afh[im][1], afh[im][2], afh[im][3], bl[jn][0], bl[jn][1]);
                        mma16816(acc_a[im][jn], afl[im][0], afl[im][1], afl[im][2], afl[im][3], bh[jn][0], bh[jn][1]);
                    }
            }
            {
                uint32_t bh[4][2], bl[4][2];
#pragma unroll
                for (int jn = 0; jn < 4; jn++) {
                    const int nb = wn + jn * 8;
                    bh[jn][0] = *reinterpret_cast<const uint32_t*>(&Bgh[(nb + r8) * APAD + kb + cp]);
                    bh[jn][1] = *reinterpret_cast<const uint32_t*>(&Bgh[(nb + r8) * APAD + kb + cp + 8]);
                    bl[jn][0] = *reinterpret_cast<const uint32_t*>(&Bgl[(nb + r8) * APAD + kb + cp]);
                    bl[jn][1] = *reinterpret_cast<const uint32_t*>(&Bgl[(nb + r8) * APAD + kb + cp + 8]);
                }
#pragma unroll
                for (int im = 0; im < 4; im++)
#pragma unroll
                    for (int jn = 0; jn < 4; jn++) {
                        mma16816(acc_g[im][jn], afh[im][0], afh[im][1], afh[im][2], afh[im][3], bh[jn][0], bh[jn][1]);
                        mma16816(acc_g[im][jn], afh[im][0], afh[im][1], afh[im][2], afh[im][3], bl[jn][0], bl[jn][1]);
                        mma16816(acc_g[im][jn], afl[im][0], afl[im][1], afl[im][2], afl[im][3], bh[jn][0], bh[jn][1]);
                    }
            }
        }

        if (nxt < NK) {
            const int sb = (nxt & 1) * G1_STAGE;
            __nv_bfloat16 h8[8], l8[8];
#pragma unroll
            for (int e = 0; e < 8; e++) split2(apre[0][e], h8[e], l8[e]);
            *reinterpret_cast<uint4*>(&sm[sb + (0 * 128 + r0c) * APAD + q0c]) = *reinterpret_cast<uint4*>(h8);
            *reinterpret_cast<uint4*>(&sm[sb + (1 * 128 + r0c) * APAD + q0c]) = *reinterpret_cast<uint4*>(l8);
#pragma unroll
            for (int e = 0; e < 8; e++) split2(apre[1][e], h8[e], l8[e]);
            *reinterpret_cast<uint4*>(&sm[sb + (0 * 128 + r1c) * APAD + q1c]) = *reinterpret_cast<uint4*>(h8);
            *reinterpret_cast<uint4*>(&sm[sb + (1 * 128 + r1c) * APAD + q1c]) = *reinterpret_cast<uint4*>(l8);
            CP_WAIT0();
            __syncthreads();
        }
    }

#pragma unroll
    for (int im = 0; im < 4; im++) {
#pragma unroll
        for (int jn = 0; jn < 4; jn++) {
            const int lc = wn + jn * 8 + cp;
            const int col = n0 + lc;
            const float ba0 = b1[col], ba1 = b1[col + 1];
            const float bg0 = b1[col + 256], bg1 = b1[col + 257];
            const int row0 = m0 + wm + im * 16 + r8;
#pragma unroll
            for (int half = 0; half < 2; half++) {
                const int row = row0 + half * 8;
                float a0 = acc_a[im][jn][half * 2 + 0] + ba0;
                float a1 = acc_a[im][jn][half * 2 + 1] + ba1;
                float gg0 = acc_g[im][jn][half * 2 + 0] + bg0;
                float gg1 = acc_g[im][jn][half * 2 + 1] + bg1;
                float x0 = a0 * (1.f / (1.f + expf(-gg0)));
                float x1 = a1 * (1.f / (1.f + expf(-gg1)));
                size_t o = (size_t)row * CC + col;
                *reinterpret_cast<float2*>(&X[o]) = make_float2(x0, x1);
                __nv_bfloat16 h0, l0, h1, l1;
                split2(x0, h0, l0); split2(x1, h1, l1);
                __nv_bfloat162 ph; ph.x = h0; ph.y = h1;
                __nv_bfloat162 pl; pl.x = l0; pl.y = l1;
                *reinterpret_cast<__nv_bfloat162*>(&Xhi[o]) = ph;
                *reinterpret_cast<__nv_bfloat162*>(&Xlo[o]) = pl;
            }
        }
    }
}

// ---------------- generic fused split-bf16 GEMM (2 CTAs/SM forced) ----------
#define STAGE_ELEMS (4 * TILE_ELEMS)
#define GSMEM_BYTES (2 * STAGE_ELEMS * 2)   // 81920

__global__ __launch_bounds__(256, 2) void gemm_split_mma(
    const __nv_bfloat16* __restrict__ Ahi, const __nv_bfloat16* __restrict__ Alo,
    const __nv_bfloat16* __restrict__ Bhi, const __nv_bfloat16* __restrict__ Blo,
    const float* __restrict__ bias, float* __restrict__ Cm,
    int Kt, int ldc, int Nout)
{
    extern __shared__ __align__(16) __nv_bfloat16 sm[];
    const int tid = threadIdx.x;
    const int wid = tid >> 5;
    const int lane = tid & 31;
    const int m0 = blockIdx.y * BMT;
    const int n0 = blockIdx.x * BNT;
    const int wm = (wid & 1) * 64;
    const int wn = (wid >> 1) * 32;
    const int r8 = lane >> 2;
    const int cp = (lane & 3) * 2;

    const __nv_bfloat16* srcs[4] = { Ahi, Alo, Bhi, Blo };
    const int bases[4] = { m0, m0, n0, n0 };

    const int c0 = tid, c1 = tid + 256;
    const int lr0 = c0 >> 2, lc0 = (c0 & 3) * 8;
    const int lr1 = c1 >> 2, lc1 = (c1 & 3) * 8;
    const uint32_t smbase = smem_u32(sm);

    float acc[4][4][4];
#pragma unroll
    for (int i = 0; i < 4; i++)
#pragma unroll
        for (int j = 0; j < 4; j++)
#pragma unroll
            for (int q = 0; q < 4; q++) acc[i][j][q] = 0.f;

    const int NK = Kt >> 5;

#pragma unroll
    for (int t = 0; t < 4; t++) {
        const __nv_bfloat16* sp = srcs[t];
        cpa16(smbase + (uint32_t)((t * 128 + lr0) * APAD + lc0) * 2,
              sp + (size_t)(bases[t] + lr0) * Kt + lc0);
        cpa16(smbase + (uint32_t)((t * 128 + lr1) * APAD + lc1) * 2,
              sp + (size_t)(bases[t] + lr1) * Kt + lc1);
    }
    CP_COMMIT();
    CP_WAIT0();
    __syncthreads();

    for (int kc = 0; kc < NK; kc++) {
        if (kc + 1 < NK) {
            const int sb = ((kc + 1) & 1) * STAGE_ELEMS;
            const int k0 = (kc + 1) << 5;
#pragma unroll
            for (int t = 0; t < 4; t++) {
                const __nv_bfloat16* sp = srcs[t];
                cpa16(smbase + (uint32_t)(sb + (t * 128 + lr0) * APAD + lc0) * 2,
                      sp + (size_t)(bases[t] + lr0) * Kt + k0 + lc0);
                cpa16(smbase + (uint32_t)(sb + (t * 128 + lr1) * APAD + lc1) * 2,
                      sp + (size_t)(bases[t] + lr1) * Kt + k0 + lc1);
            }
            CP_COMMIT();
        }
        const __nv_bfloat16* Ah_ = sm + (kc & 1) * STAGE_ELEMS;
        const __nv_bfloat16* Al_ = Ah_ + TILE_ELEMS;
        const __nv_bfloat16* Bh_ = Ah_ + 2 * TILE_ELEMS;
        const __nv_bfloat16* Bl_ = Ah_ + 3 * TILE_ELEMS;
#pragma unroll
        for (int ks = 0; ks < 2; ks++) {
            const int kb = ks * 16;
            uint32_t afh[4][4], afl[4][4];
#pragma unroll
            for (int im = 0; im < 4; im++) {
                const int rb = wm + im * 16;
                afh[im][0] = *reinterpret_cast<const uint32_t*>(&Ah_[(rb + r8) * APAD + kb + cp]);
                afh[im][1] = *reinterpret_cast<const uint32_t*>(&Ah_[(rb + r8 + 8) * APAD + kb + cp]);
                afh[im][2] = *reinterpret_cast<const uint32_t*>(&Ah_[(rb + r8) * APAD + kb + cp + 8]);
                afh[im][3] = *reinterpret_cast<const uint32_t*>(&Ah_[(rb + r8 + 8) * APAD + kb + cp + 8]);
            }
            uint32_t bfh[4][2], bfl[4][2];
#pragma unroll
            for (int jn = 0; jn < 4; jn++) {
                const int nb = wn + jn * 8;
                bfh[jn][0] = *reinterpret_cast<const uint32_t*>(&Bh_[(nb + r8) * APAD + kb + cp]);
                bfh[jn][1] = *reinterpret_cast<const uint32_t*>(&Bh_[(nb + r8) * APAD + kb + cp + 8]);
                bfl[jn][0] = *reinterpret_cast<const uint32_t*>(&Bl_[(nb + r8) * APAD + kb + cp]);
                bfl[jn][1] = *reinterpret_cast<const uint32_t*>(&Bl_[(nb + r8) * APAD + kb + cp + 8]);
            }
#pragma unroll
            for (int im = 0; im < 4; im++)
#pragma unroll
                for (int jn = 0; jn < 4; jn++) {
                    mma16816(acc[im][jn], afh[im][0], afh[im][1], afh[im][2], afh[im][3], bfh[jn][0], bfh[jn][1]);
                    mma16816(acc[im][jn], afh[im][0], afh[im][1], afh[im][2], afh[im][3], bfl[jn][0], bfl[jn][1]);
                }
#pragma unroll
            for (int im = 0; im < 4; im++) {
                const int rb = wm + im * 16;
                afl[im][0] = *reinterpret_cast<const uint32_t*>(&Al_[(rb + r8) * APAD + kb + cp]);
                afl[im][1] = *reinterpret_cast<const uint32_t*>(&Al_[(rb + r8 + 8) * APAD + kb + cp]);
                afl[im][2] = *reinterpret_cast<const uint32_t*>(&Al_[(rb + r8) * APAD + kb + cp + 8]);
                afl[im][3] = *reinterpret_cast<const uint32_t*>(&Al_[(rb + r8 + 8) * APAD + kb + cp + 8]);
            }
#pragma unroll
            for (int im = 0; im < 4; im++)
#pragma unroll
                for (int jn = 0; jn < 4; jn++)
                    mma16816(acc[im][jn], afl[im][0], afl[im][1], afl[im][2], afl[im][3], bfh[jn][0], bfh[jn][1]);
        }
        if (kc + 1 < NK) {
            CP_WAIT0();
            __syncthreads();
        }
    }

#pragma unroll
    for (int im = 0; im < 4; im++) {
#pragma unroll
        for (int jn = 0; jn < 4; jn++) {
            const int col = n0 + wn + jn * 8 + cp;
            if (col < Nout) {
                const float bx = bias[col], by = bias[col + 1];
                const int row0 = m0 + wm + im * 16 + r8;
                float2 v0 = { acc[im][jn][0] + bx, acc[im][jn][1] + by };
                float2 v1 = { acc[im][jn][2] + bx, acc[im][jn][3] + by };
                *reinterpret_cast<float2*>(&Cm[(size_t)row0 * ldc + col]) = v0;
                *reinterpret_cast<float2*>(&Cm[(size_t)(row0 + 8) * ldc + col]) = v1;
            }
        }
    }
}

// -------------------- merged prep kernel ------------------------------------
#define S_W1 (C2 * CC)
#define S_W2 (CC * C2)
#define S_WS (NSMPAD * CC)
__global__ __launch_bounds__(256) void prep_all(
    const float* __restrict__ w1, const float* __restrict__ w2,
    const float* __restrict__ wf, const float* __restrict__ ww,
    const float* __restrict__ bf, const float* __restrict__ bw,
    __nv_bfloat16* __restrict__ w1h, __nv_bfloat16* __restrict__ w1l,
    __nv_bfloat16* __restrict__ w2h, __nv_bfloat16* __restrict__ w2l,
    __nv_bfloat16* __restrict__ wsh, __nv_bfloat16* __restrict__ wsl,
    float* __restrict__ bc)
{
    int i = blockIdx.x * 256 + threadIdx.x;
    if (i < S_W1) {
        int n = i / CC, k = i % CC;
        split2(w1[(size_t)k * C2 + n], w1h[i], w1l[i]);
    } else if (i < S_W1 + S_W2) {
        int j = i - S_W1;
        int n = j / C2, k = j % C2;
        split2(w2[(size_t)k * CC + n], w2h[j], w2l[j]);
    } else if (i < S_W1 + S_W2 + S_WS) {
        int j = i - S_W1 - S_W2;
        int n = j / CC, k = j % CC;
        float v = 0.f;
        if (n < KK) v = wf[k * KK + n];
        else if (n < NSMALL) v = ww[k * NWW + (n - KK)];
        split2(v, wsh[j], wsl[j]);
    } else if (i < S_W1 + S_W2 + S_WS + NSP) {
        int j = i - S_W1 - S_W2 - S_WS;
        float v = 0.f;
        if (j < KK) v = bf[j];
        else if (j < NSMALL) v = bw[j - KK];
        bc[j] = v;
    }
}

// ========== fused band kernel: conv + softmax + attention apply =============
// CTA = 32 tokens. 8 warps, each owns 4 tokens. attn probs live in registers.
#define FT 32
#define FR (FT + 2 * PADK)   // 62
#define F_SMEM (FR * CC * (int)sizeof(float))
__global__ __launch_bounds__(256) void band_fused(
    const float* __restrict__ raw, const float* __restrict__ x,
    const int* __restrict__ mask,
    __nv_bfloat16* __restrict__ zhi, __nv_bfloat16* __restrict__ zlo)
{
    extern __shared__ float xs[];            // FR * CC
    __shared__ float msk[FT];

    const int b = blockIdx.x >> 5;           // 32 tiles per batch
    const int tb = (blockIdx.x & 31) * FT;
    const int tid = threadIdx.x;
    const int warp = tid >> 5;
    const int lane = tid & 31;

    // load x window (f4, 64 threads per row)
    for (int idx = tid; idx < FR * 64; idx += 256) {
        const int r = idx >> 6;
        const int c4 = (idx & 63) * 4;
        const int s = tb - PADK + r;
        float4 v = make_float4(0.f, 0.f, 0.f, 0.f);
        if (s >= 0 && s < TT)
            v = *reinterpret_cast<const float4*>(&x[((size_t)b * TT + s) * CC + c4]);
        *reinterpret_cast<float4*>(&xs[r * CC + c4]) = v;
    }
    if (tid < FT) msk[tid] = (mask[b * TT + tb + tid] != 0) ? 1.f : 0.f;
    __syncthreads();

#pragma unroll
    for (int it = 0; it < 4; it++) {
        const int tt = warp * 4 + it;        // local token
        const size_t t = (size_t)b * TT + tb + tt;

        // conv weights + per-head softmax (registers only)
        const float wv = (lane < KK) ? raw[t * NSP + lane] : 0.f;
        const int s_off = tb + tt + lane - PADK;
        const bool valid = (lane < KK) && (s_off >= 0) && (s_off < TT);
        float pv[HH];
#pragma unroll
        for (int h = 0; h < HH; h++) {
            float v = valid ? raw[t * NSP + KK + h * KK + lane] : -INFINITY;
            float mx = v;
#pragma unroll
            for (int o = 16; o; o >>= 1) mx = fmaxf(mx, __shfl_xor_sync(0xffffffffu, mx, o));
            float e = valid ? expf(v - mx) : 0.f;
            float sm_ = e;
#pragma unroll
            for (int o = 16; o; o >>= 1) sm_ += __shfl_xor_sync(0xffffffffu, sm_, o);
            pv[h] = e / sm_;
        }

        const float mk = msk[tt];

        // channel conv: lane owns channels [lane*8, lane*8+8)
        const float* xrow = &xs[(tt + PADK) * CC];
        float buf[44];
        const int base = lane * 8 - 16;
#pragma unroll
        for (int i = 0; i < 11; i++) {
            const int c = base + i * 4;
            float4 v = make_float4(0.f, 0.f, 0.f, 0.f);
            if (c >= 0 && c < CC)
                v = *reinterpret_cast<const float4*>(&xrow[c]);
            *reinterpret_cast<float4*>(&buf[i * 4]) = v;
        }
        float fa[8];
#pragma unroll
        for (int d = 0; d < 8; d++) fa[d] = 0.f;
#pragma unroll
        for (int j = 0; j < KK; j++) {
            const float wj = __shfl_sync(0xffffffffu, wv, j);
#pragma unroll
            for (int d = 0; d < 8; d++) fa[d] = fmaf(wj, buf[d + j + 1], fa[d]);
        }
        {
            __nv_bfloat16 h8[8], l8[8];
#pragma unroll
            for (int d = 0; d < 8; d++) split2(fa[d] * mk, h8[d], l8[d]);
            const size_t o = t * C2 + CC + lane * 8;
            *reinterpret_cast<uint4*>(&zhi[o]) = *reinterpret_cast<uint4*>(h8);
            *reinterpret_cast<uint4*>(&zlo[o]) = *reinterpret_cast<uint4*>(l8);
        }

        // attention apply: lane owns channels lane + g*32, head = g>>1
        float ya[8];
#pragma unroll
        for (int g = 0; g < 8; g++) ya[g] = 0.f;
#pragma unroll
        for (int j = 0; j < KK; j++) {
            const float w0 = __shfl_sync(0xffffffffu, pv[0], j);
            const float w1 = __shfl_sync(0xffffffffu, pv[1], j);
            const float w2 = __shfl_sync(0xffffffffu, pv[2], j);
            const float w3 = __shfl_sync(0xffffffffu, pv[3], j);
            const float* xr = &xs[(tt + j) * CC + lane];
            ya[0] = fmaf(w0, xr[0 * 32], ya[0]);
            ya[1] = fmaf(w0, xr[1 * 32], ya[1]);
            ya[2] = fmaf(w1, xr[2 * 32], ya[2]);
            ya[3] = fmaf(w1, xr[3 * 32], ya[3]);
            ya[4] = fmaf(w2, xr[4 * 32], ya[4]);
            ya[5] = fmaf(w2, xr[5 * 32], ya[5]);
            ya[6] = fmaf(w3, xr[6 * 32], ya[6]);
            ya[7] = fmaf(w3, xr[7 * 32], ya[7]);
        }
        const size_t obase = t * C2 + lane;
#pragma unroll
        for (int g = 0; g < 8; g++) {
            __nv_bfloat16 h_, l_;
            split2(ya[g] * mk, h_, l_);
            zhi[obase + g * 32] = h_;
            zlo[obase + g * 32] = l_;
        }
    }
}

// ---------------------------------------------------------------------------
extern "C" void kernel_launch(void* const* d_in, const int* in_sizes, int n_in,
                              void* d_out, int out_size)
{
    const float* query = (const float*)d_in[0];
    const int* mask = (const int*)d_in[3];
    const float* w1 = (const float*)d_in[4];
    const float* b1 = (const float*)d_in[5];
    const float* w2 = (const float*)d_in[6];
    const float* b2 = (const float*)d_in[7];
    const float* ww = (const float*)d_in[8];
    const float* bw = (const float*)d_in[9];
    const float* wf = (const float*)d_in[10];
    const float* bf = (const float*)d_in[11];
    float* out = (float*)d_out;

    void* p;
    cudaGetSymbolAddress(&p, g_x);      float* dx = (float*)p;
    cudaGetSymbolAddress(&p, g_xhi);    __nv_bfloat16* dxhi = (__nv_bfloat16*)p;
    cudaGetSymbolAddress(&p, g_xlo);    __nv_bfloat16* dxlo = (__nv_bfloat16*)p;
    cudaGetSymbolAddress(&p, g_zhi);    __nv_bfloat16* dzhi = (__nv_bfloat16*)p;
    cudaGetSymbolAddress(&p, g_zlo);    __nv_bfloat16* dzlo = (__nv_bfloat16*)p;
    cudaGetSymbolAddress(&p, g_raw);    float* draw = (float*)p;
    cudaGetSymbolAddress(&p, g_w1t_hi); __nv_bfloat16* w1h = (__nv_bfloat16*)p;
    cudaGetSymbolAddress(&p, g_w1t_lo); __nv_bfloat16* w1l = (__nv_bfloat16*)p;
    cudaGetSymbolAddress(&p, g_w2t_hi); __nv_bfloat16* w2h = (__nv_bfloat16*)p;
    cudaGetSymbolAddress(&p, g_w2t_lo); __nv_bfloat16* w2l = (__nv_bfloat16*)p;
    cudaGetSymbolAddress(&p, g_wst_hi); __nv_bfloat16* wsh = (__nv_bfloat16*)p;
    cudaGetSymbolAddress(&p, g_wst_lo); __nv_bfloat16* wsl = (__nv_bfloat16*)p;
    cudaGetSymbolAddress(&p, g_bsmall); float* dbs = (float*)p;

    static bool attr_done = false;
    if (!attr_done) {
        cudaFuncSetAttribute(gemm1_glu,
                             cudaFuncAttributeMaxDynamicSharedMemorySize, G1_SMEM_BYTES);
        cudaFuncSetAttribute(gemm_split_mma,
                             cudaFuncAttributeMaxDynamicSharedMemorySize, GSMEM_BYTES);
        cudaFuncSetAttribute(band_fused,
                             cudaFuncAttributeMaxDynamicSharedMemorySize, F_SMEM);
        attr_done = true;
    }

    // prep: all weight splits in one launch
    prep_all<<<(S_W1 + S_W2 + S_WS + NSP + 255) / 256, 256>>>(
        w1, w2, wf, ww, bf, bw, w1h, w1l, w2h, w2l, wsh, wsl, dbs);

    // 1) x = GLU(query @ w1 + b1), fused
    gemm1_glu<<<dim3(2, BT / BMT), 256, G1_SMEM_BYTES>>>(
        query, w1h, w1l, b1, dx, dxhi, dxlo);
    // 2) raw = x @ [wf|ww] + [bf|bw]
    gemm_split_mma<<<dim3(NSMPAD / BNT, BT / BMT), 256, GSMEM_BYTES>>>(
        dxhi, dxlo, wsh, wsl, dbs, draw, CC, NSP, NSP);
    // 3) fused: channel conv + banded softmax + attention apply -> z
    band_fused<<<BB * (TT / FT), 256, F_SMEM>>>(draw, dx, mask, dzhi, dzlo);
    // 4) out = z @ w2 + b2
    gemm_split_mma<<<dim3(CC / BNT, BT / BMT), 256, GSMEM_BYTES>>>(
        dzhi, dzlo, w2h, w2l, b2, out, C2, CC, CC);
}

// round 13
// speedup vs baseline: 1.4796x; 1.4796x over previous
#include <cuda_runtime.h>
#include <cuda_bf16.h>
#include <math.h>
#include <stdint.h>

// Problem constants
#define BB 16
#define TT 1024
#define CC 256
#define HH 4
#define KK 31
#define PADK 15
#define BT (BB * TT)          // 16384 tokens
#define C2 (2 * CC)           // 512
#define NSMALL (KK + HH * KK) // 155
#define NSP 160               // padded row stride for raw
#define NWW (HH * KK)         // 124
#define NSMPAD 256            // padded N rows for small weight

// -------------------- device scratch ---------------------------------------
__device__ float g_x[(size_t)BT * CC];
__device__ __nv_bfloat16 g_xhi[(size_t)BT * CC];
__device__ __nv_bfloat16 g_xlo[(size_t)BT * CC];
__device__ __nv_bfloat16 g_zhi[(size_t)BT * C2];
__device__ __nv_bfloat16 g_zlo[(size_t)BT * C2];
__device__ float g_raw[(size_t)BT * NSP];
__device__ float g_attn[(size_t)BT * NWW];
__device__ __nv_bfloat16 g_w1t_hi[(size_t)C2 * CC];
__device__ __nv_bfloat16 g_w1t_lo[(size_t)C2 * CC];
__device__ __nv_bfloat16 g_w2t_hi[(size_t)CC * C2];
__device__ __nv_bfloat16 g_w2t_lo[(size_t)CC * C2];
__device__ __nv_bfloat16 g_wst_hi[(size_t)NSMPAD * CC];
__device__ __nv_bfloat16 g_wst_lo[(size_t)NSMPAD * CC];
__device__ float g_bsmall[NSP];

static __device__ __forceinline__ void split2(float v, __nv_bfloat16& h, __nv_bfloat16& l) {
    h = __float2bfloat16(v);
    l = __float2bfloat16(v - __bfloat162float(h));
}

__device__ __forceinline__ void mma16816(float* c, uint32_t a0, uint32_t a1,
                                         uint32_t a2, uint32_t a3,
                                         uint32_t b0, uint32_t b1) {
    asm volatile(
        "mma.sync.aligned.m16n8k16.row.col.f32.bf16.bf16.f32 "
        "{%0,%1,%2,%3}, {%4,%5,%6,%7}, {%8,%9}, {%0,%1,%2,%3};"
        : "+f"(c[0]), "+f"(c[1]), "+f"(c[2]), "+f"(c[3])
        : "r"(a0), "r"(a1), "r"(a2), "r"(a3), "r"(b0), "r"(b1));
}

__device__ __forceinline__ uint32_t smem_u32(const void* p) {
    uint32_t a;
    asm("{ .reg .u64 t; cvta.to.shared.u64 t, %1; cvt.u32.u64 %0, t; }"
        : "=r"(a) : "l"(p));
    return a;
}
__device__ __forceinline__ void cpa16(uint32_t saddr, const void* g) {
    asm volatile("cp.async.cg.shared.global [%0], [%1], 16;" :: "r"(saddr), "l"(g));
}
#define CP_COMMIT() asm volatile("cp.async.commit_group;" ::: "memory")
#define CP_WAIT0()  asm volatile("cp.async.wait_group 0;" ::: "memory")

#define BMT 128
#define BNT 128
#define APAD 40   // bf16 elems per smem row
#define TILE_ELEMS (128 * APAD)

// ============ fused GEMM1 + GLU + split (R11 config) ========================
#define G1_STAGE (6 * TILE_ELEMS)
#define G1_SMEM_BYTES (2 * G1_STAGE * 2)   // 122880

__global__ __launch_bounds__(256) void gemm1_glu(
    const float* __restrict__ Q,
    const __nv_bfloat16* __restrict__ Wh, const __nv_bfloat16* __restrict__ Wl,
    const float* __restrict__ b1,
    float* __restrict__ X, __nv_bfloat16* __restrict__ Xhi,
    __nv_bfloat16* __restrict__ Xlo)
{
    extern __shared__ __align__(16) __nv_bfloat16 sm[];
    const int tid = threadIdx.x;
    const int wid = tid >> 5;
    const int lane = tid & 31;
    const int m0 = blockIdx.y * BMT;
    const int n0 = blockIdx.x * BNT;
    const int wm = (wid & 1) * 64;
    const int wn = (wid >> 1) * 32;
    const int r8 = lane >> 2;
    const int cp = (lane & 3) * 2;
    const uint32_t smbase = smem_u32(sm);

    const __nv_bfloat16* bsrc[4] = { Wh, Wl, Wh, Wl };
    const int brow[4] = { n0, n0, n0 + 256, n0 + 256 };

    const int c0 = tid, c1 = tid + 256;
    const int r0c = c0 >> 2, q0c = (c0 & 3) * 8;
    const int r1c = c1 >> 2, q1c = (c1 & 3) * 8;

    float acc_a[4][4][4], acc_g[4][4][4];
#pragma unroll
    for (int i = 0; i < 4; i++)
#pragma unroll
        for (int j = 0; j < 4; j++)
#pragma unroll
            for (int q = 0; q < 4; q++) { acc_a[i][j][q] = 0.f; acc_g[i][j][q] = 0.f; }

    const int NK = CC / 32;  // 8
    float apre[2][8];

#pragma unroll
    for (int t = 0; t < 4; t++) {
        cpa16(smbase + (uint32_t)(((t + 2) * 128 + r0c) * APAD + q0c) * 2,
              bsrc[t] + (size_t)(brow[t] + r0c) * CC + q0c);
        cpa16(smbase + (uint32_t)(((t + 2) * 128 + r1c) * APAD + q1c) * 2,
              bsrc[t] + (size_t)(brow[t] + r1c) * CC + q1c);
    }
    CP_COMMIT();
    {
        *reinterpret_cast<float4*>(&apre[0][0]) = *reinterpret_cast<const float4*>(&Q[(size_t)(m0 + r0c) * CC + q0c]);
        *reinterpret_cast<float4*>(&apre[0][4]) = *reinterpret_cast<const float4*>(&Q[(size_t)(m0 + r0c) * CC + q0c + 4]);
        *reinterpret_cast<float4*>(&apre[1][0]) = *reinterpret_cast<const float4*>(&Q[(size_t)(m0 + r1c) * CC + q1c]);
        *reinterpret_cast<float4*>(&apre[1][4]) = *reinterpret_cast<const float4*>(&Q[(size_t)(m0 + r1c) * CC + q1c + 4]);
        __nv_bfloat16 h8[8], l8[8];
#pragma unroll
        for (int e = 0; e < 8; e++) split2(apre[0][e], h8[e], l8[e]);
        *reinterpret_cast<uint4*>(&sm[(0 * 128 + r0c) * APAD + q0c]) = *reinterpret_cast<uint4*>(h8);
        *reinterpret_cast<uint4*>(&sm[(1 * 128 + r0c) * APAD + q0c]) = *reinterpret_cast<uint4*>(l8);
#pragma unroll
        for (int e = 0; e < 8; e++) split2(apre[1][e], h8[e], l8[e]);
        *reinterpret_cast<uint4*>(&sm[(0 * 128 + r1c) * APAD + q1c]) = *reinterpret_cast<uint4*>(h8);
        *reinterpret_cast<uint4*>(&sm[(1 * 128 + r1c) * APAD + q1c]) = *reinterpret_cast<uint4*>(l8);
    }
    CP_WAIT0();
    __syncthreads();

    for (int kc = 0; kc < NK; kc++) {
        const int nxt = kc + 1;
        if (nxt < NK) {
            const int sb = (nxt & 1) * G1_STAGE;
            const int k0 = nxt << 5;
#pragma unroll
            for (int t = 0; t < 4; t++) {
                cpa16(smbase + (uint32_t)(sb + ((t + 2) * 128 + r0c) * APAD + q0c) * 2,
                      bsrc[t] + (size_t)(brow[t] + r0c) * CC + k0 + q0c);
                cpa16(smbase + (uint32_t)(sb + ((t + 2) * 128 + r1c) * APAD + q1c) * 2,
                      bsrc[t] + (size_t)(brow[t] + r1c) * CC + k0 + q1c);
            }
            CP_COMMIT();
            *reinterpret_cast<float4*>(&apre[0][0]) = *reinterpret_cast<const float4*>(&Q[(size_t)(m0 + r0c) * CC + k0 + q0c]);
            *reinterpret_cast<float4*>(&apre[0][4]) = *reinterpret_cast<const float4*>(&Q[(size_t)(m0 + r0c) * CC + k0 + q0c + 4]);
            *reinterpret_cast<float4*>(&apre[1][0]) = *reinterpret_cast<const float4*>(&Q[(size_t)(m0 + r1c) * CC + k0 + q1c]);
            *reinterpret_cast<float4*>(&apre[1][4]) = *reinterpret_cast<const float4*>(&Q[(size_t)(m0 + r1c) * CC + k0 + q1c + 4]);
        }

        const __nv_bfloat16* Ah_ = sm + (kc & 1) * G1_STAGE;
        const __nv_bfloat16* Al_ = Ah_ + TILE_ELEMS;
        const __nv_bfloat16* Bah = Ah_ + 2 * TILE_ELEMS;
        const __nv_bfloat16* Bal = Ah_ + 3 * TILE_ELEMS;
        const __nv_bfloat16* Bgh = Ah_ + 4 * TILE_ELEMS;
        const __nv_bfloat16* Bgl = Ah_ + 5 * TILE_ELEMS;
#pragma unroll
        for (int ks = 0; ks < 2; ks++) {
            const int kb = ks * 16;
            uint32_t afh[4][4], afl[4][4];
#pragma unroll
            for (int im = 0; im < 4; im++) {
                const int rb = wm + im * 16;
                afh[im][0] = *reinterpret_cast<const uint32_t*>(&Ah_[(rb + r8) * APAD + kb + cp]);
                afh[im][1] = *reinterpret_cast<const uint32_t*>(&Ah_[(rb + r8 + 8) * APAD + kb + cp]);
                afh[im][2] = *reinterpret_cast<const uint32_t*>(&Ah_[(rb + r8) * APAD + kb + cp + 8]);
                afh[im][3] = *reinterpret_cast<const uint32_t*>(&Ah_[(rb + r8 + 8) * APAD + kb + cp + 8]);
                afl[im][0] = *reinterpret_cast<const uint32_t*>(&Al_[(rb + r8) * APAD + kb + cp]);
                afl[im][1] = *reinterpret_cast<const uint32_t*>(&Al_[(rb + r8 + 8) * APAD + kb + cp]);
                afl[im][2] = *reinterpret_cast<const uint32_t*>(&Al_[(rb + r8) * APAD + kb + cp + 8]);
                afl[im][3] = *reinterpret_cast<const uint32_t*>(&Al_[(rb + r8 + 8) * APAD + kb + cp + 8]);
            }
            {
                uint32_t bh[4][2], bl[4][2];
#pragma unroll
                for (int jn = 0; jn < 4; jn++) {
                    const int nb = wn + jn * 8;
                    bh[jn][0] = *reinterpret_cast<const uint32_t*>(&Bah[(nb + r8) * APAD + kb + cp]);
                    bh[jn][1] = *reinterpret_cast<const uint32_t*>(&Bah[(nb + r8) * APAD + kb + cp + 8]);
                    bl[jn][0] = *reinterpret_cast<const uint32_t*>(&Bal[(nb + r8) * APAD + kb + cp]);
                    bl[jn][1] = *reinterpret_cast<const uint32_t*>(&Bal[(nb + r8) * APAD + kb + cp + 8]);
                }
#pragma unroll
                for (int im = 0; im < 4; im++)
#pragma unroll
                    for (int jn = 0; jn < 4; jn++) {
                        mma16816(acc_a[im][jn], afh[im][0], afh[im][1], afh[im][2], afh[im][3], bh[jn][0], bh[jn][1]);
                        mma16816(acc_a[im][jn], afh[im][0], afh[im][1], afh[im][2], afh[im][3], bl[jn][0], bl[jn][1]);
                        mma16816(acc_a[im][jn], afl[im][0], afl[im][1], afl[im][2], afl[im][3], bh[jn][0], bh[jn][1]);
                    }
            }
            {
                uint32_t bh[4][2], bl[4][2];
#pragma unroll
                for (int jn = 0; jn < 4; jn++) {
                    const int nb = wn + jn * 8;
                    bh[jn][0] = *reinterpret_cast<const uint32_t*>(&Bgh[(nb + r8) * APAD + kb + cp]);
                    bh[jn][1] = *reinterpret_cast<const uint32_t*>(&Bgh[(nb + r8) * APAD + kb + cp + 8]);
                    bl[jn][0] = *reinterpret_cast<const uint32_t*>(&Bgl[(nb + r8) * APAD + kb + cp]);
                    bl[jn][1] = *reinterpret_cast<const uint32_t*>(&Bgl[(nb + r8) * APAD + kb + cp + 8]);
                }
#pragma unroll
                for (int im = 0; im < 4; im++)
#pragma unroll
                    for (int jn = 0; jn < 4; jn++) {
                        mma16816(acc_g[im][jn], afh[im][0], afh[im][1], afh[im][2], afh[im][3], bh[jn][0], bh[jn][1]);
                        mma16816(acc_g[im][jn], afh[im][0], afh[im][1], afh[im][2], afh[im][3], bl[jn][0], bl[jn][1]);
                        mma16816(acc_g[im][jn], afl[im][0], afl[im][1], afl[im][2], afl[im][3], bh[jn][0], bh[jn][1]);
                    }
            }
        }

        if (nxt < NK) {
            const int sb = (nxt & 1) * G1_STAGE;
            __nv_bfloat16 h8[8], l8[8];
#pragma unroll
            for (int e = 0; e < 8; e++) split2(apre[0][e], h8[e], l8[e]);
            *reinterpret_cast<uint4*>(&sm[sb + (0 * 128 + r0c) * APAD + q0c]) = *reinterpret_cast<uint4*>(h8);
            *reinterpret_cast<uint4*>(&sm[sb + (1 * 128 + r0c) * APAD + q0c]) = *reinterpret_cast<uint4*>(l8);
#pragma unroll
            for (int e = 0; e < 8; e++) split2(apre[1][e], h8[e], l8[e]);
            *reinterpret_cast<uint4*>(&sm[sb + (0 * 128 + r1c) * APAD + q1c]) = *reinterpret_cast<uint4*>(h8);
            *reinterpret_cast<uint4*>(&sm[sb + (1 * 128 + r1c) * APAD + q1c]) = *reinterpret_cast<uint4*>(l8);
            CP_WAIT0();
            __syncthreads();
        }
    }

#pragma unroll
    for (int im = 0; im < 4; im++) {
#pragma unroll
        for (int jn = 0; jn < 4; jn++) {
            const int lc = wn + jn * 8 + cp;
            const int col = n0 + lc;
            const float ba0 = b1[col], ba1 = b1[col + 1];
            const float bg0 = b1[col + 256], bg1 = b1[col + 257];
            const int row0 = m0 + wm + im * 16 + r8;
#pragma unroll
            for (int half = 0; half < 2; half++) {
                const int row = row0 + half * 8;
                float a0 = acc_a[im][jn][half * 2 + 0] + ba0;
                float a1 = acc_a[im][jn][half * 2 + 1] + ba1;
                float gg0 = acc_g[im][jn][half * 2 + 0] + bg0;
                float gg1 = acc_g[im][jn][half * 2 + 1] + bg1;
                float x0 = a0 * (1.f / (1.f + expf(-gg0)));
                float x1 = a1 * (1.f / (1.f + expf(-gg1)));
                size_t o = (size_t)row * CC + col;
                *reinterpret_cast<float2*>(&X[o]) = make_float2(x0, x1);
                __nv_bfloat16 h0, l0, h1, l1;
                split2(x0, h0, l0); split2(x1, h1, l1);
                __nv_bfloat162 ph; ph.x = h0; ph.y = h1;
                __nv_bfloat162 pl; pl.x = l0; pl.y = l1;
                *reinterpret_cast<__nv_bfloat162*>(&Xhi[o]) = ph;
                *reinterpret_cast<__nv_bfloat162*>(&Xlo[o]) = pl;
            }
        }
    }
}

// ---------------- generic fused split-bf16 GEMM (2 CTAs/SM, kept from R12) --
#define STAGE_ELEMS (4 * TILE_ELEMS)
#define GSMEM_BYTES (2 * STAGE_ELEMS * 2)   // 81920

__global__ __launch_bounds__(256, 2) void gemm_split_mma(
    const __nv_bfloat16* __restrict__ Ahi, const __nv_bfloat16* __restrict__ Alo,
    const __nv_bfloat16* __restrict__ Bhi, const __nv_bfloat16* __restrict__ Blo,
    const float* __restrict__ bias, float* __restrict__ Cm,
    int Kt, int ldc, int Nout)
{
    extern __shared__ __align__(16) __nv_bfloat16 sm[];
    const int tid = threadIdx.x;
    const int wid = tid >> 5;
    const int lane = tid & 31;
    const int m0 = blockIdx.y * BMT;
    const int n0 = blockIdx.x * BNT;
    const int wm = (wid & 1) * 64;
    const int wn = (wid >> 1) * 32;
    const int r8 = lane >> 2;
    const int cp = (lane & 3) * 2;

    const __nv_bfloat16* srcs[4] = { Ahi, Alo, Bhi, Blo };
    const int bases[4] = { m0, m0, n0, n0 };

    const int c0 = tid, c1 = tid + 256;
    const int lr0 = c0 >> 2, lc0 = (c0 & 3) * 8;
    const int lr1 = c1 >> 2, lc1 = (c1 & 3) * 8;
    const uint32_t smbase = smem_u32(sm);

    float acc[4][4][4];
#pragma unroll
    for (int i = 0; i < 4; i++)
#pragma unroll
        for (int j = 0; j < 4; j++)
#pragma unroll
            for (int q = 0; q < 4; q++) acc[i][j][q] = 0.f;

    const int NK = Kt >> 5;

#pragma unroll
    for (int t = 0; t < 4; t++) {
        const __nv_bfloat16* sp = srcs[t];
        cpa16(smbase + (uint32_t)((t * 128 + lr0) * APAD + lc0) * 2,
              sp + (size_t)(bases[t] + lr0) * Kt + lc0);
        cpa16(smbase + (uint32_t)((t * 128 + lr1) * APAD + lc1) * 2,
              sp + (size_t)(bases[t] + lr1) * Kt + lc1);
    }
    CP_COMMIT();
    CP_WAIT0();
    __syncthreads();

    for (int kc = 0; kc < NK; kc++) {
        if (kc + 1 < NK) {
            const int sb = ((kc + 1) & 1) * STAGE_ELEMS;
            const int k0 = (kc + 1) << 5;
#pragma unroll
            for (int t = 0; t < 4; t++) {
                const __nv_bfloat16* sp = srcs[t];
                cpa16(smbase + (uint32_t)(sb + (t * 128 + lr0) * APAD + lc0) * 2,
                      sp + (size_t)(bases[t] + lr0) * Kt + k0 + lc0);
                cpa16(smbase + (uint32_t)(sb + (t * 128 + lr1) * APAD + lc1) * 2,
                      sp + (size_t)(bases[t] + lr1) * Kt + k0 + lc1);
            }
            CP_COMMIT();
        }
        const __nv_bfloat16* Ah_ = sm + (kc & 1) * STAGE_ELEMS;
        const __nv_bfloat16* Al_ = Ah_ + TILE_ELEMS;
        const __nv_bfloat16* Bh_ = Ah_ + 2 * TILE_ELEMS;
        const __nv_bfloat16* Bl_ = Ah_ + 3 * TILE_ELEMS;
#pragma unroll
        for (int ks = 0; ks < 2; ks++) {
            const int kb = ks * 16;
            uint32_t afh[4][4], afl[4][4];
#pragma unroll
            for (int im = 0; im < 4; im++) {
                const int rb = wm + im * 16;
                afh[im][0] = *reinterpret_cast<const uint32_t*>(&Ah_[(rb + r8) * APAD + kb + cp]);
                afh[im][1] = *reinterpret_cast<const uint32_t*>(&Ah_[(rb + r8 + 8) * APAD + kb + cp]);
                afh[im][2] = *reinterpret_cast<const uint32_t*>(&Ah_[(rb + r8) * APAD + kb + cp + 8]);
                afh[im][3] = *reinterpret_cast<const uint32_t*>(&Ah_[(rb + r8 + 8) * APAD + kb + cp + 8]);
            }
            uint32_t bfh[4][2], bfl[4][2];
#pragma unroll
            for (int jn = 0; jn < 4; jn++) {
                const int nb = wn + jn * 8;
                bfh[jn][0] = *reinterpret_cast<const uint32_t*>(&Bh_[(nb + r8) * APAD + kb + cp]);
                bfh[jn][1] = *reinterpret_cast<const uint32_t*>(&Bh_[(nb + r8) * APAD + kb + cp + 8]);
                bfl[jn][0] = *reinterpret_cast<const uint32_t*>(&Bl_[(nb + r8) * APAD + kb + cp]);
                bfl[jn][1] = *reinterpret_cast<const uint32_t*>(&Bl_[(nb + r8) * APAD + kb + cp + 8]);
            }
#pragma unroll
            for (int im = 0; im < 4; im++)
#pragma unroll
                for (int jn = 0; jn < 4; jn++) {
                    mma16816(acc[im][jn], afh[im][0], afh[im][1], afh[im][2], afh[im][3], bfh[jn][0], bfh[jn][1]);
                    mma16816(acc[im][jn], afh[im][0], afh[im][1], afh[im][2], afh[im][3], bfl[jn][0], bfl[jn][1]);
                }
#pragma unroll
            for (int im = 0; im < 4; im++) {
                const int rb = wm + im * 16;
                afl[im][0] = *reinterpret_cast<const uint32_t*>(&Al_[(rb + r8) * APAD + kb + cp]);
                afl[im][1] = *reinterpret_cast<const uint32_t*>(&Al_[(rb + r8 + 8) * APAD + kb + cp]);
                afl[im][2] = *reinterpret_cast<const uint32_t*>(&Al_[(rb + r8) * APAD + kb + cp + 8]);
                afl[im][3] = *reinterpret_cast<const uint32_t*>(&Al_[(rb + r8 + 8) * APAD + kb + cp + 8]);
            }
#pragma unroll
            for (int im = 0; im < 4; im++)
#pragma unroll
                for (int jn = 0; jn < 4; jn++)
                    mma16816(acc[im][jn], afl[im][0], afl[im][1], afl[im][2], afl[im][3], bfh[jn][0], bfh[jn][1]);
        }
        if (kc + 1 < NK) {
            CP_WAIT0();
            __syncthreads();
        }
    }

#pragma unroll
    for (int im = 0; im < 4; im++) {
#pragma unroll
        for (int jn = 0; jn < 4; jn++) {
            const int col = n0 + wn + jn * 8 + cp;
            if (col < Nout) {
                const float bx = bias[col], by = bias[col + 1];
                const int row0 = m0 + wm + im * 16 + r8;
                float2 v0 = { acc[im][jn][0] + bx, acc[im][jn][1] + by };
                float2 v1 = { acc[im][jn][2] + bx, acc[im][jn][3] + by };
                *reinterpret_cast<float2*>(&Cm[(size_t)row0 * ldc + col]) = v0;
                *reinterpret_cast<float2*>(&Cm[(size_t)(row0 + 8) * ldc + col]) = v1;
            }
        }
    }
}

// -------------------- merged prep kernel ------------------------------------
#define S_W1 (C2 * CC)
#define S_W2 (CC * C2)
#define S_WS (NSMPAD * CC)
__global__ __launch_bounds__(256) void prep_all(
    const float* __restrict__ w1, const float* __restrict__ w2,
    const float* __restrict__ wf, const float* __restrict__ ww,
    const float* __restrict__ bf, const float* __restrict__ bw,
    __nv_bfloat16* __restrict__ w1h, __nv_bfloat16* __restrict__ w1l,
    __nv_bfloat16* __restrict__ w2h, __nv_bfloat16* __restrict__ w2l,
    __nv_bfloat16* __restrict__ wsh, __nv_bfloat16* __restrict__ wsl,
    float* __restrict__ bc)
{
    int i = blockIdx.x * 256 + threadIdx.x;
    if (i < S_W1) {
        int n = i / CC, k = i % CC;
        split2(w1[(size_t)k * C2 + n], w1h[i], w1l[i]);
    } else if (i < S_W1 + S_W2) {
        int j = i - S_W1;
        int n = j / C2, k = j % C2;
        split2(w2[(size_t)k * CC + n], w2h[j], w2l[j]);
    } else if (i < S_W1 + S_W2 + S_WS) {
        int j = i - S_W1 - S_W2;
        int n = j / CC, k = j % CC;
        float v = 0.f;
        if (n < KK) v = wf[k * KK + n];
        else if (n < NSMALL) v = ww[k * NWW + (n - KK)];
        split2(v, wsh[j], wsl[j]);
    } else if (i < S_W1 + S_W2 + S_WS + NSP) {
        int j = i - S_W1 - S_W2 - S_WS;
        float v = 0.f;
        if (j < KK) v = bf[j];
        else if (j < NSMALL) v = bw[j - KK];
        bc[j] = v;
    }
}

// ---------- per-token conv + softmax: register-window version (R11) ---------
__global__ __launch_bounds__(256) void post_small(
    const float* __restrict__ raw, const float* __restrict__ x,
    const int* __restrict__ mask, float* __restrict__ attn,
    __nv_bfloat16* __restrict__ zhi, __nv_bfloat16* __restrict__ zlo)
{
    __shared__ float xpad[8][288];
    const int warp = threadIdx.x >> 5;
    const int lane = threadIdx.x & 31;
    const int t = blockIdx.x * 8 + warp;
    const int b = t >> 10;
    const int tt = t & 1023;

    float* xp = xpad[warp];
#pragma unroll
    for (int i = lane; i < 288; i += 32) {
        int c = i - PADK;
        xp[i] = (c >= 0 && c < CC) ? x[(size_t)t * CC + c] : 0.f;
    }
    __syncwarp();

    const float mk = (mask[b * TT + tt] != 0) ? 1.f : 0.f;
    float wv = (lane < KK) ? raw[(size_t)t * NSP + lane] : 0.f;

    float win[40];
#pragma unroll
    for (int i = 0; i < 10; i++)
        *reinterpret_cast<float4*>(&win[i * 4]) =
            *reinterpret_cast<const float4*>(&xp[lane * 8 + i * 4]);

    float acc[8];
#pragma unroll
    for (int d = 0; d < 8; d++) acc[d] = 0.f;
#pragma unroll
    for (int j = 0; j < KK; j++) {
        float wj = __shfl_sync(0xffffffffu, wv, j);
#pragma unroll
        for (int d = 0; d < 8; d++) acc[d] = fmaf(wj, win[d + j], acc[d]);
    }
    {
        __nv_bfloat16 h8[8], l8[8];
#pragma unroll
        for (int d = 0; d < 8; d++) split2(acc[d] * mk, h8[d], l8[d]);
        size_t o = (size_t)t * C2 + CC + lane * 8;
        *reinterpret_cast<uint4*>(&zhi[o]) = *reinterpret_cast<uint4*>(h8);
        *reinterpret_cast<uint4*>(&zlo[o]) = *reinterpret_cast<uint4*>(l8);
    }

    const int s = tt + lane - PADK;
    const bool valid = (lane < KK) && (s >= 0) && (s < TT);
#pragma unroll
    for (int h = 0; h < HH; h++) {
        float v = valid ? raw[(size_t)t * NSP + KK + h * KK + lane] : -INFINITY;
        float mx = v;
#pragma unroll
        for (int o = 16; o; o >>= 1) mx = fmaxf(mx, __shfl_xor_sync(0xffffffffu, mx, o));
        float e = valid ? expf(v - mx) : 0.f;
        float sm = e;
#pragma unroll
        for (int o = 16; o; o >>= 1) sm += __shfl_xor_sync(0xffffffffu, sm, o);
        if (lane < KK) attn[(size_t)t * NWW + h * KK + lane] = e / sm;
    }
}

// ---------- banded attention apply: warp-per-token, shuffle attn (R11) ------
#define TCT 32
#define TCR (TCT + 2 * PADK)   // 62
#define TC_SMEM ((TCR * CC + TCT * NWW) * (int)sizeof(float))
__global__ __launch_bounds__(256) void timeconv(
    const float* __restrict__ x, const float* __restrict__ attn,
    const int* __restrict__ mask,
    __nv_bfloat16* __restrict__ zhi, __nv_bfloat16* __restrict__ zlo)
{
    extern __shared__ float smemf[];
    float* xs = smemf;                       // TCR * CC
    float* ats = smemf + TCR * CC;           // TCT * NWW
    __shared__ float msk[TCT];

    const int b = blockIdx.x >> 5;
    const int tb = (blockIdx.x & 31) * TCT;
    const int tid = threadIdx.x;
    const int warp = tid >> 5;
    const int lane = tid & 31;

    for (int r = 0; r < TCR; r++) {
        int s = tb - PADK + r;
        xs[r * CC + tid] = (s >= 0 && s < TT)
            ? x[((size_t)b * TT + s) * CC + tid] : 0.f;
    }
    for (int i = tid; i < TCT * NWW; i += 256)
        ats[i] = attn[((size_t)b * TT + tb) * NWW + i];
    if (tid < TCT) msk[tid] = (mask[b * TT + tb + tid] != 0) ? 1.f : 0.f;
    __syncthreads();

#pragma unroll
    for (int it = 0; it < 4; it++) {
        const int tt = warp * 4 + it;
        float wv0 = (lane < KK) ? ats[tt * NWW + 0 * KK + lane] : 0.f;
        float wv1 = (lane < KK) ? ats[tt * NWW + 1 * KK + lane] : 0.f;
        float wv2 = (lane < KK) ? ats[tt * NWW + 2 * KK + lane] : 0.f;
        float wv3 = (lane < KK) ? ats[tt * NWW + 3 * KK + lane] : 0.f;
        float acc[8];
#pragma unroll
        for (int g = 0; g < 8; g++) acc[g] = 0.f;
#pragma unroll
        for (int j = 0; j < KK; j++) {
            float w0 = __shfl_sync(0xffffffffu, wv0, j);
            float w1 = __shfl_sync(0xffffffffu, wv1, j);
            float w2 = __shfl_sync(0xffffffffu, wv2, j);
            float w3 = __shfl_sync(0xffffffffu, wv3, j);
            const float* xr = &xs[(tt + j) * CC + lane];
            acc[0] = fmaf(w0, xr[0 * 32], acc[0]);
            acc[1] = fmaf(w0, xr[1 * 32], acc[1]);
            acc[2] = fmaf(w1, xr[2 * 32], acc[2]);
            acc[3] = fmaf(w1, xr[3 * 32], acc[3]);
            acc[4] = fmaf(w2, xr[4 * 32], acc[4]);
            acc[5] = fmaf(w2, xr[5 * 32], acc[5]);
            acc[6] = fmaf(w3, xr[6 * 32], acc[6]);
            acc[7] = fmaf(w3, xr[7 * 32], acc[7]);
        }
        const float mv = msk[tt];
        const size_t obase = ((size_t)b * TT + tb + tt) * C2 + lane;
#pragma unroll
        for (int g = 0; g < 8; g++) {
            __nv_bfloat16 h_, l_;
            split2(acc[g] * mv, h_, l_);
            zhi[obase + g * 32] = h_;
            zlo[obase + g * 32] = l_;
        }
    }
}

// ---------------------------------------------------------------------------
extern "C" void kernel_launch(void* const* d_in, const int* in_sizes, int n_in,
                              void* d_out, int out_size)
{
    const float* query = (const float*)d_in[0];
    const int* mask = (const int*)d_in[3];
    const float* w1 = (const float*)d_in[4];
    const float* b1 = (const float*)d_in[5];
    const float* w2 = (const float*)d_in[6];
    const float* b2 = (const float*)d_in[7];
    const float* ww = (const float*)d_in[8];
    const float* bw = (const float*)d_in[9];
    const float* wf = (const float*)d_in[10];
    const float* bf = (const float*)d_in[11];
    float* out = (float*)d_out;

    void* p;
    cudaGetSymbolAddress(&p, g_x);      float* dx = (float*)p;
    cudaGetSymbolAddress(&p, g_xhi);    __nv_bfloat16* dxhi = (__nv_bfloat16*)p;
    cudaGetSymbolAddress(&p, g_xlo);    __nv_bfloat16* dxlo = (__nv_bfloat16*)p;
    cudaGetSymbolAddress(&p, g_zhi);    __nv_bfloat16* dzhi = (__nv_bfloat16*)p;
    cudaGetSymbolAddress(&p, g_zlo);    __nv_bfloat16* dzlo = (__nv_bfloat16*)p;
    cudaGetSymbolAddress(&p, g_raw);    float* draw = (float*)p;
    cudaGetSymbolAddress(&p, g_attn);   float* dattn = (float*)p;
    cudaGetSymbolAddress(&p, g_w1t_hi); __nv_bfloat16* w1h = (__nv_bfloat16*)p;
    cudaGetSymbolAddress(&p, g_w1t_lo); __nv_bfloat16* w1l = (__nv_bfloat16*)p;
    cudaGetSymbolAddress(&p, g_w2t_hi); __nv_bfloat16* w2h = (__nv_bfloat16*)p;
    cudaGetSymbolAddress(&p, g_w2t_lo); __nv_bfloat16* w2l = (__nv_bfloat16*)p;
    cudaGetSymbolAddress(&p, g_wst_hi); __nv_bfloat16* wsh = (__nv_bfloat16*)p;
    cudaGetSymbolAddress(&p, g_wst_lo); __nv_bfloat16* wsl = (__nv_bfloat16*)p;
    cudaGetSymbolAddress(&p, g_bsmall); float* dbs = (float*)p;

    static bool attr_done = false;
    if (!attr_done) {
        cudaFuncSetAttribute(gemm1_glu,
                             cudaFuncAttributeMaxDynamicSharedMemorySize, G1_SMEM_BYTES);
        cudaFuncSetAttribute(gemm_split_mma,
                             cudaFuncAttributeMaxDynamicSharedMemorySize, GSMEM_BYTES);
        cudaFuncSetAttribute(timeconv,
                             cudaFuncAttributeMaxDynamicSharedMemorySize, TC_SMEM);
        attr_done = true;
    }

    // prep: all weight splits in one launch
    prep_all<<<(S_W1 + S_W2 + S_WS + NSP + 255) / 256, 256>>>(
        w1, w2, wf, ww, bf, bw, w1h, w1l, w2h, w2l, wsh, wsl, dbs);

    // 1) x = GLU(query @ w1 + b1), fused
    gemm1_glu<<<dim3(2, BT / BMT), 256, G1_SMEM_BYTES>>>(
        query, w1h, w1l, b1, dx, dxhi, dxlo);
    // 2) raw = x @ [wf|ww] + [bf|bw]
    gemm_split_mma<<<dim3(NSMPAD / BNT, BT / BMT), 256, GSMEM_BYTES>>>(
        dxhi, dxlo, wsh, wsl, dbs, draw, CC, NSP, NSP);
    // 3) channel conv xf + banded softmax
    post_small<<<BT / 8, 256>>>(draw, dx, mask, dattn, dzhi, dzlo);
    // 4) banded attention apply
    timeconv<<<BB * (TT / TCT), 256, TC_SMEM>>>(dx, dattn, mask, dzhi, dzlo);
    // 5) out = z @ w2 + b2
    gemm_split_mma<<<dim3(CC / BNT, BT / BMT), 256, GSMEM_BYTES>>>(
        dzhi, dzlo, w2h, w2l, b2, out, C2, CC, CC);
}

// round 14
// speedup vs baseline: 1.5191x; 1.0267x over previous
#include <cuda_runtime.h>
#include <cuda_bf16.h>
#include <math.h>
#include <stdint.h>

// Problem constants
#define BB 16
#define TT 1024
#define CC 256
#define HH 4
#define KK 31
#define PADK 15
#define BT (BB * TT)          // 16384 tokens
#define C2 (2 * CC)           // 512
#define NSMALL (KK + HH * KK) // 155
#define NSP 160               // padded row stride for raw
#define NWW (HH * KK)         // 124
#define NSMPAD 256            // padded N rows for small weight

// -------------------- device scratch ---------------------------------------
__device__ float g_x[(size_t)BT * CC];
__device__ __nv_bfloat16 g_xhi[(size_t)BT * CC];
__device__ __nv_bfloat16 g_xlo[(size_t)BT * CC];
__device__ __nv_bfloat16 g_zhi[(size_t)BT * C2];
__device__ __nv_bfloat16 g_zlo[(size_t)BT * C2];
__device__ float g_raw[(size_t)BT * NSP];
__device__ float g_attn[(size_t)BT * NWW];
__device__ __nv_bfloat16 g_w1t_hi[(size_t)C2 * CC];
__device__ __nv_bfloat16 g_w1t_lo[(size_t)C2 * CC];
__device__ __nv_bfloat16 g_w2t_hi[(size_t)CC * C2];
__device__ __nv_bfloat16 g_w2t_lo[(size_t)CC * C2];
__device__ __nv_bfloat16 g_wst_hi[(size_t)NSMPAD * CC];
__device__ __nv_bfloat16 g_wst_lo[(size_t)NSMPAD * CC];
__device__ float g_bsmall[NSP];

static __device__ __forceinline__ void split2(float v, __nv_bfloat16& h, __nv_bfloat16& l) {
    h = __float2bfloat16(v);
    l = __float2bfloat16(v - __bfloat162float(h));
}

__device__ __forceinline__ void mma16816(float* c, uint32_t a0, uint32_t a1,
                                         uint32_t a2, uint32_t a3,
                                         uint32_t b0, uint32_t b1) {
    asm volatile(
        "mma.sync.aligned.m16n8k16.row.col.f32.bf16.bf16.f32 "
        "{%0,%1,%2,%3}, {%4,%5,%6,%7}, {%8,%9}, {%0,%1,%2,%3};"
        : "+f"(c[0]), "+f"(c[1]), "+f"(c[2]), "+f"(c[3])
        : "r"(a0), "r"(a1), "r"(a2), "r"(a3), "r"(b0), "r"(b1));
}

__device__ __forceinline__ void ldsm_x4(uint32_t* r, uint32_t saddr) {
    asm volatile("ldmatrix.sync.aligned.m8n8.x4.shared.b16 {%0,%1,%2,%3}, [%4];"
                 : "=r"(r[0]), "=r"(r[1]), "=r"(r[2]), "=r"(r[3]) : "r"(saddr));
}
__device__ __forceinline__ void ldsm_x2(uint32_t* r, uint32_t saddr) {
    asm volatile("ldmatrix.sync.aligned.m8n8.x2.shared.b16 {%0,%1}, [%2];"
                 : "=r"(r[0]), "=r"(r[1]) : "r"(saddr));
}

__device__ __forceinline__ uint32_t smem_u32(const void* p) {
    uint32_t a;
    asm("{ .reg .u64 t; cvta.to.shared.u64 t, %1; cvt.u32.u64 %0, t; }"
        : "=r"(a) : "l"(p));
    return a;
}
__device__ __forceinline__ void cpa16(uint32_t saddr, const void* g) {
    asm volatile("cp.async.cg.shared.global [%0], [%1], 16;" :: "r"(saddr), "l"(g));
}
#define CP_COMMIT() asm volatile("cp.async.commit_group;" ::: "memory")
#define CP_WAIT0()  asm volatile("cp.async.wait_group 0;" ::: "memory")

#define BMT 128
#define BNT 128
#define APAD 40   // bf16 elems per smem row
#define TILE_ELEMS (128 * APAD)
#define TILE_BYTES_SM (TILE_ELEMS * 2)

// ldmatrix per-lane address components (within a 16x16 A tile / n8k16 B tile)
#define A_LDSM_ROW(lane) (((lane) & 7) + (((lane) >> 3) & 1) * 8)
#define A_LDSM_COL(lane) ((((lane) >> 4) & 1) * 8)
#define B_LDSM_ROW(lane) ((lane) & 7)
#define B_LDSM_COL(lane) ((((lane) >> 3) & 1) * 8)

// ============ fused GEMM1 + GLU + split =====================================
#define G1_STAGE (6 * TILE_ELEMS)
#define G1_SMEM_BYTES (2 * G1_STAGE * 2)   // 122880

__global__ __launch_bounds__(256) void gemm1_glu(
    const float* __restrict__ Q,
    const __nv_bfloat16* __restrict__ Wh, const __nv_bfloat16* __restrict__ Wl,
    const float* __restrict__ b1,
    float* __restrict__ X, __nv_bfloat16* __restrict__ Xhi,
    __nv_bfloat16* __restrict__ Xlo)
{
    extern __shared__ __align__(16) __nv_bfloat16 sm[];
    const int tid = threadIdx.x;
    const int wid = tid >> 5;
    const int lane = tid & 31;
    const int m0 = blockIdx.y * BMT;
    const int n0 = blockIdx.x * BNT;     // a-col base; g-cols at n0+256
    const int wm = (wid & 1) * 64;
    const int wn = (wid >> 1) * 32;
    const int r8 = lane >> 2;
    const int cp = (lane & 3) * 2;
    const uint32_t smbase = smem_u32(sm);

    // ldmatrix address components
    const int alr = A_LDSM_ROW(lane), alc = A_LDSM_COL(lane);
    const int blr = B_LDSM_ROW(lane), blc = B_LDSM_COL(lane);

    const __nv_bfloat16* bsrc[4] = { Wh, Wl, Wh, Wl };
    const int brow[4] = { n0, n0, n0 + 256, n0 + 256 };

    const int c0 = tid, c1 = tid + 256;
    const int r0c = c0 >> 2, q0c = (c0 & 3) * 8;
    const int r1c = c1 >> 2, q1c = (c1 & 3) * 8;

    float acc_a[4][4][4], acc_g[4][4][4];
#pragma unroll
    for (int i = 0; i < 4; i++)
#pragma unroll
        for (int j = 0; j < 4; j++)
#pragma unroll
            for (int q = 0; q < 4; q++) { acc_a[i][j][q] = 0.f; acc_g[i][j][q] = 0.f; }

    const int NK = CC / 32;  // 8
    float apre[2][8];

#pragma unroll
    for (int t = 0; t < 4; t++) {
        cpa16(smbase + (uint32_t)(((t + 2) * 128 + r0c) * APAD + q0c) * 2,
              bsrc[t] + (size_t)(brow[t] + r0c) * CC + q0c);
        cpa16(smbase + (uint32_t)(((t + 2) * 128 + r1c) * APAD + q1c) * 2,
              bsrc[t] + (size_t)(brow[t] + r1c) * CC + q1c);
    }
    CP_COMMIT();
    {
        *reinterpret_cast<float4*>(&apre[0][0]) = *reinterpret_cast<const float4*>(&Q[(size_t)(m0 + r0c) * CC + q0c]);
        *reinterpret_cast<float4*>(&apre[0][4]) = *reinterpret_cast<const float4*>(&Q[(size_t)(m0 + r0c) * CC + q0c + 4]);
        *reinterpret_cast<float4*>(&apre[1][0]) = *reinterpret_cast<const float4*>(&Q[(size_t)(m0 + r1c) * CC + q1c]);
        *reinterpret_cast<float4*>(&apre[1][4]) = *reinterpret_cast<const float4*>(&Q[(size_t)(m0 + r1c) * CC + q1c + 4]);
        __nv_bfloat16 h8[8], l8[8];
#pragma unroll
        for (int e = 0; e < 8; e++) split2(apre[0][e], h8[e], l8[e]);
        *reinterpret_cast<uint4*>(&sm[(0 * 128 + r0c) * APAD + q0c]) = *reinterpret_cast<uint4*>(h8);
        *reinterpret_cast<uint4*>(&sm[(1 * 128 + r0c) * APAD + q0c]) = *reinterpret_cast<uint4*>(l8);
#pragma unroll
        for (int e = 0; e < 8; e++) split2(apre[1][e], h8[e], l8[e]);
        *reinterpret_cast<uint4*>(&sm[(0 * 128 + r1c) * APAD + q1c]) = *reinterpret_cast<uint4*>(h8);
        *reinterpret_cast<uint4*>(&sm[(1 * 128 + r1c) * APAD + q1c]) = *reinterpret_cast<uint4*>(l8);
    }
    CP_WAIT0();
    __syncthreads();

    for (int kc = 0; kc < NK; kc++) {
        const int nxt = kc + 1;
        if (nxt < NK) {
            const int sb = (nxt & 1) * G1_STAGE;
            const int k0 = nxt << 5;
#pragma unroll
            for (int t = 0; t < 4; t++) {
                cpa16(smbase + (uint32_t)(sb + ((t + 2) * 128 + r0c) * APAD + q0c) * 2,
                      bsrc[t] + (size_t)(brow[t] + r0c) * CC + k0 + q0c);
                cpa16(smbase + (uint32_t)(sb + ((t + 2) * 128 + r1c) * APAD + q1c) * 2,
                      bsrc[t] + (size_t)(brow[t] + r1c) * CC + k0 + q1c);
            }
            CP_COMMIT();
            *reinterpret_cast<float4*>(&apre[0][0]) = *reinterpret_cast<const float4*>(&Q[(size_t)(m0 + r0c) * CC + k0 + q0c]);
            *reinterpret_cast<float4*>(&apre[0][4]) = *reinterpret_cast<const float4*>(&Q[(size_t)(m0 + r0c) * CC + k0 + q0c + 4]);
            *reinterpret_cast<float4*>(&apre[1][0]) = *reinterpret_cast<const float4*>(&Q[(size_t)(m0 + r1c) * CC + k0 + q1c]);
            *reinterpret_cast<float4*>(&apre[1][4]) = *reinterpret_cast<const float4*>(&Q[(size_t)(m0 + r1c) * CC + k0 + q1c + 4]);
        }

        const uint32_t stg = smbase + (uint32_t)((kc & 1) * G1_STAGE) * 2;
#pragma unroll
        for (int ks = 0; ks < 2; ks++) {
            const int kb = ks * 16;
            uint32_t afh[4][4], afl[4][4];
#pragma unroll
            for (int im = 0; im < 4; im++) {
                const uint32_t aaddr = stg +
                    (uint32_t)(((wm + im * 16 + alr) * APAD + kb + alc) * 2);
                ldsm_x4(afh[im], aaddr);
                ldsm_x4(afl[im], aaddr + TILE_BYTES_SM);
            }
            {
                uint32_t bh[4][2], bl[4][2];
#pragma unroll
                for (int jn = 0; jn < 4; jn++) {
                    const uint32_t baddr = stg + 2 * TILE_BYTES_SM +
                        (uint32_t)(((wn + jn * 8 + blr) * APAD + kb + blc) * 2);
                    ldsm_x2(bh[jn], baddr);
                    ldsm_x2(bl[jn], baddr + TILE_BYTES_SM);
                }
#pragma unroll
                for (int im = 0; im < 4; im++)
#pragma unroll
                    for (int jn = 0; jn < 4; jn++) {
                        mma16816(acc_a[im][jn], afh[im][0], afh[im][1], afh[im][2], afh[im][3], bh[jn][0], bh[jn][1]);
                        mma16816(acc_a[im][jn], afh[im][0], afh[im][1], afh[im][2], afh[im][3], bl[jn][0], bl[jn][1]);
                        mma16816(acc_a[im][jn], afl[im][0], afl[im][1], afl[im][2], afl[im][3], bh[jn][0], bh[jn][1]);
                    }
            }
            {
                uint32_t bh[4][2], bl[4][2];
#pragma unroll
                for (int jn = 0; jn < 4; jn++) {
                    const uint32_t baddr = stg + 4 * TILE_BYTES_SM +
                        (uint32_t)(((wn + jn * 8 + blr) * APAD + kb + blc) * 2);
                    ldsm_x2(bh[jn], baddr);
                    ldsm_x2(bl[jn], baddr + TILE_BYTES_SM);
                }
#pragma unroll
                for (int im = 0; im < 4; im++)
#pragma unroll
                    for (int jn = 0; jn < 4; jn++) {
                        mma16816(acc_g[im][jn], afh[im][0], afh[im][1], afh[im][2], afh[im][3], bh[jn][0], bh[jn][1]);
                        mma16816(acc_g[im][jn], afh[im][0], afh[im][1], afh[im][2], afh[im][3], bl[jn][0], bl[jn][1]);
                        mma16816(acc_g[im][jn], afl[im][0], afl[im][1], afl[im][2], afl[im][3], bh[jn][0], bh[jn][1]);
                    }
            }
        }

        if (nxt < NK) {
            const int sb = (nxt & 1) * G1_STAGE;
            __nv_bfloat16 h8[8], l8[8];
#pragma unroll
            for (int e = 0; e < 8; e++) split2(apre[0][e], h8[e], l8[e]);
            *reinterpret_cast<uint4*>(&sm[sb + (0 * 128 + r0c) * APAD + q0c]) = *reinterpret_cast<uint4*>(h8);
            *reinterpret_cast<uint4*>(&sm[sb + (1 * 128 + r0c) * APAD + q0c]) = *reinterpret_cast<uint4*>(l8);
#pragma unroll
            for (int e = 0; e < 8; e++) split2(apre[1][e], h8[e], l8[e]);
            *reinterpret_cast<uint4*>(&sm[sb + (0 * 128 + r1c) * APAD + q1c]) = *reinterpret_cast<uint4*>(h8);
            *reinterpret_cast<uint4*>(&sm[sb + (1 * 128 + r1c) * APAD + q1c]) = *reinterpret_cast<uint4*>(l8);
            CP_WAIT0();
            __syncthreads();
        }
    }

#pragma unroll
    for (int im = 0; im < 4; im++) {
#pragma unroll
        for (int jn = 0; jn < 4; jn++) {
            const int lc = wn + jn * 8 + cp;
            const int col = n0 + lc;
            const float ba0 = b1[col], ba1 = b1[col + 1];
            const float bg0 = b1[col + 256], bg1 = b1[col + 257];
            const int row0 = m0 + wm + im * 16 + r8;
#pragma unroll
            for (int half = 0; half < 2; half++) {
                const int row = row0 + half * 8;
                float a0 = acc_a[im][jn][half * 2 + 0] + ba0;
                float a1 = acc_a[im][jn][half * 2 + 1] + ba1;
                float gg0 = acc_g[im][jn][half * 2 + 0] + bg0;
                float gg1 = acc_g[im][jn][half * 2 + 1] + bg1;
                float x0 = a0 * (1.f / (1.f + expf(-gg0)));
                float x1 = a1 * (1.f / (1.f + expf(-gg1)));
                size_t o = (size_t)row * CC + col;
                *reinterpret_cast<float2*>(&X[o]) = make_float2(x0, x1);
                __nv_bfloat16 h0, l0, h1, l1;
                split2(x0, h0, l0); split2(x1, h1, l1);
                __nv_bfloat162 ph; ph.x = h0; ph.y = h1;
                __nv_bfloat162 pl; pl.x = l0; pl.y = l1;
                *reinterpret_cast<__nv_bfloat162*>(&Xhi[o]) = ph;
                *reinterpret_cast<__nv_bfloat162*>(&Xlo[o]) = pl;
            }
        }
    }
}

// ---------------- generic fused split-bf16 GEMM (2 CTAs/SM, ldmatrix) -------
#define STAGE_ELEMS (4 * TILE_ELEMS)
#define GSMEM_BYTES (2 * STAGE_ELEMS * 2)   // 81920

__global__ __launch_bounds__(256, 2) void gemm_split_mma(
    const __nv_bfloat16* __restrict__ Ahi, const __nv_bfloat16* __restrict__ Alo,
    const __nv_bfloat16* __restrict__ Bhi, const __nv_bfloat16* __restrict__ Blo,
    const float* __restrict__ bias, float* __restrict__ Cm,
    int Kt, int ldc, int Nout)
{
    extern __shared__ __align__(16) __nv_bfloat16 sm[];
    const int tid = threadIdx.x;
    const int wid = tid >> 5;
    const int lane = tid & 31;
    const int m0 = blockIdx.y * BMT;
    const int n0 = blockIdx.x * BNT;
    const int wm = (wid & 1) * 64;
    const int wn = (wid >> 1) * 32;
    const int r8 = lane >> 2;
    const int cp = (lane & 3) * 2;

    const int alr = A_LDSM_ROW(lane), alc = A_LDSM_COL(lane);
    const int blr = B_LDSM_ROW(lane), blc = B_LDSM_COL(lane);

    const __nv_bfloat16* srcs[4] = { Ahi, Alo, Bhi, Blo };
    const int bases[4] = { m0, m0, n0, n0 };

    const int c0 = tid, c1 = tid + 256;
    const int lr0 = c0 >> 2, lc0 = (c0 & 3) * 8;
    const int lr1 = c1 >> 2, lc1 = (c1 & 3) * 8;
    const uint32_t smbase = smem_u32(sm);

    float acc[4][4][4];
#pragma unroll
    for (int i = 0; i < 4; i++)
#pragma unroll
        for (int j = 0; j < 4; j++)
#pragma unroll
            for (int q = 0; q < 4; q++) acc[i][j][q] = 0.f;

    const int NK = Kt >> 5;

#pragma unroll
    for (int t = 0; t < 4; t++) {
        const __nv_bfloat16* sp = srcs[t];
        cpa16(smbase + (uint32_t)((t * 128 + lr0) * APAD + lc0) * 2,
              sp + (size_t)(bases[t] + lr0) * Kt + lc0);
        cpa16(smbase + (uint32_t)((t * 128 + lr1) * APAD + lc1) * 2,
              sp + (size_t)(bases[t] + lr1) * Kt + lc1);
    }
    CP_COMMIT();
    CP_WAIT0();
    __syncthreads();

    for (int kc = 0; kc < NK; kc++) {
        if (kc + 1 < NK) {
            const int sb = ((kc + 1) & 1) * STAGE_ELEMS;
            const int k0 = (kc + 1) << 5;
#pragma unroll
            for (int t = 0; t < 4; t++) {
                const __nv_bfloat16* sp = srcs[t];
                cpa16(smbase + (uint32_t)(sb + (t * 128 + lr0) * APAD + lc0) * 2,
                      sp + (size_t)(bases[t] + lr0) * Kt + k0 + lc0);
                cpa16(smbase + (uint32_t)(sb + (t * 128 + lr1) * APAD + lc1) * 2,
                      sp + (size_t)(bases[t] + lr1) * Kt + k0 + lc1);
            }
            CP_COMMIT();
        }
        const uint32_t stg = smbase + (uint32_t)((kc & 1) * STAGE_ELEMS) * 2;
#pragma unroll
        for (int ks = 0; ks < 2; ks++) {
            const int kb = ks * 16;
            uint32_t afh[4][4], afl[4][4];
#pragma unroll
            for (int im = 0; im < 4; im++) {
                const uint32_t aaddr = stg +
                    (uint32_t)(((wm + im * 16 + alr) * APAD + kb + alc) * 2);
                ldsm_x4(afh[im], aaddr);
            }
            uint32_t bfh[4][2], bfl[4][2];
#pragma unroll
            for (int jn = 0; jn < 4; jn++) {
                const uint32_t baddr = stg + 2 * TILE_BYTES_SM +
                    (uint32_t)(((wn + jn * 8 + blr) * APAD + kb + blc) * 2);
                ldsm_x2(bfh[jn], baddr);
                ldsm_x2(bfl[jn], baddr + TILE_BYTES_SM);
            }
#pragma unroll
            for (int im = 0; im < 4; im++)
#pragma unroll
                for (int jn = 0; jn < 4; jn++) {
                    mma16816(acc[im][jn], afh[im][0], afh[im][1], afh[im][2], afh[im][3], bfh[jn][0], bfh[jn][1]);
                    mma16816(acc[im][jn], afh[im][0], afh[im][1], afh[im][2], afh[im][3], bfl[jn][0], bfl[jn][1]);
                }
#pragma unroll
            for (int im = 0; im < 4; im++) {
                const uint32_t aaddr = stg + TILE_BYTES_SM +
                    (uint32_t)(((wm + im * 16 + alr) * APAD + kb + alc) * 2);
                ldsm_x4(afl[im], aaddr);
            }
#pragma unroll
            for (int im = 0; im < 4; im++)
#pragma unroll
                for (int jn = 0; jn < 4; jn++)
                    mma16816(acc[im][jn], afl[im][0], afl[im][1], afl[im][2], afl[im][3], bfh[jn][0], bfh[jn][1]);
        }
        if (kc + 1 < NK) {
            CP_WAIT0();
            __syncthreads();
        }
    }

#pragma unroll
    for (int im = 0; im < 4; im++) {
#pragma unroll
        for (int jn = 0; jn < 4; jn++) {
            const int col = n0 + wn + jn * 8 + cp;
            if (col < Nout) {
                const float bx = bias[col], by = bias[col + 1];
                const int row0 = m0 + wm + im * 16 + r8;
                float2 v0 = { acc[im][jn][0] + bx, acc[im][jn][1] + by };
                float2 v1 = { acc[im][jn][2] + bx, acc[im][jn][3] + by };
                *reinterpret_cast<float2*>(&Cm[(size_t)row0 * ldc + col]) = v0;
                *reinterpret_cast<float2*>(&Cm[(size_t)(row0 + 8) * ldc + col]) = v1;
            }
        }
    }
}

// -------------------- merged prep kernel ------------------------------------
#define S_W1 (C2 * CC)
#define S_W2 (CC * C2)
#define S_WS (NSMPAD * CC)
__global__ __launch_bounds__(256) void prep_all(
    const float* __restrict__ w1, const float* __restrict__ w2,
    const float* __restrict__ wf, const float* __restrict__ ww,
    const float* __restrict__ bf, const float* __restrict__ bw,
    __nv_bfloat16* __restrict__ w1h, __nv_bfloat16* __restrict__ w1l,
    __nv_bfloat16* __restrict__ w2h, __nv_bfloat16* __restrict__ w2l,
    __nv_bfloat16* __restrict__ wsh, __nv_bfloat16* __restrict__ wsl,
    float* __restrict__ bc)
{
    int i = blockIdx.x * 256 + threadIdx.x;
    if (i < S_W1) {
        int n = i / CC, k = i % CC;
        split2(w1[(size_t)k * C2 + n], w1h[i], w1l[i]);
    } else if (i < S_W1 + S_W2) {
        int j = i - S_W1;
        int n = j / C2, k = j % C2;
        split2(w2[(size_t)k * CC + n], w2h[j], w2l[j]);
    } else if (i < S_W1 + S_W2 + S_WS) {
        int j = i - S_W1 - S_W2;
        int n = j / CC, k = j % CC;
        float v = 0.f;
        if (n < KK) v = wf[k * KK + n];
        else if (n < NSMALL) v = ww[k * NWW + (n - KK)];
        split2(v, wsh[j], wsl[j]);
    } else if (i < S_W1 + S_W2 + S_WS + NSP) {
        int j = i - S_W1 - S_W2 - S_WS;
        float v = 0.f;
        if (j < KK) v = bf[j];
        else if (j < NSMALL) v = bw[j - KK];
        bc[j] = v;
    }
}

// ---------- per-token conv + softmax: register-window version ---------------
__global__ __launch_bounds__(256) void post_small(
    const float* __restrict__ raw, const float* __restrict__ x,
    const int* __restrict__ mask, float* __restrict__ attn,
    __nv_bfloat16* __restrict__ zhi, __nv_bfloat16* __restrict__ zlo)
{
    __shared__ float xpad[8][288];
    const int warp = threadIdx.x >> 5;
    const int lane = threadIdx.x & 31;
    const int t = blockIdx.x * 8 + warp;
    const int b = t >> 10;
    const int tt = t & 1023;

    float* xp = xpad[warp];
#pragma unroll
    for (int i = lane; i < 288; i += 32) {
        int c = i - PADK;
        xp[i] = (c >= 0 && c < CC) ? x[(size_t)t * CC + c] : 0.f;
    }
    __syncwarp();

    const float mk = (mask[b * TT + tt] != 0) ? 1.f : 0.f;
    float wv = (lane < KK) ? raw[(size_t)t * NSP + lane] : 0.f;

    float win[40];
#pragma unroll
    for (int i = 0; i < 10; i++)
        *reinterpret_cast<float4*>(&win[i * 4]) =
            *reinterpret_cast<const float4*>(&xp[lane * 8 + i * 4]);

    float acc[8];
#pragma unroll
    for (int d = 0; d < 8; d++) acc[d] = 0.f;
#pragma unroll
    for (int j = 0; j < KK; j++) {
        float wj = __shfl_sync(0xffffffffu, wv, j);
#pragma unroll
        for (int d = 0; d < 8; d++) acc[d] = fmaf(wj, win[d + j], acc[d]);
    }
    {
        __nv_bfloat16 h8[8], l8[8];
#pragma unroll
        for (int d = 0; d < 8; d++) split2(acc[d] * mk, h8[d], l8[d]);
        size_t o = (size_t)t * C2 + CC + lane * 8;
        *reinterpret_cast<uint4*>(&zhi[o]) = *reinterpret_cast<uint4*>(h8);
        *reinterpret_cast<uint4*>(&zlo[o]) = *reinterpret_cast<uint4*>(l8);
    }

    const int s = tt + lane - PADK;
    const bool valid = (lane < KK) && (s >= 0) && (s < TT);
#pragma unroll
    for (int h = 0; h < HH; h++) {
        float v = valid ? raw[(size_t)t * NSP + KK + h * KK + lane] : -INFINITY;
        float mx = v;
#pragma unroll
        for (int o = 16; o; o >>= 1) mx = fmaxf(mx, __shfl_xor_sync(0xffffffffu, mx, o));
        float e = valid ? expf(v - mx) : 0.f;
        float sm = e;
#pragma unroll
        for (int o = 16; o; o >>= 1) sm += __shfl_xor_sync(0xffffffffu, sm, o);
        if (lane < KK) attn[(size_t)t * NWW + h * KK + lane] = e / sm;
    }
}

// ---------- banded attention apply: warp-per-token, shuffle attn ------------
#define TCT 32
#define TCR (TCT + 2 * PADK)   // 62
#define TC_SMEM ((TCR * CC + TCT * NWW) * (int)sizeof(float))
__global__ __launch_bounds__(256) void timeconv(
    const float* __restrict__ x, const float* __restrict__ attn,
    const int* __restrict__ mask,
    __nv_bfloat16* __restrict__ zhi, __nv_bfloat16* __restrict__ zlo)
{
    extern __shared__ float smemf[];
    float* xs = smemf;                       // TCR * CC
    float* ats = smemf + TCR * CC;           // TCT * NWW
    __shared__ float msk[TCT];

    const int b = blockIdx.x >> 5;
    const int tb = (blockIdx.x & 31) * TCT;
    const int tid = threadIdx.x;
    const int warp = tid >> 5;
    const int lane = tid & 31;

    for (int r = 0; r < TCR; r++) {
        int s = tb - PADK + r;
        xs[r * CC + tid] = (s >= 0 && s < TT)
            ? x[((size_t)b * TT + s) * CC + tid] : 0.f;
    }
    for (int i = tid; i < TCT * NWW; i += 256)
        ats[i] = attn[((size_t)b * TT + tb) * NWW + i];
    if (tid < TCT) msk[tid] = (mask[b * TT + tb + tid] != 0) ? 1.f : 0.f;
    __syncthreads();

#pragma unroll
    for (int it = 0; it < 4; it++) {
        const int tt = warp * 4 + it;
        float wv0 = (lane < KK) ? ats[tt * NWW + 0 * KK + lane] : 0.f;
        float wv1 = (lane < KK) ? ats[tt * NWW + 1 * KK + lane] : 0.f;
        float wv2 = (lane < KK) ? ats[tt * NWW + 2 * KK + lane] : 0.f;
        float wv3 = (lane < KK) ? ats[tt * NWW + 3 * KK + lane] : 0.f;
        float acc[8];
#pragma unroll
        for (int g = 0; g < 8; g++) acc[g] = 0.f;
#pragma unroll
        for (int j = 0; j < KK; j++) {
            float w0 = __shfl_sync(0xffffffffu, wv0, j);
            float w1 = __shfl_sync(0xffffffffu, wv1, j);
            float w2 = __shfl_sync(0xffffffffu, wv2, j);
            float w3 = __shfl_sync(0xffffffffu, wv3, j);
            const float* xr = &xs[(tt + j) * CC + lane];
            acc[0] = fmaf(w0, xr[0 * 32], acc[0]);
            acc[1] = fmaf(w0, xr[1 * 32], acc[1]);
            acc[2] = fmaf(w1, xr[2 * 32], acc[2]);
            acc[3] = fmaf(w1, xr[3 * 32], acc[3]);
            acc[4] = fmaf(w2, xr[4 * 32], acc[4]);
            acc[5] = fmaf(w2, xr[5 * 32], acc[5]);
            acc[6] = fmaf(w3, xr[6 * 32], acc[6]);
            acc[7] = fmaf(w3, xr[7 * 32], acc[7]);
        }
        const float mv = msk[tt];
        const size_t obase = ((size_t)b * TT + tb + tt) * C2 + lane;
#pragma unroll
        for (int g = 0; g < 8; g++) {
            __nv_bfloat16 h_, l_;
            split2(acc[g] * mv, h_, l_);
            zhi[obase + g * 32] = h_;
            zlo[obase + g * 32] = l_;
        }
    }
}

// ---------------------------------------------------------------------------
extern "C" void kernel_launch(void* const* d_in, const int* in_sizes, int n_in,
                              void* d_out, int out_size)
{
    const float* query = (const float*)d_in[0];
    const int* mask = (const int*)d_in[3];
    const float* w1 = (const float*)d_in[4];
    const float* b1 = (const float*)d_in[5];
    const float* w2 = (const float*)d_in[6];
    const float* b2 = (const float*)d_in[7];
    const float* ww = (const float*)d_in[8];
    const float* bw = (const float*)d_in[9];
    const float* wf = (const float*)d_in[10];
    const float* bf = (const float*)d_in[11];
    float* out = (float*)d_out;

    void* p;
    cudaGetSymbolAddress(&p, g_x);      float* dx = (float*)p;
    cudaGetSymbolAddress(&p, g_xhi);    __nv_bfloat16* dxhi = (__nv_bfloat16*)p;
    cudaGetSymbolAddress(&p, g_xlo);    __nv_bfloat16* dxlo = (__nv_bfloat16*)p;
    cudaGetSymbolAddress(&p, g_zhi);    __nv_bfloat16* dzhi = (__nv_bfloat16*)p;
    cudaGetSymbolAddress(&p, g_zlo);    __nv_bfloat16* dzlo = (__nv_bfloat16*)p;
    cudaGetSymbolAddress(&p, g_raw);    float* draw = (float*)p;
    cudaGetSymbolAddress(&p, g_attn);   float* dattn = (float*)p;
    cudaGetSymbolAddress(&p, g_w1t_hi); __nv_bfloat16* w1h = (__nv_bfloat16*)p;
    cudaGetSymbolAddress(&p, g_w1t_lo); __nv_bfloat16* w1l = (__nv_bfloat16*)p;
    cudaGetSymbolAddress(&p, g_w2t_hi); __nv_bfloat16* w2h = (__nv_bfloat16*)p;
    cudaGetSymbolAddress(&p, g_w2t_lo); __nv_bfloat16* w2l = (__nv_bfloat16*)p;
    cudaGetSymbolAddress(&p, g_wst_hi); __nv_bfloat16* wsh = (__nv_bfloat16*)p;
    cudaGetSymbolAddress(&p, g_wst_lo); __nv_bfloat16* wsl = (__nv_bfloat16*)p;
    cudaGetSymbolAddress(&p, g_bsmall); float* dbs = (float*)p;

    static bool attr_done = false;
    if (!attr_done) {
        cudaFuncSetAttribute(gemm1_glu,
                             cudaFuncAttributeMaxDynamicSharedMemorySize, G1_SMEM_BYTES);
        cudaFuncSetAttribute(gemm_split_mma,
                             cudaFuncAttributeMaxDynamicSharedMemorySize, GSMEM_BYTES);
        cudaFuncSetAttribute(timeconv,
                             cudaFuncAttributeMaxDynamicSharedMemorySize, TC_SMEM);
        attr_done = true;
    }

    // prep: all weight splits in one launch
    prep_all<<<(S_W1 + S_W2 + S_WS + NSP + 255) / 256, 256>>>(
        w1, w2, wf, ww, bf, bw, w1h, w1l, w2h, w2l, wsh, wsl, dbs);

    // 1) x = GLU(query @ w1 + b1), fused
    gemm1_glu<<<dim3(2, BT / BMT), 256, G1_SMEM_BYTES>>>(
        query, w1h, w1l, b1, dx, dxhi, dxlo);
    // 2) raw = x @ [wf|ww] + [bf|bw]
    gemm_split_mma<<<dim3(NSMPAD / BNT, BT / BMT), 256, GSMEM_BYTES>>>(
        dxhi, dxlo, wsh, wsl, dbs, draw, CC, NSP, NSP);
    // 3) channel conv xf + banded softmax
    post_small<<<BT / 8, 256>>>(draw, dx, mask, dattn, dzhi, dzlo);
    // 4) banded attention apply
    timeconv<<<BB * (TT / TCT), 256, TC_SMEM>>>(dx, dattn, mask, dzhi, dzlo);
    // 5) out = z @ w2 + b2
    gemm_split_mma<<<dim3(CC / BNT, BT / BMT), 256, GSMEM_BYTES>>>(
        dzhi, dzlo, w2h, w2l, b2, out, C2, CC, CC);
}

// round 15
// speedup vs baseline: 1.5507x; 1.0208x over previous
#include <cuda_runtime.h>
#include <cuda_bf16.h>
#include <math.h>
#include <stdint.h>

// Problem constants
#define BB 16
#define TT 1024
#define CC 256
#define HH 4
#define KK 31
#define PADK 15
#define BT (BB * TT)          // 16384 tokens
#define C2 (2 * CC)           // 512
#define NSMALL (KK + HH * KK) // 155
#define NSP 160               // padded row stride for raw
#define NWW (HH * KK)         // 124
#define NSMPAD 256            // padded N rows for small weight

// -------------------- device scratch ---------------------------------------
__device__ float g_x[(size_t)BT * CC];
__device__ __nv_bfloat16 g_xhi[(size_t)BT * CC];
__device__ __nv_bfloat16 g_xlo[(size_t)BT * CC];
__device__ __nv_bfloat16 g_zhi[(size_t)BT * C2];
__device__ __nv_bfloat16 g_zlo[(size_t)BT * C2];
__device__ float g_raw[(size_t)BT * NSP];
__device__ float g_attn[(size_t)BT * NWW];
__device__ __nv_bfloat16 g_w1t_hi[(size_t)C2 * CC];
__device__ __nv_bfloat16 g_w1t_lo[(size_t)C2 * CC];
__device__ __nv_bfloat16 g_w2t_hi[(size_t)CC * C2];
__device__ __nv_bfloat16 g_w2t_lo[(size_t)CC * C2];
__device__ __nv_bfloat16 g_wst_hi[(size_t)NSMPAD * CC];
__device__ __nv_bfloat16 g_wst_lo[(size_t)NSMPAD * CC];
__device__ float g_bsmall[NSP];

static __device__ __forceinline__ void split2(float v, __nv_bfloat16& h, __nv_bfloat16& l) {
    h = __float2bfloat16(v);
    l = __float2bfloat16(v - __bfloat162float(h));
}

__device__ __forceinline__ void mma16816(float* c, uint32_t a0, uint32_t a1,
                                         uint32_t a2, uint32_t a3,
                                         uint32_t b0, uint32_t b1) {
    asm volatile(
        "mma.sync.aligned.m16n8k16.row.col.f32.bf16.bf16.f32 "
        "{%0,%1,%2,%3}, {%4,%5,%6,%7}, {%8,%9}, {%0,%1,%2,%3};"
        : "+f"(c[0]), "+f"(c[1]), "+f"(c[2]), "+f"(c[3])
        : "r"(a0), "r"(a1), "r"(a2), "r"(a3), "r"(b0), "r"(b1));
}

__device__ __forceinline__ void ldsm_x4(uint32_t* r, uint32_t saddr) {
    asm volatile("ldmatrix.sync.aligned.m8n8.x4.shared.b16 {%0,%1,%2,%3}, [%4];"
                 : "=r"(r[0]), "=r"(r[1]), "=r"(r[2]), "=r"(r[3]) : "r"(saddr));
}
__device__ __forceinline__ void ldsm_x2(uint32_t* r, uint32_t saddr) {
    asm volatile("ldmatrix.sync.aligned.m8n8.x2.shared.b16 {%0,%1}, [%2];"
                 : "=r"(r[0]), "=r"(r[1]) : "r"(saddr));
}

__device__ __forceinline__ uint32_t smem_u32(const void* p) {
    uint32_t a;
    asm("{ .reg .u64 t; cvta.to.shared.u64 t, %1; cvt.u32.u64 %0, t; }"
        : "=r"(a) : "l"(p));
    return a;
}
__device__ __forceinline__ void cpa16(uint32_t saddr, const void* g) {
    asm volatile("cp.async.cg.shared.global [%0], [%1], 16;" :: "r"(saddr), "l"(g));
}
#define CP_COMMIT() asm volatile("cp.async.commit_group;" ::: "memory")
#define CP_WAIT0()  asm volatile("cp.async.wait_group 0;" ::: "memory")

#define BMT 128
#define BNT 128
#define APAD 40   // bf16 elems per smem row
#define TILE_ELEMS (128 * APAD)
#define TILE_BYTES_SM (TILE_ELEMS * 2)

// ldmatrix per-lane address components
#define A_LDSM_ROW(lane) (((lane) & 7) + (((lane) >> 3) & 1) * 8)
#define A_LDSM_COL(lane) ((((lane) >> 4) & 1) * 8)
#define B_LDSM_ROW(lane) ((lane) & 7)
#define B_LDSM_COL(lane) ((((lane) >> 3) & 1) * 8)

// ============ fused GEMM1 + GLU + split: 128x64 twin tile, 2 CTAs/SM ========
// grid (4, BT/128). CTA: a-cols [bx*64, bx*64+64), g-cols at +256.
// 8 warps: 2M x 4N, warp tile 64(M) x 16(N) for each of a/g.
// Stage: region0=Ahi(128r), region1=Alo(128r), region2=Bah(64r)+Bal(64r),
//        region3=Bgh(64r)+Bgl(64r).  40KB/stage, double-buffered.
#define G1_STAGE (4 * TILE_ELEMS)
#define G1_SMEM_BYTES (2 * G1_STAGE * 2)   // 81920

__global__ __launch_bounds__(256, 2) void gemm1_glu(
    const float* __restrict__ Q,
    const __nv_bfloat16* __restrict__ Wh, const __nv_bfloat16* __restrict__ Wl,
    const float* __restrict__ b1,
    float* __restrict__ X, __nv_bfloat16* __restrict__ Xhi,
    __nv_bfloat16* __restrict__ Xlo)
{
    extern __shared__ __align__(16) __nv_bfloat16 sm[];
    const int tid = threadIdx.x;
    const int wid = tid >> 5;
    const int lane = tid & 31;
    const int m0 = blockIdx.y * BMT;
    const int na0 = blockIdx.x * 64;       // a-col base; g at na0+256
    const int wm = (wid & 1) * 64;
    const int wn = (wid >> 1) * 16;        // 4 N-warps x 16
    const int r8 = lane >> 2;
    const int cp = (lane & 3) * 2;
    const uint32_t smbase = smem_u32(sm);

    const int alr = A_LDSM_ROW(lane), alc = A_LDSM_COL(lane);
    const int blr = B_LDSM_ROW(lane), blc = B_LDSM_COL(lane);

    // B loader: 4 chunks/thread over 1024 chunk ids (4 sub-tiles x 64r x 4cc)
    const __nv_bfloat16* bsrc[4] = { Wh, Wl, Wh, Wl };
    const int brow[4] = { na0, na0, na0 + 256, na0 + 256 };
    int btt[4], brr[4]; uint32_t bdst[4];
#pragma unroll
    for (int i = 0; i < 4; i++) {
        const int c = tid + i * 256;
        const int t = c >> 8, rem = c & 255;
        const int row = rem >> 2, q = (rem & 3) * 8;
        btt[i] = t; brr[i] = row * 4 + (rem & 3); // row*CC chunk idx helper unused
        brr[i] = row; // keep row
        bdst[i] = (uint32_t)(((2 + (t >> 1)) * 128 + (t & 1) * 64 + row) * APAD + q) * 2;
    }
    // A loader: 2 chunks/thread (128 rows x 4 colchunks = 512)
    const int c0 = tid, c1 = tid + 256;
    const int r0c = c0 >> 2, q0c = (c0 & 3) * 8;
    const int r1c = c1 >> 2, q1c = (c1 & 3) * 8;

    float acc_a[4][2][4], acc_g[4][2][4];
#pragma unroll
    for (int i = 0; i < 4; i++)
#pragma unroll
        for (int j = 0; j < 2; j++)
#pragma unroll
            for (int q = 0; q < 4; q++) { acc_a[i][j][q] = 0.f; acc_g[i][j][q] = 0.f; }

    const int NK = CC / 32;  // 8
    float apre[2][8];

    // ---- prologue: stage 0
#pragma unroll
    for (int i = 0; i < 4; i++) {
        const int t = btt[i], row = brr[i];
        const int q = ((tid + i * 256) & 3) * 8;
        cpa16(smbase + bdst[i],
              bsrc[t] + (size_t)(brow[t] + row) * CC + q);
    }
    CP_COMMIT();
    {
        *reinterpret_cast<float4*>(&apre[0][0]) = *reinterpret_cast<const float4*>(&Q[(size_t)(m0 + r0c) * CC + q0c]);
        *reinterpret_cast<float4*>(&apre[0][4]) = *reinterpret_cast<const float4*>(&Q[(size_t)(m0 + r0c) * CC + q0c + 4]);
        *reinterpret_cast<float4*>(&apre[1][0]) = *reinterpret_cast<const float4*>(&Q[(size_t)(m0 + r1c) * CC + q1c]);
        *reinterpret_cast<float4*>(&apre[1][4]) = *reinterpret_cast<const float4*>(&Q[(size_t)(m0 + r1c) * CC + q1c + 4]);
        __nv_bfloat16 h8[8], l8[8];
#pragma unroll
        for (int e = 0; e < 8; e++) split2(apre[0][e], h8[e], l8[e]);
        *reinterpret_cast<uint4*>(&sm[(0 * 128 + r0c) * APAD + q0c]) = *reinterpret_cast<uint4*>(h8);
        *reinterpret_cast<uint4*>(&sm[(1 * 128 + r0c) * APAD + q0c]) = *reinterpret_cast<uint4*>(l8);
#pragma unroll
        for (int e = 0; e < 8; e++) split2(apre[1][e], h8[e], l8[e]);
        *reinterpret_cast<uint4*>(&sm[(0 * 128 + r1c) * APAD + q1c]) = *reinterpret_cast<uint4*>(h8);
        *reinterpret_cast<uint4*>(&sm[(1 * 128 + r1c) * APAD + q1c]) = *reinterpret_cast<uint4*>(l8);
    }
    CP_WAIT0();
    __syncthreads();

    for (int kc = 0; kc < NK; kc++) {
        const int nxt = kc + 1;
        if (nxt < NK) {
            const int sb = (nxt & 1) * G1_STAGE;
            const int k0 = nxt << 5;
#pragma unroll
            for (int i = 0; i < 4; i++) {
                const int t = btt[i], row = brr[i];
                const int q = ((tid + i * 256) & 3) * 8;
                cpa16(smbase + (uint32_t)(sb * 2) + bdst[i],
                      bsrc[t] + (size_t)(brow[t] + row) * CC + k0 + q);
            }
            CP_COMMIT();
            *reinterpret_cast<float4*>(&apre[0][0]) = *reinterpret_cast<const float4*>(&Q[(size_t)(m0 + r0c) * CC + k0 + q0c]);
            *reinterpret_cast<float4*>(&apre[0][4]) = *reinterpret_cast<const float4*>(&Q[(size_t)(m0 + r0c) * CC + k0 + q0c + 4]);
            *reinterpret_cast<float4*>(&apre[1][0]) = *reinterpret_cast<const float4*>(&Q[(size_t)(m0 + r1c) * CC + k0 + q1c]);
            *reinterpret_cast<float4*>(&apre[1][4]) = *reinterpret_cast<const float4*>(&Q[(size_t)(m0 + r1c) * CC + k0 + q1c + 4]);
        }

        const uint32_t stg = smbase + (uint32_t)((kc & 1) * G1_STAGE) * 2;
#pragma unroll
        for (int ks = 0; ks < 2; ks++) {
            const int kb = ks * 16;
            uint32_t afh[4][4], afl[4][4];
#pragma unroll
            for (int im = 0; im < 4; im++) {
                const uint32_t aaddr = stg +
                    (uint32_t)(((wm + im * 16 + alr) * APAD + kb + alc) * 2);
                ldsm_x4(afh[im], aaddr);
            }
            // B a-half (region2): Bah rows 0-63, Bal rows 64-127
            uint32_t bh[2][2], bl[2][2], gh[2][2], gl[2][2];
#pragma unroll
            for (int jn = 0; jn < 2; jn++) {
                const uint32_t ba = stg + 2 * TILE_BYTES_SM +
                    (uint32_t)(((wn + jn * 8 + blr) * APAD + kb + blc) * 2);
                ldsm_x2(bh[jn], ba);
                ldsm_x2(bl[jn], ba + (uint32_t)(64 * APAD * 2));
                const uint32_t bg = stg + 3 * TILE_BYTES_SM +
                    (uint32_t)(((wn + jn * 8 + blr) * APAD + kb + blc) * 2);
                ldsm_x2(gh[jn], bg);
                ldsm_x2(gl[jn], bg + (uint32_t)(64 * APAD * 2));
            }
            // hh + hl combos
#pragma unroll
            for (int im = 0; im < 4; im++)
#pragma unroll
                for (int jn = 0; jn < 2; jn++) {
                    mma16816(acc_a[im][jn], afh[im][0], afh[im][1], afh[im][2], afh[im][3], bh[jn][0], bh[jn][1]);
                    mma16816(acc_a[im][jn], afh[im][0], afh[im][1], afh[im][2], afh[im][3], bl[jn][0], bl[jn][1]);
                    mma16816(acc_g[im][jn], afh[im][0], afh[im][1], afh[im][2], afh[im][3], gh[jn][0], gh[jn][1]);
                    mma16816(acc_g[im][jn], afh[im][0], afh[im][1], afh[im][2], afh[im][3], gl[jn][0], gl[jn][1]);
                }
            // lh combo
#pragma unroll
            for (int im = 0; im < 4; im++) {
                const uint32_t aaddr = stg + TILE_BYTES_SM +
                    (uint32_t)(((wm + im * 16 + alr) * APAD + kb + alc) * 2);
                ldsm_x4(afl[im], aaddr);
            }
#pragma unroll
            for (int im = 0; im < 4; im++)
#pragma unroll
                for (int jn = 0; jn < 2; jn++) {
                    mma16816(acc_a[im][jn], afl[im][0], afl[im][1], afl[im][2], afl[im][3], bh[jn][0], bh[jn][1]);
                    mma16816(acc_g[im][jn], afl[im][0], afl[im][1], afl[im][2], afl[im][3], gh[jn][0], gh[jn][1]);
                }
        }

        if (nxt < NK) {
            const int sb = (nxt & 1) * G1_STAGE;
            __nv_bfloat16 h8[8], l8[8];
#pragma unroll
            for (int e = 0; e < 8; e++) split2(apre[0][e], h8[e], l8[e]);
            *reinterpret_cast<uint4*>(&sm[sb + (0 * 128 + r0c) * APAD + q0c]) = *reinterpret_cast<uint4*>(h8);
            *reinterpret_cast<uint4*>(&sm[sb + (1 * 128 + r0c) * APAD + q0c]) = *reinterpret_cast<uint4*>(l8);
#pragma unroll
            for (int e = 0; e < 8; e++) split2(apre[1][e], h8[e], l8[e]);
            *reinterpret_cast<uint4*>(&sm[sb + (0 * 128 + r1c) * APAD + q1c]) = *reinterpret_cast<uint4*>(h8);
            *reinterpret_cast<uint4*>(&sm[sb + (1 * 128 + r1c) * APAD + q1c]) = *reinterpret_cast<uint4*>(l8);
            CP_WAIT0();
            __syncthreads();
        }
    }

    // ---- epilogue: GLU + split
#pragma unroll
    for (int im = 0; im < 4; im++) {
#pragma unroll
        for (int jn = 0; jn < 2; jn++) {
            const int col = na0 + wn + jn * 8 + cp;
            const float ba0 = b1[col], ba1 = b1[col + 1];
            const float bg0 = b1[col + 256], bg1 = b1[col + 257];
            const int row0 = m0 + wm + im * 16 + r8;
#pragma unroll
            for (int half = 0; half < 2; half++) {
                const int row = row0 + half * 8;
                float a0 = acc_a[im][jn][half * 2 + 0] + ba0;
                float a1 = acc_a[im][jn][half * 2 + 1] + ba1;
                float gg0 = acc_g[im][jn][half * 2 + 0] + bg0;
                float gg1 = acc_g[im][jn][half * 2 + 1] + bg1;
                float x0 = a0 * (1.f / (1.f + expf(-gg0)));
                float x1 = a1 * (1.f / (1.f + expf(-gg1)));
                size_t o = (size_t)row * CC + col;
                *reinterpret_cast<float2*>(&X[o]) = make_float2(x0, x1);
                __nv_bfloat16 h0, l0, h1, l1;
                split2(x0, h0, l0); split2(x1, h1, l1);
                __nv_bfloat162 ph; ph.x = h0; ph.y = h1;
                __nv_bfloat162 pl; pl.x = l0; pl.y = l1;
                *reinterpret_cast<__nv_bfloat162*>(&Xhi[o]) = ph;
                *reinterpret_cast<__nv_bfloat162*>(&Xlo[o]) = pl;
            }
        }
    }
}

// ---------------- generic fused split-bf16 GEMM (2 CTAs/SM, ldmatrix) -------
#define STAGE_ELEMS (4 * TILE_ELEMS)
#define GSMEM_BYTES (2 * STAGE_ELEMS * 2)   // 81920

__global__ __launch_bounds__(256, 2) void gemm_split_mma(
    const __nv_bfloat16* __restrict__ Ahi, const __nv_bfloat16* __restrict__ Alo,
    const __nv_bfloat16* __restrict__ Bhi, const __nv_bfloat16* __restrict__ Blo,
    const float* __restrict__ bias, float* __restrict__ Cm,
    int Kt, int ldc, int Nout)
{
    extern __shared__ __align__(16) __nv_bfloat16 sm[];
    const int tid = threadIdx.x;
    const int wid = tid >> 5;
    const int lane = tid & 31;
    const int m0 = blockIdx.y * BMT;
    const int n0 = blockIdx.x * BNT;
    const int wm = (wid & 1) * 64;
    const int wn = (wid >> 1) * 32;
    const int r8 = lane >> 2;
    const int cp = (lane & 3) * 2;

    const int alr = A_LDSM_ROW(lane), alc = A_LDSM_COL(lane);
    const int blr = B_LDSM_ROW(lane), blc = B_LDSM_COL(lane);

    const __nv_bfloat16* srcs[4] = { Ahi, Alo, Bhi, Blo };
    const int bases[4] = { m0, m0, n0, n0 };

    const int c0 = tid, c1 = tid + 256;
    const int lr0 = c0 >> 2, lc0 = (c0 & 3) * 8;
    const int lr1 = c1 >> 2, lc1 = (c1 & 3) * 8;
    const uint32_t smbase = smem_u32(sm);

    float acc[4][4][4];
#pragma unroll
    for (int i = 0; i < 4; i++)
#pragma unroll
        for (int j = 0; j < 4; j++)
#pragma unroll
            for (int q = 0; q < 4; q++) acc[i][j][q] = 0.f;

    const int NK = Kt >> 5;

#pragma unroll
    for (int t = 0; t < 4; t++) {
        const __nv_bfloat16* sp = srcs[t];
        cpa16(smbase + (uint32_t)((t * 128 + lr0) * APAD + lc0) * 2,
              sp + (size_t)(bases[t] + lr0) * Kt + lc0);
        cpa16(smbase + (uint32_t)((t * 128 + lr1) * APAD + lc1) * 2,
              sp + (size_t)(bases[t] + lr1) * Kt + lc1);
    }
    CP_COMMIT();
    CP_WAIT0();
    __syncthreads();

    for (int kc = 0; kc < NK; kc++) {
        if (kc + 1 < NK) {
            const int sb = ((kc + 1) & 1) * STAGE_ELEMS;
            const int k0 = (kc + 1) << 5;
#pragma unroll
            for (int t = 0; t < 4; t++) {
                const __nv_bfloat16* sp = srcs[t];
                cpa16(smbase + (uint32_t)(sb + (t * 128 + lr0) * APAD + lc0) * 2,
                      sp + (size_t)(bases[t] + lr0) * Kt + k0 + lc0);
                cpa16(smbase + (uint32_t)(sb + (t * 128 + lr1) * APAD + lc1) * 2,
                      sp + (size_t)(bases[t] + lr1) * Kt + k0 + lc1);
            }
            CP_COMMIT();
        }
        const uint32_t stg = smbase + (uint32_t)((kc & 1) * STAGE_ELEMS) * 2;
#pragma unroll
        for (int ks = 0; ks < 2; ks++) {
            const int kb = ks * 16;
            uint32_t afh[4][4], afl[4][4];
#pragma unroll
            for (int im = 0; im < 4; im++) {
                const uint32_t aaddr = stg +
                    (uint32_t)(((wm + im * 16 + alr) * APAD + kb + alc) * 2);
                ldsm_x4(afh[im], aaddr);
            }
            uint32_t bfh[4][2], bfl[4][2];
#pragma unroll
            for (int jn = 0; jn < 4; jn++) {
                const uint32_t baddr = stg + 2 * TILE_BYTES_SM +
                    (uint32_t)(((wn + jn * 8 + blr) * APAD + kb + blc) * 2);
                ldsm_x2(bfh[jn], baddr);
                ldsm_x2(bfl[jn], baddr + TILE_BYTES_SM);
            }
#pragma unroll
            for (int im = 0; im < 4; im++)
#pragma unroll
                for (int jn = 0; jn < 4; jn++) {
                    mma16816(acc[im][jn], afh[im][0], afh[im][1], afh[im][2], afh[im][3], bfh[jn][0], bfh[jn][1]);
                    mma16816(acc[im][jn], afh[im][0], afh[im][1], afh[im][2], afh[im][3], bfl[jn][0], bfl[jn][1]);
                }
#pragma unroll
            for (int im = 0; im < 4; im++) {
                const uint32_t aaddr = stg + TILE_BYTES_SM +
                    (uint32_t)(((wm + im * 16 + alr) * APAD + kb + alc) * 2);
                ldsm_x4(afl[im], aaddr);
            }
#pragma unroll
            for (int im = 0; im < 4; im++)
#pragma unroll
                for (int jn = 0; jn < 4; jn++)
                    mma16816(acc[im][jn], afl[im][0], afl[im][1], afl[im][2], afl[im][3], bfh[jn][0], bfh[jn][1]);
        }
        if (kc + 1 < NK) {
            CP_WAIT0();
            __syncthreads();
        }
    }

#pragma unroll
    for (int im = 0; im < 4; im++) {
#pragma unroll
        for (int jn = 0; jn < 4; jn++) {
            const int col = n0 + wn + jn * 8 + cp;
            if (col < Nout) {
                const float bx = bias[col], by = bias[col + 1];
                const int row0 = m0 + wm + im * 16 + r8;
                float2 v0 = { acc[im][jn][0] + bx, acc[im][jn][1] + by };
                float2 v1 = { acc[im][jn][2] + bx, acc[im][jn][3] + by };
                *reinterpret_cast<float2*>(&Cm[(size_t)row0 * ldc + col]) = v0;
                *reinterpret_cast<float2*>(&Cm[(size_t)(row0 + 8) * ldc + col]) = v1;
            }
        }
    }
}

// -------------------- merged prep kernel ------------------------------------
#define S_W1 (C2 * CC)
#define S_W2 (CC * C2)
#define S_WS (NSMPAD * CC)
__global__ __launch_bounds__(256) void prep_all(
    const float* __restrict__ w1, const float* __restrict__ w2,
    const float* __restrict__ wf, const float* __restrict__ ww,
    const float* __restrict__ bf, const float* __restrict__ bw,
    __nv_bfloat16* __restrict__ w1h, __nv_bfloat16* __restrict__ w1l,
    __nv_bfloat16* __restrict__ w2h, __nv_bfloat16* __restrict__ w2l,
    __nv_bfloat16* __restrict__ wsh, __nv_bfloat16* __restrict__ wsl,
    float* __restrict__ bc)
{
    int i = blockIdx.x * 256 + threadIdx.x;
    if (i < S_W1) {
        int n = i / CC, k = i % CC;
        split2(w1[(size_t)k * C2 + n], w1h[i], w1l[i]);
    } else if (i < S_W1 + S_W2) {
        int j = i - S_W1;
        int n = j / C2, k = j % C2;
        split2(w2[(size_t)k * CC + n], w2h[j], w2l[j]);
    } else if (i < S_W1 + S_W2 + S_WS) {
        int j = i - S_W1 - S_W2;
        int n = j / CC, k = j % CC;
        float v = 0.f;
        if (n < KK) v = wf[k * KK + n];
        else if (n < NSMALL) v = ww[k * NWW + (n - KK)];
        split2(v, wsh[j], wsl[j]);
    } else if (i < S_W1 + S_W2 + S_WS + NSP) {
        int j = i - S_W1 - S_W2 - S_WS;
        float v = 0.f;
        if (j < KK) v = bf[j];
        else if (j < NSMALL) v = bw[j - KK];
        bc[j] = v;
    }
}

// ---------- per-token conv + softmax: register-window version ---------------
__global__ __launch_bounds__(256) void post_small(
    const float* __restrict__ raw, const float* __restrict__ x,
    const int* __restrict__ mask, float* __restrict__ attn,
    __nv_bfloat16* __restrict__ zhi, __nv_bfloat16* __restrict__ zlo)
{
    __shared__ float xpad[8][288];
    const int warp = threadIdx.x >> 5;
    const int lane = threadIdx.x & 31;
    const int t = blockIdx.x * 8 + warp;
    const int b = t >> 10;
    const int tt = t & 1023;

    float* xp = xpad[warp];
#pragma unroll
    for (int i = lane; i < 288; i += 32) {
        int c = i - PADK;
        xp[i] = (c >= 0 && c < CC) ? x[(size_t)t * CC + c] : 0.f;
    }
    __syncwarp();

    const float mk = (mask[b * TT + tt] != 0) ? 1.f : 0.f;
    float wv = (lane < KK) ? raw[(size_t)t * NSP + lane] : 0.f;

    float win[40];
#pragma unroll
    for (int i = 0; i < 10; i++)
        *reinterpret_cast<float4*>(&win[i * 4]) =
            *reinterpret_cast<const float4*>(&xp[lane * 8 + i * 4]);

    float acc[8];
#pragma unroll
    for (int d = 0; d < 8; d++) acc[d] = 0.f;
#pragma unroll
    for (int j = 0; j < KK; j++) {
        float wj = __shfl_sync(0xffffffffu, wv, j);
#pragma unroll
        for (int d = 0; d < 8; d++) acc[d] = fmaf(wj, win[d + j], acc[d]);
    }
    {
        __nv_bfloat16 h8[8], l8[8];
#pragma unroll
        for (int d = 0; d < 8; d++) split2(acc[d] * mk, h8[d], l8[d]);
        size_t o = (size_t)t * C2 + CC + lane * 8;
        *reinterpret_cast<uint4*>(&zhi[o]) = *reinterpret_cast<uint4*>(h8);
        *reinterpret_cast<uint4*>(&zlo[o]) = *reinterpret_cast<uint4*>(l8);
    }

    const int s = tt + lane - PADK;
    const bool valid = (lane < KK) && (s >= 0) && (s < TT);
#pragma unroll
    for (int h = 0; h < HH; h++) {
        float v = valid ? raw[(size_t)t * NSP + KK + h * KK + lane] : -INFINITY;
        float mx = v;
#pragma unroll
        for (int o = 16; o; o >>= 1) mx = fmaxf(mx, __shfl_xor_sync(0xffffffffu, mx, o));
        float e = valid ? expf(v - mx) : 0.f;
        float sm = e;
#pragma unroll
        for (int o = 16; o; o >>= 1) sm += __shfl_xor_sync(0xffffffffu, sm, o);
        if (lane < KK) attn[(size_t)t * NWW + h * KK + lane] = e / sm;
    }
}

// ---------- banded attention apply: warp-per-token, shuffle attn ------------
#define TCT 32
#define TCR (TCT + 2 * PADK)   // 62
#define TC_SMEM ((TCR * CC + TCT * NWW) * (int)sizeof(float))
__global__ __launch_bounds__(256) void timeconv(
    const float* __restrict__ x, const float* __restrict__ attn,
    const int* __restrict__ mask,
    __nv_bfloat16* __restrict__ zhi, __nv_bfloat16* __restrict__ zlo)
{
    extern __shared__ float smemf[];
    float* xs = smemf;                       // TCR * CC
    float* ats = smemf + TCR * CC;           // TCT * NWW
    __shared__ float msk[TCT];

    const int b = blockIdx.x >> 5;
    const int tb = (blockIdx.x & 31) * TCT;
    const int tid = threadIdx.x;
    const int warp = tid >> 5;
    const int lane = tid & 31;

    for (int r = 0; r < TCR; r++) {
        int s = tb - PADK + r;
        xs[r * CC + tid] = (s >= 0 && s < TT)
            ? x[((size_t)b * TT + s) * CC + tid] : 0.f;
    }
    for (int i = tid; i < TCT * NWW; i += 256)
        ats[i] = attn[((size_t)b * TT + tb) * NWW + i];
    if (tid < TCT) msk[tid] = (mask[b * TT + tb + tid] != 0) ? 1.f : 0.f;
    __syncthreads();

#pragma unroll
    for (int it = 0; it < 4; it++) {
        const int tt = warp * 4 + it;
        float wv0 = (lane < KK) ? ats[tt * NWW + 0 * KK + lane] : 0.f;
        float wv1 = (lane < KK) ? ats[tt * NWW + 1 * KK + lane] : 0.f;
        float wv2 = (lane < KK) ? ats[tt * NWW + 2 * KK + lane] : 0.f;
        float wv3 = (lane < KK) ? ats[tt * NWW + 3 * KK + lane] : 0.f;
        float acc[8];
#pragma unroll
        for (int g = 0; g < 8; g++) acc[g] = 0.f;
#pragma unroll
        for (int j = 0; j < KK; j++) {
            float w0 = __shfl_sync(0xffffffffu, wv0, j);
            float w1 = __shfl_sync(0xffffffffu, wv1, j);
            float w2 = __shfl_sync(0xffffffffu, wv2, j);
            float w3 = __shfl_sync(0xffffffffu, wv3, j);
            const float* xr = &xs[(tt + j) * CC + lane];
            acc[0] = fmaf(w0, xr[0 * 32], acc[0]);
            acc[1] = fmaf(w0, xr[1 * 32], acc[1]);
            acc[2] = fmaf(w1, xr[2 * 32], acc[2]);
            acc[3] = fmaf(w1, xr[3 * 32], acc[3]);
            acc[4] = fmaf(w2, xr[4 * 32], acc[4]);
            acc[5] = fmaf(w2, xr[5 * 32], acc[5]);
            acc[6] = fmaf(w3, xr[6 * 32], acc[6]);
            acc[7] = fmaf(w3, xr[7 * 32], acc[7]);
        }
        const float mv = msk[tt];
        const size_t obase = ((size_t)b * TT + tb + tt) * C2 + lane;
#pragma unroll
        for (int g = 0; g < 8; g++) {
            __nv_bfloat16 h_, l_;
            split2(acc[g] * mv, h_, l_);
            zhi[obase + g * 32] = h_;
            zlo[obase + g * 32] = l_;
        }
    }
}

// ---------------------------------------------------------------------------
extern "C" void kernel_launch(void* const* d_in, const int* in_sizes, int n_in,
                              void* d_out, int out_size)
{
    const float* query = (const float*)d_in[0];
    const int* mask = (const int*)d_in[3];
    const float* w1 = (const float*)d_in[4];
    const float* b1 = (const float*)d_in[5];
    const float* w2 = (const float*)d_in[6];
    const float* b2 = (const float*)d_in[7];
    const float* ww = (const float*)d_in[8];
    const float* bw = (const float*)d_in[9];
    const float* wf = (const float*)d_in[10];
    const float* bf = (const float*)d_in[11];
    float* out = (float*)d_out;

    void* p;
    cudaGetSymbolAddress(&p, g_x);      float* dx = (float*)p;
    cudaGetSymbolAddress(&p, g_xhi);    __nv_bfloat16* dxhi = (__nv_bfloat16*)p;
    cudaGetSymbolAddress(&p, g_xlo);    __nv_bfloat16* dxlo = (__nv_bfloat16*)p;
    cudaGetSymbolAddress(&p, g_zhi);    __nv_bfloat16* dzhi = (__nv_bfloat16*)p;
    cudaGetSymbolAddress(&p, g_zlo);    __nv_bfloat16* dzlo = (__nv_bfloat16*)p;
    cudaGetSymbolAddress(&p, g_raw);    float* draw = (float*)p;
    cudaGetSymbolAddress(&p, g_attn);   float* dattn = (float*)p;
    cudaGetSymbolAddress(&p, g_w1t_hi); __nv_bfloat16* w1h = (__nv_bfloat16*)p;
    cudaGetSymbolAddress(&p, g_w1t_lo); __nv_bfloat16* w1l = (__nv_bfloat16*)p;
    cudaGetSymbolAddress(&p, g_w2t_hi); __nv_bfloat16* w2h = (__nv_bfloat16*)p;
    cudaGetSymbolAddress(&p, g_w2t_lo); __nv_bfloat16* w2l = (__nv_bfloat16*)p;
    cudaGetSymbolAddress(&p, g_wst_hi); __nv_bfloat16* wsh = (__nv_bfloat16*)p;
    cudaGetSymbolAddress(&p, g_wst_lo); __nv_bfloat16* wsl = (__nv_bfloat16*)p;
    cudaGetSymbolAddress(&p, g_bsmall); float* dbs = (float*)p;

    static bool attr_done = false;
    if (!attr_done) {
        cudaFuncSetAttribute(gemm1_glu,
                             cudaFuncAttributeMaxDynamicSharedMemorySize, G1_SMEM_BYTES);
        cudaFuncSetAttribute(gemm_split_mma,
                             cudaFuncAttributeMaxDynamicSharedMemorySize, GSMEM_BYTES);
        cudaFuncSetAttribute(timeconv,
                             cudaFuncAttributeMaxDynamicSharedMemorySize, TC_SMEM);
        attr_done = true;
    }

    // prep: all weight splits in one launch
    prep_all<<<(S_W1 + S_W2 + S_WS + NSP + 255) / 256, 256>>>(
        w1, w2, wf, ww, bf, bw, w1h, w1l, w2h, w2l, wsh, wsl, dbs);

    // 1) x = GLU(query @ w1 + b1), fused (grid 4 x 128, 2 CTAs/SM)
    gemm1_glu<<<dim3(4, BT / BMT), 256, G1_SMEM_BYTES>>>(
        query, w1h, w1l, b1, dx, dxhi, dxlo);
    // 2) raw = x @ [wf|ww] + [bf|bw]
    gemm_split_mma<<<dim3(NSMPAD / BNT, BT / BMT), 256, GSMEM_BYTES>>>(
        dxhi, dxlo, wsh, wsl, dbs, draw, CC, NSP, NSP);
    // 3) channel conv xf + banded softmax
    post_small<<<BT / 8, 256>>>(draw, dx, mask, dattn, dzhi, dzlo);
    // 4) banded attention apply
    timeconv<<<BB * (TT / TCT), 256, TC_SMEM>>>(dx, dattn, mask, dzhi, dzlo);
    // 5) out = z @ w2 + b2
    gemm_split_mma<<<dim3(CC / BNT, BT / BMT), 256, GSMEM_BYTES>>>(
        dzhi, dzlo, w2h, w2l, b2, out, C2, CC, CC);
}

// round 16
// speedup vs baseline: 1.7898x; 1.1542x over previous
#include <cuda_runtime.h>
#include <cuda_bf16.h>
#include <math.h>
#include <stdint.h>

// Problem constants
#define BB 16
#define TT 1024
#define CC 256
#define HH 4
#define KK 31
#define PADK 15
#define BT (BB * TT)          // 16384 tokens
#define C2 (2 * CC)           // 512
#define NSMALL (KK + HH * KK) // 155
#define NSP 160               // padded row stride for raw
#define NWW (HH * KK)         // 124
#define NSMPAD 256            // padded N rows for small weight

// -------------------- device scratch ---------------------------------------
__device__ float g_x[(size_t)BT * CC];
__device__ __nv_bfloat16 g_xhi[(size_t)BT * CC];
__device__ __nv_bfloat16 g_xlo[(size_t)BT * CC];
__device__ __nv_bfloat16 g_zhi[(size_t)BT * C2];
__device__ __nv_bfloat16 g_zlo[(size_t)BT * C2];
__device__ float g_raw[(size_t)BT * NSP];
__device__ __nv_bfloat16 g_w1t_hi[(size_t)C2 * CC];
__device__ __nv_bfloat16 g_w1t_lo[(size_t)C2 * CC];
__device__ __nv_bfloat16 g_w2t_hi[(size_t)CC * C2];
__device__ __nv_bfloat16 g_w2t_lo[(size_t)CC * C2];
__device__ __nv_bfloat16 g_wst_hi[(size_t)NSMPAD * CC];
__device__ __nv_bfloat16 g_wst_lo[(size_t)NSMPAD * CC];
__device__ float g_bsmall[NSP];

static __device__ __forceinline__ void split2(float v, __nv_bfloat16& h, __nv_bfloat16& l) {
    h = __float2bfloat16(v);
    l = __float2bfloat16(v - __bfloat162float(h));
}

__device__ __forceinline__ void mma16816(float* c, uint32_t a0, uint32_t a1,
                                         uint32_t a2, uint32_t a3,
                                         uint32_t b0, uint32_t b1) {
    asm volatile(
        "mma.sync.aligned.m16n8k16.row.col.f32.bf16.bf16.f32 "
        "{%0,%1,%2,%3}, {%4,%5,%6,%7}, {%8,%9}, {%0,%1,%2,%3};"
        : "+f"(c[0]), "+f"(c[1]), "+f"(c[2]), "+f"(c[3])
        : "r"(a0), "r"(a1), "r"(a2), "r"(a3), "r"(b0), "r"(b1));
}

__device__ __forceinline__ void ldsm_x4(uint32_t* r, uint32_t saddr) {
    asm volatile("ldmatrix.sync.aligned.m8n8.x4.shared.b16 {%0,%1,%2,%3}, [%4];"
                 : "=r"(r[0]), "=r"(r[1]), "=r"(r[2]), "=r"(r[3]) : "r"(saddr));
}
__device__ __forceinline__ void ldsm_x2(uint32_t* r, uint32_t saddr) {
    asm volatile("ldmatrix.sync.aligned.m8n8.x2.shared.b16 {%0,%1}, [%2];"
                 : "=r"(r[0]), "=r"(r[1]) : "r"(saddr));
}

__device__ __forceinline__ uint32_t smem_u32(const void* p) {
    uint32_t a;
    asm("{ .reg .u64 t; cvta.to.shared.u64 t, %1; cvt.u32.u64 %0, t; }"
        : "=r"(a) : "l"(p));
    return a;
}
__device__ __forceinline__ void cpa16(uint32_t saddr, const void* g) {
    asm volatile("cp.async.cg.shared.global [%0], [%1], 16;" :: "r"(saddr), "l"(g));
}
#define CP_COMMIT() asm volatile("cp.async.commit_group;" ::: "memory")
#define CP_WAIT0()  asm volatile("cp.async.wait_group 0;" ::: "memory")

#define BMT 128
#define BNT 128
#define APAD 40   // bf16 elems per smem row
#define TILE_ELEMS (128 * APAD)
#define TILE_BYTES_SM (TILE_ELEMS * 2)

// ldmatrix per-lane address components
#define A_LDSM_ROW(lane) (((lane) & 7) + (((lane) >> 3) & 1) * 8)
#define A_LDSM_COL(lane) ((((lane) >> 4) & 1) * 8)
#define B_LDSM_ROW(lane) ((lane) & 7)
#define B_LDSM_COL(lane) ((((lane) >> 3) & 1) * 8)

// ============ fused GEMM1 + GLU + split: 128x64 twin tile, 2 CTAs/SM ========
#define G1_STAGE (4 * TILE_ELEMS)
#define G1_SMEM_BYTES (2 * G1_STAGE * 2)   // 81920

__global__ __launch_bounds__(256, 2) void gemm1_glu(
    const float* __restrict__ Q,
    const __nv_bfloat16* __restrict__ Wh, const __nv_bfloat16* __restrict__ Wl,
    const float* __restrict__ b1,
    float* __restrict__ X, __nv_bfloat16* __restrict__ Xhi,
    __nv_bfloat16* __restrict__ Xlo)
{
    extern __shared__ __align__(16) __nv_bfloat16 sm[];
    const int tid = threadIdx.x;
    const int wid = tid >> 5;
    const int lane = tid & 31;
    const int m0 = blockIdx.y * BMT;
    const int na0 = blockIdx.x * 64;       // a-col base; g at na0+256
    const int wm = (wid & 1) * 64;
    const int wn = (wid >> 1) * 16;        // 4 N-warps x 16
    const int r8 = lane >> 2;
    const int cp = (lane & 3) * 2;
    const uint32_t smbase = smem_u32(sm);

    const int alr = A_LDSM_ROW(lane), alc = A_LDSM_COL(lane);
    const int blr = B_LDSM_ROW(lane), blc = B_LDSM_COL(lane);

    const __nv_bfloat16* bsrc[4] = { Wh, Wl, Wh, Wl };
    const int brow[4] = { na0, na0, na0 + 256, na0 + 256 };
    int btt[4], brr[4]; uint32_t bdst[4];
#pragma unroll
    for (int i = 0; i < 4; i++) {
        const int c = tid + i * 256;
        const int t = c >> 8, rem = c & 255;
        const int row = rem >> 2, q = (rem & 3) * 8;
        btt[i] = t; brr[i] = row;
        bdst[i] = (uint32_t)(((2 + (t >> 1)) * 128 + (t & 1) * 64 + row) * APAD + q) * 2;
    }
    const int c0 = tid, c1 = tid + 256;
    const int r0c = c0 >> 2, q0c = (c0 & 3) * 8;
    const int r1c = c1 >> 2, q1c = (c1 & 3) * 8;

    float acc_a[4][2][4], acc_g[4][2][4];
#pragma unroll
    for (int i = 0; i < 4; i++)
#pragma unroll
        for (int j = 0; j < 2; j++)
#pragma unroll
            for (int q = 0; q < 4; q++) { acc_a[i][j][q] = 0.f; acc_g[i][j][q] = 0.f; }

    const int NK = CC / 32;  // 8
    float apre[2][8];

#pragma unroll
    for (int i = 0; i < 4; i++) {
        const int t = btt[i], row = brr[i];
        const int q = ((tid + i * 256) & 3) * 8;
        cpa16(smbase + bdst[i],
              bsrc[t] + (size_t)(brow[t] + row) * CC + q);
    }
    CP_COMMIT();
    {
        *reinterpret_cast<float4*>(&apre[0][0]) = *reinterpret_cast<const float4*>(&Q[(size_t)(m0 + r0c) * CC + q0c]);
        *reinterpret_cast<float4*>(&apre[0][4]) = *reinterpret_cast<const float4*>(&Q[(size_t)(m0 + r0c) * CC + q0c + 4]);
        *reinterpret_cast<float4*>(&apre[1][0]) = *reinterpret_cast<const float4*>(&Q[(size_t)(m0 + r1c) * CC + q1c]);
        *reinterpret_cast<float4*>(&apre[1][4]) = *reinterpret_cast<const float4*>(&Q[(size_t)(m0 + r1c) * CC + q1c + 4]);
        __nv_bfloat16 h8[8], l8[8];
#pragma unroll
        for (int e = 0; e < 8; e++) split2(apre[0][e], h8[e], l8[e]);
        *reinterpret_cast<uint4*>(&sm[(0 * 128 + r0c) * APAD + q0c]) = *reinterpret_cast<uint4*>(h8);
        *reinterpret_cast<uint4*>(&sm[(1 * 128 + r0c) * APAD + q0c]) = *reinterpret_cast<uint4*>(l8);
#pragma unroll
        for (int e = 0; e < 8; e++) split2(apre[1][e], h8[e], l8[e]);
        *reinterpret_cast<uint4*>(&sm[(0 * 128 + r1c) * APAD + q1c]) = *reinterpret_cast<uint4*>(h8);
        *reinterpret_cast<uint4*>(&sm[(1 * 128 + r1c) * APAD + q1c]) = *reinterpret_cast<uint4*>(l8);
    }
    CP_WAIT0();
    __syncthreads();

    for (int kc = 0; kc < NK; kc++) {
        const int nxt = kc + 1;
        if (nxt < NK) {
            const int sb = (nxt & 1) * G1_STAGE;
            const int k0 = nxt << 5;
#pragma unroll
            for (int i = 0; i < 4; i++) {
                const int t = btt[i], row = brr[i];
                const int q = ((tid + i * 256) & 3) * 8;
                cpa16(smbase + (uint32_t)(sb * 2) + bdst[i],
                      bsrc[t] + (size_t)(brow[t] + row) * CC + k0 + q);
            }
            CP_COMMIT();
            *reinterpret_cast<float4*>(&apre[0][0]) = *reinterpret_cast<const float4*>(&Q[(size_t)(m0 + r0c) * CC + k0 + q0c]);
            *reinterpret_cast<float4*>(&apre[0][4]) = *reinterpret_cast<const float4*>(&Q[(size_t)(m0 + r0c) * CC + k0 + q0c + 4]);
            *reinterpret_cast<float4*>(&apre[1][0]) = *reinterpret_cast<const float4*>(&Q[(size_t)(m0 + r1c) * CC + k0 + q1c]);
            *reinterpret_cast<float4*>(&apre[1][4]) = *reinterpret_cast<const float4*>(&Q[(size_t)(m0 + r1c) * CC + k0 + q1c + 4]);
        }

        const uint32_t stg = smbase + (uint32_t)((kc & 1) * G1_STAGE) * 2;
#pragma unroll
        for (int ks = 0; ks < 2; ks++) {
            const int kb = ks * 16;
            uint32_t afh[4][4], afl[4][4];
#pragma unroll
            for (int im = 0; im < 4; im++) {
                const uint32_t aaddr = stg +
                    (uint32_t)(((wm + im * 16 + alr) * APAD + kb + alc) * 2);
                ldsm_x4(afh[im], aaddr);
            }
            uint32_t bh[2][2], bl[2][2], gh[2][2], gl[2][2];
#pragma unroll
            for (int jn = 0; jn < 2; jn++) {
                const uint32_t ba = stg + 2 * TILE_BYTES_SM +
                    (uint32_t)(((wn + jn * 8 + blr) * APAD + kb + blc) * 2);
                ldsm_x2(bh[jn], ba);
                ldsm_x2(bl[jn], ba + (uint32_t)(64 * APAD * 2));
                const uint32_t bg = stg + 3 * TILE_BYTES_SM +
                    (uint32_t)(((wn + jn * 8 + blr) * APAD + kb + blc) * 2);
                ldsm_x2(gh[jn], bg);
                ldsm_x2(gl[jn], bg + (uint32_t)(64 * APAD * 2));
            }
#pragma unroll
            for (int im = 0; im < 4; im++)
#pragma unroll
                for (int jn = 0; jn < 2; jn++) {
                    mma16816(acc_a[im][jn], afh[im][0], afh[im][1], afh[im][2], afh[im][3], bh[jn][0], bh[jn][1]);
                    mma16816(acc_a[im][jn], afh[im][0], afh[im][1], afh[im][2], afh[im][3], bl[jn][0], bl[jn][1]);
                    mma16816(acc_g[im][jn], afh[im][0], afh[im][1], afh[im][2], afh[im][3], gh[jn][0], gh[jn][1]);
                    mma16816(acc_g[im][jn], afh[im][0], afh[im][1], afh[im][2], afh[im][3], gl[jn][0], gl[jn][1]);
                }
#pragma unroll
            for (int im = 0; im < 4; im++) {
                const uint32_t aaddr = stg + TILE_BYTES_SM +
                    (uint32_t)(((wm + im * 16 + alr) * APAD + kb + alc) * 2);
                ldsm_x4(afl[im], aaddr);
            }
#pragma unroll
            for (int im = 0; im < 4; im++)
#pragma unroll
                for (int jn = 0; jn < 2; jn++) {
                    mma16816(acc_a[im][jn], afl[im][0], afl[im][1], afl[im][2], afl[im][3], bh[jn][0], bh[jn][1]);
                    mma16816(acc_g[im][jn], afl[im][0], afl[im][1], afl[im][2], afl[im][3], gh[jn][0], gh[jn][1]);
                }
        }

        if (nxt < NK) {
            const int sb = (nxt & 1) * G1_STAGE;
            __nv_bfloat16 h8[8], l8[8];
#pragma unroll
            for (int e = 0; e < 8; e++) split2(apre[0][e], h8[e], l8[e]);
            *reinterpret_cast<uint4*>(&sm[sb + (0 * 128 + r0c) * APAD + q0c]) = *reinterpret_cast<uint4*>(h8);
            *reinterpret_cast<uint4*>(&sm[sb + (1 * 128 + r0c) * APAD + q0c]) = *reinterpret_cast<uint4*>(l8);
#pragma unroll
            for (int e = 0; e < 8; e++) split2(apre[1][e], h8[e], l8[e]);
            *reinterpret_cast<uint4*>(&sm[sb + (0 * 128 + r1c) * APAD + q1c]) = *reinterpret_cast<uint4*>(h8);
            *reinterpret_cast<uint4*>(&sm[sb + (1 * 128 + r1c) * APAD + q1c]) = *reinterpret_cast<uint4*>(l8);
            CP_WAIT0();
            __syncthreads();
        }
    }

#pragma unroll
    for (int im = 0; im < 4; im++) {
#pragma unroll
        for (int jn = 0; jn < 2; jn++) {
            const int col = na0 + wn + jn * 8 + cp;
            const float ba0 = b1[col], ba1 = b1[col + 1];
            const float bg0 = b1[col + 256], bg1 = b1[col + 257];
            const int row0 = m0 + wm + im * 16 + r8;
#pragma unroll
            for (int half = 0; half < 2; half++) {
                const int row = row0 + half * 8;
                float a0 = acc_a[im][jn][half * 2 + 0] + ba0;
                float a1 = acc_a[im][jn][half * 2 + 1] + ba1;
                float gg0 = acc_g[im][jn][half * 2 + 0] + bg0;
                float gg1 = acc_g[im][jn][half * 2 + 1] + bg1;
                float x0 = a0 * (1.f / (1.f + expf(-gg0)));
                float x1 = a1 * (1.f / (1.f + expf(-gg1)));
                size_t o = (size_t)row * CC + col;
                *reinterpret_cast<float2*>(&X[o]) = make_float2(x0, x1);
                __nv_bfloat16 h0, l0, h1, l1;
                split2(x0, h0, l0); split2(x1, h1, l1);
                __nv_bfloat162 ph; ph.x = h0; ph.y = h1;
                __nv_bfloat162 pl; pl.x = l0; pl.y = l1;
                *reinterpret_cast<__nv_bfloat162*>(&Xhi[o]) = ph;
                *reinterpret_cast<__nv_bfloat162*>(&Xlo[o]) = pl;
            }
        }
    }
}

// ---------------- generic fused split-bf16 GEMM (2 CTAs/SM, ldmatrix) -------
#define STAGE_ELEMS (4 * TILE_ELEMS)
#define GSMEM_BYTES (2 * STAGE_ELEMS * 2)   // 81920

__global__ __launch_bounds__(256, 2) void gemm_split_mma(
    const __nv_bfloat16* __restrict__ Ahi, const __nv_bfloat16* __restrict__ Alo,
    const __nv_bfloat16* __restrict__ Bhi, const __nv_bfloat16* __restrict__ Blo,
    const float* __restrict__ bias, float* __restrict__ Cm,
    int Kt, int ldc, int Nout)
{
    extern __shared__ __align__(16) __nv_bfloat16 sm[];
    const int tid = threadIdx.x;
    const int wid = tid >> 5;
    const int lane = tid & 31;
    const int m0 = blockIdx.y * BMT;
    const int n0 = blockIdx.x * BNT;
    const int wm = (wid & 1) * 64;
    const int wn = (wid >> 1) * 32;
    const int r8 = lane >> 2;
    const int cp = (lane & 3) * 2;

    const int alr = A_LDSM_ROW(lane), alc = A_LDSM_COL(lane);
    const int blr = B_LDSM_ROW(lane), blc = B_LDSM_COL(lane);

    const __nv_bfloat16* srcs[4] = { Ahi, Alo, Bhi, Blo };
    const int bases[4] = { m0, m0, n0, n0 };

    const int c0 = tid, c1 = tid + 256;
    const int lr0 = c0 >> 2, lc0 = (c0 & 3) * 8;
    const int lr1 = c1 >> 2, lc1 = (c1 & 3) * 8;
    const uint32_t smbase = smem_u32(sm);

    float acc[4][4][4];
#pragma unroll
    for (int i = 0; i < 4; i++)
#pragma unroll
        for (int j = 0; j < 4; j++)
#pragma unroll
            for (int q = 0; q < 4; q++) acc[i][j][q] = 0.f;

    const int NK = Kt >> 5;

#pragma unroll
    for (int t = 0; t < 4; t++) {
        const __nv_bfloat16* sp = srcs[t];
        cpa16(smbase + (uint32_t)((t * 128 + lr0) * APAD + lc0) * 2,
              sp + (size_t)(bases[t] + lr0) * Kt + lc0);
        cpa16(smbase + (uint32_t)((t * 128 + lr1) * APAD + lc1) * 2,
              sp + (size_t)(bases[t] + lr1) * Kt + lc1);
    }
    CP_COMMIT();
    CP_WAIT0();
    __syncthreads();

    for (int kc = 0; kc < NK; kc++) {
        if (kc + 1 < NK) {
            const int sb = ((kc + 1) & 1) * STAGE_ELEMS;
            const int k0 = (kc + 1) << 5;
#pragma unroll
            for (int t = 0; t < 4; t++) {
                const __nv_bfloat16* sp = srcs[t];
                cpa16(smbase + (uint32_t)(sb + (t * 128 + lr0) * APAD + lc0) * 2,
                      sp + (size_t)(bases[t] + lr0) * Kt + k0 + lc0);
                cpa16(smbase + (uint32_t)(sb + (t * 128 + lr1) * APAD + lc1) * 2,
                      sp + (size_t)(bases[t] + lr1) * Kt + k0 + lc1);
            }
            CP_COMMIT();
        }
        const uint32_t stg = smbase + (uint32_t)((kc & 1) * STAGE_ELEMS) * 2;
#pragma unroll
        for (int ks = 0; ks < 2; ks++) {
            const int kb = ks * 16;
            uint32_t afh[4][4], afl[4][4];
#pragma unroll
            for (int im = 0; im < 4; im++) {
                const uint32_t aaddr = stg +
                    (uint32_t)(((wm + im * 16 + alr) * APAD + kb + alc) * 2);
                ldsm_x4(afh[im], aaddr);
            }
            uint32_t bfh[4][2], bfl[4][2];
#pragma unroll
            for (int jn = 0; jn < 4; jn++) {
                const uint32_t baddr = stg + 2 * TILE_BYTES_SM +
                    (uint32_t)(((wn + jn * 8 + blr) * APAD + kb + blc) * 2);
                ldsm_x2(bfh[jn], baddr);
                ldsm_x2(bfl[jn], baddr + TILE_BYTES_SM);
            }
#pragma unroll
            for (int im = 0; im < 4; im++)
#pragma unroll
                for (int jn = 0; jn < 4; jn++) {
                    mma16816(acc[im][jn], afh[im][0], afh[im][1], afh[im][2], afh[im][3], bfh[jn][0], bfh[jn][1]);
                    mma16816(acc[im][jn], afh[im][0], afh[im][1], afh[im][2], afh[im][3], bfl[jn][0], bfl[jn][1]);
                }
#pragma unroll
            for (int im = 0; im < 4; im++) {
                const uint32_t aaddr = stg + TILE_BYTES_SM +
                    (uint32_t)(((wm + im * 16 + alr) * APAD + kb + alc) * 2);
                ldsm_x4(afl[im], aaddr);
            }
#pragma unroll
            for (int im = 0; im < 4; im++)
#pragma unroll
                for (int jn = 0; jn < 4; jn++)
                    mma16816(acc[im][jn], afl[im][0], afl[im][1], afl[im][2], afl[im][3], bfh[jn][0], bfh[jn][1]);
        }
        if (kc + 1 < NK) {
            CP_WAIT0();
            __syncthreads();
        }
    }

#pragma unroll
    for (int im = 0; im < 4; im++) {
#pragma unroll
        for (int jn = 0; jn < 4; jn++) {
            const int col = n0 + wn + jn * 8 + cp;
            if (col < Nout) {
                const float bx = bias[col], by = bias[col + 1];
                const int row0 = m0 + wm + im * 16 + r8;
                float2 v0 = { acc[im][jn][0] + bx, acc[im][jn][1] + by };
                float2 v1 = { acc[im][jn][2] + bx, acc[im][jn][3] + by };
                *reinterpret_cast<float2*>(&Cm[(size_t)row0 * ldc + col]) = v0;
                *reinterpret_cast<float2*>(&Cm[(size_t)(row0 + 8) * ldc + col]) = v1;
            }
        }
    }
}

// -------------------- merged prep kernel ------------------------------------
#define S_W1 (C2 * CC)
#define S_W2 (CC * C2)
#define S_WS (NSMPAD * CC)
__global__ __launch_bounds__(256) void prep_all(
    const float* __restrict__ w1, const float* __restrict__ w2,
    const float* __restrict__ wf, const float* __restrict__ ww,
    const float* __restrict__ bf, const float* __restrict__ bw,
    __nv_bfloat16* __restrict__ w1h, __nv_bfloat16* __restrict__ w1l,
    __nv_bfloat16* __restrict__ w2h, __nv_bfloat16* __restrict__ w2l,
    __nv_bfloat16* __restrict__ wsh, __nv_bfloat16* __restrict__ wsl,
    float* __restrict__ bc)
{
    int i = blockIdx.x * 256 + threadIdx.x;
    if (i < S_W1) {
        int n = i / CC, k = i % CC;
        split2(w1[(size_t)k * C2 + n], w1h[i], w1l[i]);
    } else if (i < S_W1 + S_W2) {
        int j = i - S_W1;
        int n = j / C2, k = j % C2;
        split2(w2[(size_t)k * CC + n], w2h[j], w2l[j]);
    } else if (i < S_W1 + S_W2 + S_WS) {
        int j = i - S_W1 - S_W2;
        int n = j / CC, k = j % CC;
        float v = 0.f;
        if (n < KK) v = wf[k * KK + n];
        else if (n < NSMALL) v = ww[k * NWW + (n - KK)];
        split2(v, wsh[j], wsl[j]);
    } else if (i < S_W1 + S_W2 + S_WS + NSP) {
        int j = i - S_W1 - S_W2 - S_WS;
        float v = 0.f;
        if (j < KK) v = bf[j];
        else if (j < NSMALL) v = bw[j - KK];
        bc[j] = v;
    }
}

// ========== merged band kernel: conv + softmax + attention apply ============
// Two sequential phases; only pv[4][HH] (softmax probs, lane-register layout)
// crosses phase boundary. 32-token tile, 8 warps x 4 tokens.
#define FT 32
#define FR (FT + 2 * PADK)   // 62
#define B2_SMEM (FR * CC * (int)sizeof(float))   // 63488

__global__ __launch_bounds__(256) void band2(
    const float* __restrict__ raw, const float* __restrict__ x,
    const int* __restrict__ mask,
    __nv_bfloat16* __restrict__ zhi, __nv_bfloat16* __restrict__ zlo)
{
    extern __shared__ float xs[];   // FR * CC
    __shared__ float msk[FT];

    const int b = blockIdx.x >> 5;           // 32 tiles per batch
    const int tb = (blockIdx.x & 31) * FT;
    const int tid = threadIdx.x;
    const int warp = tid >> 5;
    const int lane = tid & 31;

    for (int idx = tid; idx < FR * 64; idx += 256) {
        const int r = idx >> 6;
        const int c4 = (idx & 63) * 4;
        const int s = tb - PADK + r;
        float4 v = make_float4(0.f, 0.f, 0.f, 0.f);
        if (s >= 0 && s < TT)
            v = *reinterpret_cast<const float4*>(&x[((size_t)b * TT + s) * CC + c4]);
        *reinterpret_cast<float4*>(&xs[r * CC + c4]) = v;
    }
    if (tid < FT) msk[tid] = (mask[b * TT + tb + tid] != 0) ? 1.f : 0.f;
    __syncthreads();

    float pv[4][HH];

    // ---- phase 1: per-token softmax (to registers) + channel conv ---------
#pragma unroll 1
    for (int it = 0; it < 4; it++) {
        const int tt = warp * 4 + it;
        const size_t t = (size_t)b * TT + tb + tt;
        const float mk = msk[tt];

        const int soff = tb + tt + lane - PADK;
        const bool valid = (lane < KK) && (soff >= 0) && (soff < TT);
#pragma unroll
        for (int h = 0; h < HH; h++) {
            float v = valid ? raw[t * NSP + KK + h * KK + lane] : -INFINITY;
            float mx = v;
#pragma unroll
            for (int o = 16; o; o >>= 1) mx = fmaxf(mx, __shfl_xor_sync(0xffffffffu, mx, o));
            float e = valid ? expf(v - mx) : 0.f;
            float sm_ = e;
#pragma unroll
            for (int o = 16; o; o >>= 1) sm_ += __shfl_xor_sync(0xffffffffu, sm_, o);
            pv[it][h] = e / sm_;
        }

        const float wv = (lane < KK) ? raw[t * NSP + lane] : 0.f;
        const float* xrow = &xs[(tt + PADK) * CC];
        float buf[44];
        const int base = lane * 8 - 16;
#pragma unroll
        for (int i = 0; i < 11; i++) {
            const int c = base + i * 4;
            float4 v = make_float4(0.f, 0.f, 0.f, 0.f);
            if (c >= 0 && c < CC)
                v = *reinterpret_cast<const float4*>(&xrow[c]);
            *reinterpret_cast<float4*>(&buf[i * 4]) = v;
        }
        float fa[8];
#pragma unroll
        for (int d = 0; d < 8; d++) fa[d] = 0.f;
#pragma unroll
        for (int j = 0; j < KK; j++) {
            const float wj = __shfl_sync(0xffffffffu, wv, j);
#pragma unroll
            for (int d = 0; d < 8; d++) fa[d] = fmaf(wj, buf[d + j + 1], fa[d]);
        }
        __nv_bfloat16 h8[8], l8[8];
#pragma unroll
        for (int d = 0; d < 8; d++) split2(fa[d] * mk, h8[d], l8[d]);
        const size_t o = t * C2 + CC + lane * 8;
        *reinterpret_cast<uint4*>(&zhi[o]) = *reinterpret_cast<uint4*>(h8);
        *reinterpret_cast<uint4*>(&zlo[o]) = *reinterpret_cast<uint4*>(l8);
    }

    // ---- phase 2: attention apply (pv via shuffles; xs already synced) ----
#pragma unroll 1
    for (int it = 0; it < 4; it++) {
        const int tt = warp * 4 + it;
        const size_t t = (size_t)b * TT + tb + tt;
        float ya[8];
#pragma unroll
        for (int g = 0; g < 8; g++) ya[g] = 0.f;
#pragma unroll
        for (int j = 0; j < KK; j++) {
            const float w0 = __shfl_sync(0xffffffffu, pv[it][0], j);
            const float w1 = __shfl_sync(0xffffffffu, pv[it][1], j);
            const float w2 = __shfl_sync(0xffffffffu, pv[it][2], j);
            const float w3 = __shfl_sync(0xffffffffu, pv[it][3], j);
            const float* xr = &xs[(tt + j) * CC + lane];
            ya[0] = fmaf(w0, xr[0 * 32], ya[0]);
            ya[1] = fmaf(w0, xr[1 * 32], ya[1]);
            ya[2] = fmaf(w1, xr[2 * 32], ya[2]);
            ya[3] = fmaf(w1, xr[3 * 32], ya[3]);
            ya[4] = fmaf(w2, xr[4 * 32], ya[4]);
            ya[5] = fmaf(w2, xr[5 * 32], ya[5]);
            ya[6] = fmaf(w3, xr[6 * 32], ya[6]);
            ya[7] = fmaf(w3, xr[7 * 32], ya[7]);
        }
        const float mv = msk[tt];
        const size_t obase = t * C2 + lane;
#pragma unroll
        for (int g = 0; g < 8; g++) {
            __nv_bfloat16 h_, l_;
            split2(ya[g] * mv, h_, l_);
            zhi[obase + g * 32] = h_;
            zlo[obase + g * 32] = l_;
        }
    }
}

// ---------------------------------------------------------------------------
extern "C" void kernel_launch(void* const* d_in, const int* in_sizes, int n_in,
                              void* d_out, int out_size)
{
    const float* query = (const float*)d_in[0];
    const int* mask = (const int*)d_in[3];
    const float* w1 = (const float*)d_in[4];
    const float* b1 = (const float*)d_in[5];
    const float* w2 = (const float*)d_in[6];
    const float* b2 = (const float*)d_in[7];
    const float* ww = (const float*)d_in[8];
    const float* bw = (const float*)d_in[9];
    const float* wf = (const float*)d_in[10];
    const float* bf = (const float*)d_in[11];
    float* out = (float*)d_out;

    void* p;
    cudaGetSymbolAddress(&p, g_x);      float* dx = (float*)p;
    cudaGetSymbolAddress(&p, g_xhi);    __nv_bfloat16* dxhi = (__nv_bfloat16*)p;
    cudaGetSymbolAddress(&p, g_xlo);    __nv_bfloat16* dxlo = (__nv_bfloat16*)p;
    cudaGetSymbolAddress(&p, g_zhi);    __nv_bfloat16* dzhi = (__nv_bfloat16*)p;
    cudaGetSymbolAddress(&p, g_zlo);    __nv_bfloat16* dzlo = (__nv_bfloat16*)p;
    cudaGetSymbolAddress(&p, g_raw);    float* draw = (float*)p;
    cudaGetSymbolAddress(&p, g_w1t_hi); __nv_bfloat16* w1h = (__nv_bfloat16*)p;
    cudaGetSymbolAddress(&p, g_w1t_lo); __nv_bfloat16* w1l = (__nv_bfloat16*)p;
    cudaGetSymbolAddress(&p, g_w2t_hi); __nv_bfloat16* w2h = (__nv_bfloat16*)p;
    cudaGetSymbolAddress(&p, g_w2t_lo); __nv_bfloat16* w2l = (__nv_bfloat16*)p;
    cudaGetSymbolAddress(&p, g_wst_hi); __nv_bfloat16* wsh = (__nv_bfloat16*)p;
    cudaGetSymbolAddress(&p, g_wst_lo); __nv_bfloat16* wsl = (__nv_bfloat16*)p;
    cudaGetSymbolAddress(&p, g_bsmall); float* dbs = (float*)p;

    static bool attr_done = false;
    if (!attr_done) {
        cudaFuncSetAttribute(gemm1_glu,
                             cudaFuncAttributeMaxDynamicSharedMemorySize, G1_SMEM_BYTES);
        cudaFuncSetAttribute(gemm_split_mma,
                             cudaFuncAttributeMaxDynamicSharedMemorySize, GSMEM_BYTES);
        cudaFuncSetAttribute(band2,
                             cudaFuncAttributeMaxDynamicSharedMemorySize, B2_SMEM);
        attr_done = true;
    }

    // prep: all weight splits in one launch
    prep_all<<<(S_W1 + S_W2 + S_WS + NSP + 255) / 256, 256>>>(
        w1, w2, wf, ww, bf, bw, w1h, w1l, w2h, w2l, wsh, wsl, dbs);

    // 1) x = GLU(query @ w1 + b1), fused (grid 4 x 128, 2 CTAs/SM)
    gemm1_glu<<<dim3(4, BT / BMT), 256, G1_SMEM_BYTES>>>(
        query, w1h, w1l, b1, dx, dxhi, dxlo);
    // 2) raw = x @ [wf|ww] + [bf|bw]
    gemm_split_mma<<<dim3(NSMPAD / BNT, BT / BMT), 256, GSMEM_BYTES>>>(
        dxhi, dxlo, wsh, wsl, dbs, draw, CC, NSP, NSP);
    // 3) merged band kernel: conv + softmax + attention apply -> z
    band2<<<BB * (TT / FT), 256, B2_SMEM>>>(draw, dx, mask, dzhi, dzlo);
    // 4) out = z @ w2 + b2
    gemm_split_mma<<<dim3(CC / BNT, BT / BMT), 256, GSMEM_BYTES>>>(
        dzhi, dzlo, w2h, w2l, b2, out, C2, CC, CC);
}

// round 17
// speedup vs baseline: 1.9085x; 1.0663x over previous
#include <cuda_runtime.h>
#include <cuda_bf16.h>
#include <math.h>
#include <stdint.h>

// Problem constants
#define BB 16
#define TT 1024
#define CC 256
#define HH 4
#define KK 31
#define PADK 15
#define BT (BB * TT)          // 16384 tokens
#define C2 (2 * CC)           // 512
#define NSMALL (KK + HH * KK) // 155
#define NSP 160               // padded row stride for raw
#define NWW (HH * KK)         // 124
#define NSMPAD 256            // padded N rows for small weight

// -------------------- device scratch ---------------------------------------
__device__ __nv_bfloat16 g_xhi[(size_t)BT * CC];
__device__ __nv_bfloat16 g_xlo[(size_t)BT * CC];
__device__ __nv_bfloat16 g_zhi[(size_t)BT * C2];
__device__ __nv_bfloat16 g_zlo[(size_t)BT * C2];
__device__ float g_raw[(size_t)BT * NSP];
__device__ __nv_bfloat16 g_w1t_hi[(size_t)C2 * CC];
__device__ __nv_bfloat16 g_w1t_lo[(size_t)C2 * CC];
__device__ __nv_bfloat16 g_w2t_hi[(size_t)CC * C2];
__device__ __nv_bfloat16 g_w2t_lo[(size_t)CC * C2];
__device__ __nv_bfloat16 g_wst_hi[(size_t)NSMPAD * CC];
__device__ __nv_bfloat16 g_wst_lo[(size_t)NSMPAD * CC];
__device__ float g_bsmall[NSP];

static __device__ __forceinline__ void split2(float v, __nv_bfloat16& h, __nv_bfloat16& l) {
    h = __float2bfloat16(v);
    l = __float2bfloat16(v - __bfloat162float(h));
}

__device__ __forceinline__ void mma16816(float* c, uint32_t a0, uint32_t a1,
                                         uint32_t a2, uint32_t a3,
                                         uint32_t b0, uint32_t b1) {
    asm volatile(
        "mma.sync.aligned.m16n8k16.row.col.f32.bf16.bf16.f32 "
        "{%0,%1,%2,%3}, {%4,%5,%6,%7}, {%8,%9}, {%0,%1,%2,%3};"
        : "+f"(c[0]), "+f"(c[1]), "+f"(c[2]), "+f"(c[3])
        : "r"(a0), "r"(a1), "r"(a2), "r"(a3), "r"(b0), "r"(b1));
}

__device__ __forceinline__ void ldsm_x4(uint32_t* r, uint32_t saddr) {
    asm volatile("ldmatrix.sync.aligned.m8n8.x4.shared.b16 {%0,%1,%2,%3}, [%4];"
                 : "=r"(r[0]), "=r"(r[1]), "=r"(r[2]), "=r"(r[3]) : "r"(saddr));
}
__device__ __forceinline__ void ldsm_x2(uint32_t* r, uint32_t saddr) {
    asm volatile("ldmatrix.sync.aligned.m8n8.x2.shared.b16 {%0,%1}, [%2];"
                 : "=r"(r[0]), "=r"(r[1]) : "r"(saddr));
}
__device__ __forceinline__ void ldsm_x2_trans(uint32_t* r, uint32_t saddr) {
    asm volatile("ldmatrix.sync.aligned.m8n8.x2.trans.shared.b16 {%0,%1}, [%2];"
                 : "=r"(r[0]), "=r"(r[1]) : "r"(saddr));
}

__device__ __forceinline__ uint32_t smem_u32(const void* p) {
    uint32_t a;
    asm("{ .reg .u64 t; cvta.to.shared.u64 t, %1; cvt.u32.u64 %0, t; }"
        : "=r"(a) : "l"(p));
    return a;
}
__device__ __forceinline__ void cpa16(uint32_t saddr, const void* g) {
    asm volatile("cp.async.cg.shared.global [%0], [%1], 16;" :: "r"(saddr), "l"(g));
}
#define CP_COMMIT() asm volatile("cp.async.commit_group;" ::: "memory")
#define CP_WAIT0()  asm volatile("cp.async.wait_group 0;" ::: "memory")

#define BMT 128
#define BNT 128
#define APAD 40   // bf16 elems per smem row
#define TILE_ELEMS (128 * APAD)
#define TILE_BYTES_SM (TILE_ELEMS * 2)

// ldmatrix per-lane address components
#define A_LDSM_ROW(lane) (((lane) & 7) + (((lane) >> 3) & 1) * 8)
#define A_LDSM_COL(lane) ((((lane) >> 4) & 1) * 8)
#define B_LDSM_ROW(lane) ((lane) & 7)
#define B_LDSM_COL(lane) ((((lane) >> 3) & 1) * 8)

// ============ fused GEMM1 + GLU + split: 128x64 twin tile, 2 CTAs/SM ========
#define G1_STAGE (4 * TILE_ELEMS)
#define G1_SMEM_BYTES (2 * G1_STAGE * 2)   // 81920

__global__ __launch_bounds__(256, 2) void gemm1_glu(
    const float* __restrict__ Q,
    const __nv_bfloat16* __restrict__ Wh, const __nv_bfloat16* __restrict__ Wl,
    const float* __restrict__ b1,
    __nv_bfloat16* __restrict__ Xhi, __nv_bfloat16* __restrict__ Xlo)
{
    extern __shared__ __align__(16) __nv_bfloat16 sm[];
    const int tid = threadIdx.x;
    const int wid = tid >> 5;
    const int lane = tid & 31;
    const int m0 = blockIdx.y * BMT;
    const int na0 = blockIdx.x * 64;       // a-col base; g at na0+256
    const int wm = (wid & 1) * 64;
    const int wn = (wid >> 1) * 16;        // 4 N-warps x 16
    const int r8 = lane >> 2;
    const int cp = (lane & 3) * 2;
    const uint32_t smbase = smem_u32(sm);

    const int alr = A_LDSM_ROW(lane), alc = A_LDSM_COL(lane);
    const int blr = B_LDSM_ROW(lane), blc = B_LDSM_COL(lane);

    const __nv_bfloat16* bsrc[4] = { Wh, Wl, Wh, Wl };
    const int brow[4] = { na0, na0, na0 + 256, na0 + 256 };
    int btt[4], brr[4]; uint32_t bdst[4];
#pragma unroll
    for (int i = 0; i < 4; i++) {
        const int c = tid + i * 256;
        const int t = c >> 8, rem = c & 255;
        const int row = rem >> 2;
        const int q = (rem & 3) * 8;
        btt[i] = t; brr[i] = row;
        bdst[i] = (uint32_t)(((2 + (t >> 1)) * 128 + (t & 1) * 64 + row) * APAD + q) * 2;
    }
    const int c0 = tid, c1 = tid + 256;
    const int r0c = c0 >> 2, q0c = (c0 & 3) * 8;
    const int r1c = c1 >> 2, q1c = (c1 & 3) * 8;

    float acc_a[4][2][4], acc_g[4][2][4];
#pragma unroll
    for (int i = 0; i < 4; i++)
#pragma unroll
        for (int j = 0; j < 2; j++)
#pragma unroll
            for (int q = 0; q < 4; q++) { acc_a[i][j][q] = 0.f; acc_g[i][j][q] = 0.f; }

    const int NK = CC / 32;  // 8
    float apre[2][8];

#pragma unroll
    for (int i = 0; i < 4; i++) {
        const int t = btt[i], row = brr[i];
        const int q = ((tid + i * 256) & 3) * 8;
        cpa16(smbase + bdst[i],
              bsrc[t] + (size_t)(brow[t] + row) * CC + q);
    }
    CP_COMMIT();
    {
        *reinterpret_cast<float4*>(&apre[0][0]) = *reinterpret_cast<const float4*>(&Q[(size_t)(m0 + r0c) * CC + q0c]);
        *reinterpret_cast<float4*>(&apre[0][4]) = *reinterpret_cast<const float4*>(&Q[(size_t)(m0 + r0c) * CC + q0c + 4]);
        *reinterpret_cast<float4*>(&apre[1][0]) = *reinterpret_cast<const float4*>(&Q[(size_t)(m0 + r1c) * CC + q1c]);
        *reinterpret_cast<float4*>(&apre[1][4]) = *reinterpret_cast<const float4*>(&Q[(size_t)(m0 + r1c) * CC + q1c + 4]);
        __nv_bfloat16 h8[8], l8[8];
#pragma unroll
        for (int e = 0; e < 8; e++) split2(apre[0][e], h8[e], l8[e]);
        *reinterpret_cast<uint4*>(&sm[(0 * 128 + r0c) * APAD + q0c]) = *reinterpret_cast<uint4*>(h8);
        *reinterpret_cast<uint4*>(&sm[(1 * 128 + r0c) * APAD + q0c]) = *reinterpret_cast<uint4*>(l8);
#pragma unroll
        for (int e = 0; e < 8; e++) split2(apre[1][e], h8[e], l8[e]);
        *reinterpret_cast<uint4*>(&sm[(0 * 128 + r1c) * APAD + q1c]) = *reinterpret_cast<uint4*>(h8);
        *reinterpret_cast<uint4*>(&sm[(1 * 128 + r1c) * APAD + q1c]) = *reinterpret_cast<uint4*>(l8);
    }
    CP_WAIT0();
    __syncthreads();

    for (int kc = 0; kc < NK; kc++) {
        const int nxt = kc + 1;
        if (nxt < NK) {
            const int sb = (nxt & 1) * G1_STAGE;
            const int k0 = nxt << 5;
#pragma unroll
            for (int i = 0; i < 4; i++) {
                const int t = btt[i], row = brr[i];
                const int q = ((tid + i * 256) & 3) * 8;
                cpa16(smbase + (uint32_t)(sb * 2) + bdst[i],
                      bsrc[t] + (size_t)(brow[t] + row) * CC + k0 + q);
            }
            CP_COMMIT();
            *reinterpret_cast<float4*>(&apre[0][0]) = *reinterpret_cast<const float4*>(&Q[(size_t)(m0 + r0c) * CC + k0 + q0c]);
            *reinterpret_cast<float4*>(&apre[0][4]) = *reinterpret_cast<const float4*>(&Q[(size_t)(m0 + r0c) * CC + k0 + q0c + 4]);
            *reinterpret_cast<float4*>(&apre[1][0]) = *reinterpret_cast<const float4*>(&Q[(size_t)(m0 + r1c) * CC + k0 + q1c]);
            *reinterpret_cast<float4*>(&apre[1][4]) = *reinterpret_cast<const float4*>(&Q[(size_t)(m0 + r1c) * CC + k0 + q1c + 4]);
        }

        const uint32_t stg = smbase + (uint32_t)((kc & 1) * G1_STAGE) * 2;
#pragma unroll
        for (int ks = 0; ks < 2; ks++) {
            const int kb = ks * 16;
            uint32_t afh[4][4], afl[4][4];
#pragma unroll
            for (int im = 0; im < 4; im++) {
                const uint32_t aaddr = stg +
                    (uint32_t)(((wm + im * 16 + alr) * APAD + kb + alc) * 2);
                ldsm_x4(afh[im], aaddr);
            }
            uint32_t bh[2][2], bl[2][2], gh[2][2], gl[2][2];
#pragma unroll
            for (int jn = 0; jn < 2; jn++) {
                const uint32_t ba = stg + 2 * TILE_BYTES_SM +
                    (uint32_t)(((wn + jn * 8 + blr) * APAD + kb + blc) * 2);
                ldsm_x2(bh[jn], ba);
                ldsm_x2(bl[jn], ba + (uint32_t)(64 * APAD * 2));
                const uint32_t bg = stg + 3 * TILE_BYTES_SM +
                    (uint32_t)(((wn + jn * 8 + blr) * APAD + kb + blc) * 2);
                ldsm_x2(gh[jn], bg);
                ldsm_x2(gl[jn], bg + (uint32_t)(64 * APAD * 2));
            }
#pragma unroll
            for (int im = 0; im < 4; im++)
#pragma unroll
                for (int jn = 0; jn < 2; jn++) {
                    mma16816(acc_a[im][jn], afh[im][0], afh[im][1], afh[im][2], afh[im][3], bh[jn][0], bh[jn][1]);
                    mma16816(acc_a[im][jn], afh[im][0], afh[im][1], afh[im][2], afh[im][3], bl[jn][0], bl[jn][1]);
                    mma16816(acc_g[im][jn], afh[im][0], afh[im][1], afh[im][2], afh[im][3], gh[jn][0], gh[jn][1]);
                    mma16816(acc_g[im][jn], afh[im][0], afh[im][1], afh[im][2], afh[im][3], gl[jn][0], gl[jn][1]);
                }
#pragma unroll
            for (int im = 0; im < 4; im++) {
                const uint32_t aaddr = stg + TILE_BYTES_SM +
                    (uint32_t)(((wm + im * 16 + alr) * APAD + kb + alc) * 2);
                ldsm_x4(afl[im], aaddr);
            }
#pragma unroll
            for (int im = 0; im < 4; im++)
#pragma unroll
                for (int jn = 0; jn < 2; jn++) {
                    mma16816(acc_a[im][jn], afl[im][0], afl[im][1], afl[im][2], afl[im][3], bh[jn][0], bh[jn][1]);
                    mma16816(acc_g[im][jn], afl[im][0], afl[im][1], afl[im][2], afl[im][3], gh[jn][0], gh[jn][1]);
                }
        }

        if (nxt < NK) {
            const int sb = (nxt & 1) * G1_STAGE;
            __nv_bfloat16 h8[8], l8[8];
#pragma unroll
            for (int e = 0; e < 8; e++) split2(apre[0][e], h8[e], l8[e]);
            *reinterpret_cast<uint4*>(&sm[sb + (0 * 128 + r0c) * APAD + q0c]) = *reinterpret_cast<uint4*>(h8);
            *reinterpret_cast<uint4*>(&sm[sb + (1 * 128 + r0c) * APAD + q0c]) = *reinterpret_cast<uint4*>(l8);
#pragma unroll
            for (int e = 0; e < 8; e++) split2(apre[1][e], h8[e], l8[e]);
            *reinterpret_cast<uint4*>(&sm[sb + (0 * 128 + r1c) * APAD + q1c]) = *reinterpret_cast<uint4*>(h8);
            *reinterpret_cast<uint4*>(&sm[sb + (1 * 128 + r1c) * APAD + q1c]) = *reinterpret_cast<uint4*>(l8);
            CP_WAIT0();
            __syncthreads();
        }
    }

#pragma unroll
    for (int im = 0; im < 4; im++) {
#pragma unroll
        for (int jn = 0; jn < 2; jn++) {
            const int col = na0 + wn + jn * 8 + cp;
            const float ba0 = b1[col], ba1 = b1[col + 1];
            const float bg0 = b1[col + 256], bg1 = b1[col + 257];
            const int row0 = m0 + wm + im * 16 + r8;
#pragma unroll
            for (int half = 0; half < 2; half++) {
                const int row = row0 + half * 8;
                float a0 = acc_a[im][jn][half * 2 + 0] + ba0;
                float a1 = acc_a[im][jn][half * 2 + 1] + ba1;
                float gg0 = acc_g[im][jn][half * 2 + 0] + bg0;
                float gg1 = acc_g[im][jn][half * 2 + 1] + bg1;
                float x0 = a0 * (1.f / (1.f + expf(-gg0)));
                float x1 = a1 * (1.f / (1.f + expf(-gg1)));
                size_t o = (size_t)row * CC + col;
                __nv_bfloat16 h0, l0, h1, l1;
                split2(x0, h0, l0); split2(x1, h1, l1);
                __nv_bfloat162 ph; ph.x = h0; ph.y = h1;
                __nv_bfloat162 pl; pl.x = l0; pl.y = l1;
                *reinterpret_cast<__nv_bfloat162*>(&Xhi[o]) = ph;
                *reinterpret_cast<__nv_bfloat162*>(&Xlo[o]) = pl;
            }
        }
    }
}

// ---------------- generic fused split-bf16 GEMM (2 CTAs/SM, ldmatrix) -------
#define STAGE_ELEMS (4 * TILE_ELEMS)
#define GSMEM_BYTES (2 * STAGE_ELEMS * 2)   // 81920

__global__ __launch_bounds__(256, 2) void gemm_split_mma(
    const __nv_bfloat16* __restrict__ Ahi, const __nv_bfloat16* __restrict__ Alo,
    const __nv_bfloat16* __restrict__ Bhi, const __nv_bfloat16* __restrict__ Blo,
    const float* __restrict__ bias, float* __restrict__ Cm,
    int Kt, int ldc, int Nout)
{
    extern __shared__ __align__(16) __nv_bfloat16 sm[];
    const int tid = threadIdx.x;
    const int wid = tid >> 5;
    const int lane = tid & 31;
    const int m0 = blockIdx.y * BMT;
    const int n0 = blockIdx.x * BNT;
    const int wm = (wid & 1) * 64;
    const int wn = (wid >> 1) * 32;
    const int r8 = lane >> 2;
    const int cp = (lane & 3) * 2;

    const int alr = A_LDSM_ROW(lane), alc = A_LDSM_COL(lane);
    const int blr = B_LDSM_ROW(lane), blc = B_LDSM_COL(lane);

    const __nv_bfloat16* srcs[4] = { Ahi, Alo, Bhi, Blo };
    const int bases[4] = { m0, m0, n0, n0 };

    const int c0 = tid, c1 = tid + 256;
    const int lr0 = c0 >> 2, lc0 = (c0 & 3) * 8;
    const int lr1 = c1 >> 2, lc1 = (c1 & 3) * 8;
    const uint32_t smbase = smem_u32(sm);

    float acc[4][4][4];
#pragma unroll
    for (int i = 0; i < 4; i++)
#pragma unroll
        for (int j = 0; j < 4; j++)
#pragma unroll
            for (int q = 0; q < 4; q++) acc[i][j][q] = 0.f;

    const int NK = Kt >> 5;

#pragma unroll
    for (int t = 0; t < 4; t++) {
        const __nv_bfloat16* sp = srcs[t];
        cpa16(smbase + (uint32_t)((t * 128 + lr0) * APAD + lc0) * 2,
              sp + (size_t)(bases[t] + lr0) * Kt + lc0);
        cpa16(smbase + (uint32_t)((t * 128 + lr1) * APAD + lc1) * 2,
              sp + (size_t)(bases[t] + lr1) * Kt + lc1);
    }
    CP_COMMIT();
    CP_WAIT0();
    __syncthreads();

    for (int kc = 0; kc < NK; kc++) {
        if (kc + 1 < NK) {
            const int sb = ((kc + 1) & 1) * STAGE_ELEMS;
            const int k0 = (kc + 1) << 5;
#pragma unroll
            for (int t = 0; t < 4; t++) {
                const __nv_bfloat16* sp = srcs[t];
                cpa16(smbase + (uint32_t)(sb + (t * 128 + lr0) * APAD + lc0) * 2,
                      sp + (size_t)(bases[t] + lr0) * Kt + k0 + lc0);
                cpa16(smbase + (uint32_t)(sb + (t * 128 + lr1) * APAD + lc1) * 2,
                      sp + (size_t)(bases[t] + lr1) * Kt + k0 + lc1);
            }
            CP_COMMIT();
        }
        const uint32_t stg = smbase + (uint32_t)((kc & 1) * STAGE_ELEMS) * 2;
#pragma unroll
        for (int ks = 0; ks < 2; ks++) {
            const int kb = ks * 16;
            uint32_t afh[4][4], afl[4][4];
#pragma unroll
            for (int im = 0; im < 4; im++) {
                const uint32_t aaddr = stg +
                    (uint32_t)(((wm + im * 16 + alr) * APAD + kb + alc) * 2);
                ldsm_x4(afh[im], aaddr);
            }
            uint32_t bfh[4][2], bfl[4][2];
#pragma unroll
            for (int jn = 0; jn < 4; jn++) {
                const uint32_t baddr = stg + 2 * TILE_BYTES_SM +
                    (uint32_t)(((wn + jn * 8 + blr) * APAD + kb + blc) * 2);
                ldsm_x2(bfh[jn], baddr);
                ldsm_x2(bfl[jn], baddr + TILE_BYTES_SM);
            }
#pragma unroll
            for (int im = 0; im < 4; im++)
#pragma unroll
                for (int jn = 0; jn < 4; jn++) {
                    mma16816(acc[im][jn], afh[im][0], afh[im][1], afh[im][2], afh[im][3], bfh[jn][0], bfh[jn][1]);
                    mma16816(acc[im][jn], afh[im][0], afh[im][1], afh[im][2], afh[im][3], bfl[jn][0], bfl[jn][1]);
                }
#pragma unroll
            for (int im = 0; im < 4; im++) {
                const uint32_t aaddr = stg + TILE_BYTES_SM +
                    (uint32_t)(((wm + im * 16 + alr) * APAD + kb + alc) * 2);
                ldsm_x4(afl[im], aaddr);
            }
#pragma unroll
            for (int im = 0; im < 4; im++)
#pragma unroll
                for (int jn = 0; jn < 4; jn++)
                    mma16816(acc[im][jn], afl[im][0], afl[im][1], afl[im][2], afl[im][3], bfh[jn][0], bfh[jn][1]);
        }
        if (kc + 1 < NK) {
            CP_WAIT0();
            __syncthreads();
        }
    }

#pragma unroll
    for (int im = 0; im < 4; im++) {
#pragma unroll
        for (int jn = 0; jn < 4; jn++) {
            const int col = n0 + wn + jn * 8 + cp;
            if (col < Nout) {
                const float bx = bias[col], by = bias[col + 1];
                const int row0 = m0 + wm + im * 16 + r8;
                float2 v0 = { acc[im][jn][0] + bx, acc[im][jn][1] + by };
                float2 v1 = { acc[im][jn][2] + bx, acc[im][jn][3] + by };
                *reinterpret_cast<float2*>(&Cm[(size_t)row0 * ldc + col]) = v0;
                *reinterpret_cast<float2*>(&Cm[(size_t)(row0 + 8) * ldc + col]) = v1;
            }
        }
    }
}

// -------------------- merged prep kernel ------------------------------------
#define S_W1 (C2 * CC)
#define S_W2 (CC * C2)
#define S_WS (NSMPAD * CC)
__global__ __launch_bounds__(256) void prep_all(
    const float* __restrict__ w1, const float* __restrict__ w2,
    const float* __restrict__ wf, const float* __restrict__ ww,
    const float* __restrict__ bf, const float* __restrict__ bw,
    __nv_bfloat16* __restrict__ w1h, __nv_bfloat16* __restrict__ w1l,
    __nv_bfloat16* __restrict__ w2h, __nv_bfloat16* __restrict__ w2l,
    __nv_bfloat16* __restrict__ wsh, __nv_bfloat16* __restrict__ wsl,
    float* __restrict__ bc)
{
    int i = blockIdx.x * 256 + threadIdx.x;
    if (i < S_W1) {
        int n = i / CC, k = i % CC;
        split2(w1[(size_t)k * C2 + n], w1h[i], w1l[i]);
    } else if (i < S_W1 + S_W2) {
        int j = i - S_W1;
        int n = j / C2, k = j % C2;
        split2(w2[(size_t)k * CC + n], w2h[j], w2l[j]);
    } else if (i < S_W1 + S_W2 + S_WS) {
        int j = i - S_W1 - S_W2;
        int n = j / CC, k = j % CC;
        float v = 0.f;
        if (n < KK) v = wf[k * KK + n];
        else if (n < NSMALL) v = ww[k * NWW + (n - KK)];
        split2(v, wsh[j], wsl[j]);
    } else if (i < S_W1 + S_W2 + S_WS + NSP) {
        int j = i - S_W1 - S_W2 - S_WS;
        float v = 0.f;
        if (j < KK) v = bf[j];
        else if (j < NSMALL) v = bw[j - KK];
        bc[j] = v;
    }
}

// ========== band kernel v3: conv + softmax (scalar) + attn apply (MMA) ======
// Tile = 32 tokens. X window (hi/lo) 64 rows x 256 ch in smem.
// P banded (hi/lo) [4 heads][32 tok][KPAD] built from register softmax.
// Phase 2: per head, Y[32x64] = P[32x64K] @ Xwin via mma (A row-major,
// B via ldmatrix.trans on row-major [k][n] X tiles).
#define FT 32
#define XROWS 64
#define XPAD 264
#define KPAD 72
#define XH_OFF 0
#define XL_OFF (XROWS * XPAD)                    // 16896
#define PH_OFF (2 * XROWS * XPAD)                // 33792
#define PL_OFF (PH_OFF + HH * 32 * KPAD)         // 33792 + 9216
#define B3_ELEMS (PL_OFF + HH * 32 * KPAD)       // 52224
#define B3_SMEM (B3_ELEMS * 2)                   // 104448 bytes

__global__ __launch_bounds__(256) void band3(
    const float* __restrict__ raw,
    const __nv_bfloat16* __restrict__ xhi, const __nv_bfloat16* __restrict__ xlo,
    const int* __restrict__ mask,
    __nv_bfloat16* __restrict__ zhi, __nv_bfloat16* __restrict__ zlo)
{
    extern __shared__ __align__(16) __nv_bfloat16 smb[];
    __shared__ float msk[FT];

    const int b = blockIdx.x >> 5;
    const int tb = (blockIdx.x & 31) * FT;
    const int tid = threadIdx.x;
    const int warp = tid >> 5;
    const int lane = tid & 31;
    const uint32_t smbase = smem_u32(smb);

    // load X window hi/lo: 64 rows x 256 ch, 8-elem chunks
    for (int idx = tid; idx < XROWS * 32; idx += 256) {
        const int r = idx >> 5;
        const int cc = (idx & 31) * 8;
        const int s = tb - PADK + r;
        uint4 vh = make_uint4(0, 0, 0, 0), vl = vh;
        if (s >= 0 && s < TT) {
            vh = *reinterpret_cast<const uint4*>(xhi + ((size_t)b * TT + s) * CC + cc);
            vl = *reinterpret_cast<const uint4*>(xlo + ((size_t)b * TT + s) * CC + cc);
        }
        *reinterpret_cast<uint4*>(&smb[XH_OFF + r * XPAD + cc]) = vh;
        *reinterpret_cast<uint4*>(&smb[XL_OFF + r * XPAD + cc]) = vl;
    }
    // zero P region (2 * 4h * 32 * KPAD elems)
    for (int idx = tid; idx < (2 * HH * 32 * KPAD) / 8; idx += 256)
        *reinterpret_cast<uint4*>(&smb[PH_OFF + idx * 8]) = make_uint4(0, 0, 0, 0);
    if (tid < FT) msk[tid] = (mask[b * TT + tb + tid] != 0) ? 1.f : 0.f;
    __syncthreads();

    // ---- phase 1: softmax -> P smem (banded); channel conv -> z[:,CC:] ----
#pragma unroll 1
    for (int it = 0; it < 4; it++) {
        const int tt = warp * 4 + it;
        const size_t t = (size_t)b * TT + tb + tt;
        const float mk = msk[tt];

        const int soff = tb + tt + lane - PADK;
        const bool valid = (lane < KK) && (soff >= 0) && (soff < TT);
#pragma unroll
        for (int h = 0; h < HH; h++) {
            float v = valid ? raw[t * NSP + KK + h * KK + lane] : -INFINITY;
            float mx = v;
#pragma unroll
            for (int o = 16; o; o >>= 1) mx = fmaxf(mx, __shfl_xor_sync(0xffffffffu, mx, o));
            float e = valid ? expf(v - mx) : 0.f;
            float sm_ = e;
#pragma unroll
            for (int o = 16; o; o >>= 1) sm_ += __shfl_xor_sync(0xffffffffu, sm_, o);
            const float p = e / sm_;
            if (lane < KK) {
                __nv_bfloat16 ph, pl;
                split2(p, ph, pl);
                const int off = (h * 32 + tt) * KPAD + tt + lane;
                smb[PH_OFF + off] = ph;
                smb[PL_OFF + off] = pl;
            }
        }

        // channel conv on reconstructed x = hi + lo
        const float wv = (lane < KK) ? raw[t * NSP + lane] : 0.f;
        const int xrow = tt + PADK;
        float buf[48];
        const int base = lane * 8 - 16;
#pragma unroll
        for (int i = 0; i < 6; i++) {
            const int c = base + i * 8;
            if (c >= 0 && c <= CC - 8) {
                uint4 vh = *reinterpret_cast<const uint4*>(&smb[XH_OFF + xrow * XPAD + c]);
                uint4 vl = *reinterpret_cast<const uint4*>(&smb[XL_OFF + xrow * XPAD + c]);
                const __nv_bfloat16* hh = reinterpret_cast<const __nv_bfloat16*>(&vh);
                const __nv_bfloat16* ll = reinterpret_cast<const __nv_bfloat16*>(&vl);
#pragma unroll
                for (int e = 0; e < 8; e++)
                    buf[i * 8 + e] = __bfloat162float(hh[e]) + __bfloat162float(ll[e]);
            } else {
#pragma unroll
                for (int e = 0; e < 8; e++) buf[i * 8 + e] = 0.f;
            }
        }
        float fa[8];
#pragma unroll
        for (int d = 0; d < 8; d++) fa[d] = 0.f;
#pragma unroll
        for (int j = 0; j < KK; j++) {
            const float wj = __shfl_sync(0xffffffffu, wv, j);
#pragma unroll
            for (int d = 0; d < 8; d++) fa[d] = fmaf(wj, buf[d + j + 1], fa[d]);
        }
        __nv_bfloat16 h8[8], l8[8];
#pragma unroll
        for (int d = 0; d < 8; d++) split2(fa[d] * mk, h8[d], l8[d]);
        const size_t o = t * C2 + CC + lane * 8;
        *reinterpret_cast<uint4*>(&zhi[o]) = *reinterpret_cast<uint4*>(h8);
        *reinterpret_cast<uint4*>(&zlo[o]) = *reinterpret_cast<uint4*>(l8);
    }
    __syncthreads();

    // ---- phase 2: attention apply via MMA ----------------------------------
    // warp -> head h = warp>>1, channel half nh = warp&1 (32 channels)
    const int h = warp >> 1;
    const int ch0 = h * 64 + (warp & 1) * 32;
    const int alr = A_LDSM_ROW(lane), alc = A_LDSM_COL(lane);
    const int l15 = lane & 15;
    const int r8 = lane >> 2;
    const int cp = (lane & 3) * 2;

    float acc[2][4][4];
#pragma unroll
    for (int i = 0; i < 2; i++)
#pragma unroll
        for (int j = 0; j < 4; j++)
#pragma unroll
            for (int q = 0; q < 4; q++) acc[i][j][q] = 0.f;

    const uint32_t phb = smbase + (uint32_t)(PH_OFF + (h * 32) * KPAD) * 2;
    const uint32_t plb = smbase + (uint32_t)(PL_OFF + (h * 32) * KPAD) * 2;
#pragma unroll
    for (int kc = 0; kc < 4; kc++) {
        const int kb = kc * 16;
        uint32_t ah[2][4], al[2][4];
#pragma unroll
        for (int im = 0; im < 2; im++) {
            const uint32_t aoff = (uint32_t)(((im * 16 + alr) * KPAD + kb + alc) * 2);
            ldsm_x4(ah[im], phb + aoff);
            ldsm_x4(al[im], plb + aoff);
        }
        uint32_t bh[4][2], bl[4][2];
#pragma unroll
        for (int jn = 0; jn < 4; jn++) {
            const uint32_t xoff = (uint32_t)(((kb + l15) * XPAD + ch0 + jn * 8) * 2);
            ldsm_x2_trans(bh[jn], smbase + (uint32_t)(XH_OFF * 2) + xoff);
            ldsm_x2_trans(bl[jn], smbase + (uint32_t)(XL_OFF * 2) + xoff);
        }
#pragma unroll
        for (int im = 0; im < 2; im++)
#pragma unroll
            for (int jn = 0; jn < 4; jn++) {
                mma16816(acc[im][jn], ah[im][0], ah[im][1], ah[im][2], ah[im][3], bh[jn][0], bh[jn][1]);
                mma16816(acc[im][jn], ah[im][0], ah[im][1], ah[im][2], ah[im][3], bl[jn][0], bl[jn][1]);
                mma16816(acc[im][jn], al[im][0], al[im][1], al[im][2], al[im][3], bh[jn][0], bh[jn][1]);
            }
    }

    // epilogue: tt = im*16 + half*8 + r8, c = ch0 + jn*8 + cp
#pragma unroll
    for (int im = 0; im < 2; im++) {
#pragma unroll
        for (int jn = 0; jn < 4; jn++) {
            const int c = ch0 + jn * 8 + cp;
#pragma unroll
            for (int half = 0; half < 2; half++) {
                const int tt = im * 16 + half * 8 + r8;
                const float mv = msk[tt];
                const size_t o = ((size_t)b * TT + tb + tt) * C2 + c;
                __nv_bfloat16 h0, l0, h1, l1;
                split2(acc[im][jn][half * 2 + 0] * mv, h0, l0);
                split2(acc[im][jn][half * 2 + 1] * mv, h1, l1);
                __nv_bfloat162 ph2; ph2.x = h0; ph2.y = h1;
                __nv_bfloat162 pl2; pl2.x = l0; pl2.y = l1;
                *reinterpret_cast<__nv_bfloat162*>(&zhi[o]) = ph2;
                *reinterpret_cast<__nv_bfloat162*>(&zlo[o]) = pl2;
            }
        }
    }
}

// ---------------------------------------------------------------------------
extern "C" void kernel_launch(void* const* d_in, const int* in_sizes, int n_in,
                              void* d_out, int out_size)
{
    const float* query = (const float*)d_in[0];
    const int* mask = (const int*)d_in[3];
    const float* w1 = (const float*)d_in[4];
    const float* b1 = (const float*)d_in[5];
    const float* w2 = (const float*)d_in[6];
    const float* b2 = (const float*)d_in[7];
    const float* ww = (const float*)d_in[8];
    const float* bw = (const float*)d_in[9];
    const float* wf = (const float*)d_in[10];
    const float* bf = (const float*)d_in[11];
    float* out = (float*)d_out;

    void* p;
    cudaGetSymbolAddress(&p, g_xhi);    __nv_bfloat16* dxhi = (__nv_bfloat16*)p;
    cudaGetSymbolAddress(&p, g_xlo);    __nv_bfloat16* dxlo = (__nv_bfloat16*)p;
    cudaGetSymbolAddress(&p, g_zhi);    __nv_bfloat16* dzhi = (__nv_bfloat16*)p;
    cudaGetSymbolAddress(&p, g_zlo);    __nv_bfloat16* dzlo = (__nv_bfloat16*)p;
    cudaGetSymbolAddress(&p, g_raw);    float* draw = (float*)p;
    cudaGetSymbolAddress(&p, g_w1t_hi); __nv_bfloat16* w1h = (__nv_bfloat16*)p;
    cudaGetSymbolAddress(&p, g_w1t_lo); __nv_bfloat16* w1l = (__nv_bfloat16*)p;
    cudaGetSymbolAddress(&p, g_w2t_hi); __nv_bfloat16* w2h = (__nv_bfloat16*)p;
    cudaGetSymbolAddress(&p, g_w2t_lo); __nv_bfloat16* w2l = (__nv_bfloat16*)p;
    cudaGetSymbolAddress(&p, g_wst_hi); __nv_bfloat16* wsh = (__nv_bfloat16*)p;
    cudaGetSymbolAddress(&p, g_wst_lo); __nv_bfloat16* wsl = (__nv_bfloat16*)p;
    cudaGetSymbolAddress(&p, g_bsmall); float* dbs = (float*)p;

    static bool attr_done = false;
    if (!attr_done) {
        cudaFuncSetAttribute(gemm1_glu,
                             cudaFuncAttributeMaxDynamicSharedMemorySize, G1_SMEM_BYTES);
        cudaFuncSetAttribute(gemm_split_mma,
                             cudaFuncAttributeMaxDynamicSharedMemorySize, GSMEM_BYTES);
        cudaFuncSetAttribute(band3,
                             cudaFuncAttributeMaxDynamicSharedMemorySize, B3_SMEM);
        attr_done = true;
    }

    // prep: all weight splits in one launch
    prep_all<<<(S_W1 + S_W2 + S_WS + NSP + 255) / 256, 256>>>(
        w1, w2, wf, ww, bf, bw, w1h, w1l, w2h, w2l, wsh, wsl, dbs);

    // 1) xhi/xlo = split(GLU(query @ w1 + b1)), fused
    gemm1_glu<<<dim3(4, BT / BMT), 256, G1_SMEM_BYTES>>>(
        query, w1h, w1l, b1, dxhi, dxlo);
    // 2) raw = x @ [wf|ww] + [bf|bw]
    gemm_split_mma<<<dim3(NSMPAD / BNT, BT / BMT), 256, GSMEM_BYTES>>>(
        dxhi, dxlo, wsh, wsl, dbs, draw, CC, NSP, NSP);
    // 3) band kernel: conv + softmax + MMA attention apply -> z
    band3<<<BB * (TT / FT), 256, B3_SMEM>>>(draw, dxhi, dxlo, mask, dzhi, dzlo);
    // 4) out = z @ w2 + b2
    gemm_split_mma<<<dim3(CC / BNT, BT / BMT), 256, GSMEM_BYTES>>>(
        dzhi, dzlo, w2h, w2l, b2, out, C2, CC, CC);
}